// round 3
// baseline (speedup 1.0000x reference)
#include <cuda_runtime.h>
#include <cstdint>

#define EDIM   1024
#define HEADS  16
#define DHEAD  64
#define BATCH  2
#define SEQ    2048
#define RANK   8
#define MTOT   (BATCH*SEQ)

// ---------------- scratch (device globals; no allocations allowed) ----------
__device__ float g_Wc[3*EDIM*EDIM];                 // folded QKV+LoRA weights [3E][E]
__device__ float g_Wm[EDIM*EDIM];                   // folded out-proj weights [E][E]
__device__ float g_Qb[BATCH*HEADS*SEQ*DHEAD];       // Q [b,h,s,d]
__device__ float g_Kb[BATCH*HEADS*SEQ*DHEAD];
__device__ float g_Vb[BATCH*HEADS*SEQ*DHEAD];
__device__ float g_Ob[MTOT*EDIM];                   // attention out [b,s,e]
__device__ float g_Mb[MTOT*EDIM];                   // msa + residual

// ---------------- f32x2 helpers (Blackwell packed fp32) ---------------------
static __device__ __forceinline__ unsigned long long f2pack(float x) {
    unsigned long long r;
    asm("mov.b64 %0, {%1, %2};" : "=l"(r) : "f"(x), "f"(x));
    return r;
}
static __device__ __forceinline__ unsigned long long ffma2(
    unsigned long long a, unsigned long long b, unsigned long long c) {
    unsigned long long d;
    asm("fma.rn.f32x2 %0, %1, %2, %3;" : "=l"(d) : "l"(a), "l"(b), "l"(c));
    return d;
}
static __device__ __forceinline__ unsigned long long fmul2(
    unsigned long long a, unsigned long long b) {
    unsigned long long d;
    asm("mul.rn.f32x2 %0, %1, %2;" : "=l"(d) : "l"(a), "l"(b));
    return d;
}
static __device__ __forceinline__ void unpack2(unsigned long long v, float& lo, float& hi) {
    asm("mov.b64 {%0, %1}, %2;" : "=f"(lo), "=f"(hi) : "l"(v));
}

// ---------------- kernel 1: fold LoRA into weights --------------------------
__global__ __launch_bounds__(256) void prep_weights(
    const float* __restrict__ Wqkv, const float* __restrict__ Wmsa,
    const float* __restrict__ Bq, const float* __restrict__ Aq,
    const float* __restrict__ Bk, const float* __restrict__ Ak,
    const float* __restrict__ Bv, const float* __restrict__ Av,
    const float* __restrict__ Bo, const float* __restrict__ Ao)
{
    const int idx = blockIdx.x * blockDim.x + threadIdx.x;
    const int NQKV = 3 * EDIM * EDIM;
    if (idx < NQKV) {
        const int o = idx >> 10;          // output index [0,3E)
        const int i = idx & (EDIM - 1);   // input index
        const int which = o >> 10;        // 0=q,1=k,2=v
        const int e = o & (EDIM - 1);
        const float* Bw = (which == 0) ? Bq : (which == 1) ? Bk : Bv;
        const float* Aw = (which == 0) ? Aq : (which == 1) ? Ak : Av;
        float acc = Wqkv[idx];
        #pragma unroll
        for (int r = 0; r < RANK; r++) acc += Bw[i * RANK + r] * Aw[r * EDIM + e];
        g_Wc[idx] = acc;
    } else {
        const int j = idx - NQKV;         // [0, E*E)
        const int o = j >> 10;            // output (row of Wmsa)
        const int i = j & (EDIM - 1);     // input
        float acc = Wmsa[j];
        #pragma unroll
        for (int r = 0; r < RANK; r++) acc += Bo[i * RANK + r] * Ao[r * EDIM + o];
        g_Wm[j] = acc;
    }
}

// ---------------- kernel 2: QKV GEMM (M=4096,N=3072,K=1024) -----------------
// C[m,n] = sum_k y[m,k]*Wc[n,k] + bias[n], scattered into Q/K/V [b,h,s,d]
__global__ __launch_bounds__(256) void gemm_qkv_kernel(
    const float* __restrict__ A, const float* __restrict__ bias)
{
    __shared__ __align__(16) float As[16][132];   // transposed A tile: As[k][m]
    __shared__ __align__(16) float Bs[16][132];   // transposed B tile: Bs[k][n]
    const int tid = threadIdx.x;
    const int tx = tid & 15, ty = tid >> 4;
    const int m0 = blockIdx.y * 128, n0 = blockIdx.x * 128;
    const int lrow = tid >> 2;
    const int lk = (tid & 3) * 4;
    const float* Ap = A + (m0 + lrow) * EDIM + lk;
    const float* Bp = g_Wc + (n0 + lrow) * EDIM + lk;

    unsigned long long acc[8][4];
    #pragma unroll
    for (int i = 0; i < 8; i++)
        #pragma unroll
        for (int j = 0; j < 4; j++) acc[i][j] = 0ULL;

    for (int k0 = 0; k0 < EDIM; k0 += 16) {
        float4 a0 = *(const float4*)(Ap + k0);
        float4 a1 = *(const float4*)(Ap + 64 * EDIM + k0);
        float4 b0 = *(const float4*)(Bp + k0);
        float4 b1 = *(const float4*)(Bp + 64 * EDIM + k0);
        __syncthreads();
        As[lk+0][lrow] = a0.x; As[lk+1][lrow] = a0.y; As[lk+2][lrow] = a0.z; As[lk+3][lrow] = a0.w;
        As[lk+0][lrow+64] = a1.x; As[lk+1][lrow+64] = a1.y; As[lk+2][lrow+64] = a1.z; As[lk+3][lrow+64] = a1.w;
        Bs[lk+0][lrow] = b0.x; Bs[lk+1][lrow] = b0.y; Bs[lk+2][lrow] = b0.z; Bs[lk+3][lrow] = b0.w;
        Bs[lk+0][lrow+64] = b1.x; Bs[lk+1][lrow+64] = b1.y; Bs[lk+2][lrow+64] = b1.z; Bs[lk+3][lrow+64] = b1.w;
        __syncthreads();
        #pragma unroll
        for (int kk = 0; kk < 16; kk++) {
            float4 af0 = *(const float4*)&As[kk][ty * 8];
            float4 af1 = *(const float4*)&As[kk][ty * 8 + 4];
            ulonglong2 bu0 = *(const ulonglong2*)&Bs[kk][tx * 8];
            ulonglong2 bu1 = *(const ulonglong2*)&Bs[kk][tx * 8 + 4];
            unsigned long long bp[4] = {bu0.x, bu0.y, bu1.x, bu1.y};
            float av[8] = {af0.x, af0.y, af0.z, af0.w, af1.x, af1.y, af1.z, af1.w};
            #pragma unroll
            for (int i = 0; i < 8; i++) {
                unsigned long long ap = f2pack(av[i]);
                #pragma unroll
                for (int j = 0; j < 4; j++) acc[i][j] = ffma2(ap, bp[j], acc[i][j]);
            }
        }
    }

    #pragma unroll
    for (int i = 0; i < 8; i++) {
        const int m = m0 + ty * 8 + i;
        const int b = m >> 11;             // /SEQ
        const int s = m & (SEQ - 1);
        #pragma unroll
        for (int j = 0; j < 4; j++) {
            float c0, c1;
            unpack2(acc[i][j], c0, c1);
            const int n = n0 + tx * 8 + j * 2;
            #pragma unroll
            for (int u = 0; u < 2; u++) {
                const int nn = n + u;
                const float v = (u == 0 ? c0 : c1) + bias[nn];
                const int which = nn >> 10;
                const int e = nn & (EDIM - 1);
                const int h = e >> 6;
                const int d = e & (DHEAD - 1);
                float* dst = (which == 0) ? g_Qb : (which == 1) ? g_Kb : g_Vb;
                dst[((b * HEADS + h) * SEQ + s) * DHEAD + d] = v;
            }
        }
    }
}

// ---------------- kernel 3: flash attention ---------------------------------
// grid (S/64, B*H), 256 threads. Tiles: Qt[d][r], KPt = K^T then P^T, Vs[kv][d]
#define ATT_STRIDE 68
#define ATT_SMEM   (3 * 64 * ATT_STRIDE * 4)
__global__ __launch_bounds__(256) void attn_kernel()
{
    extern __shared__ __align__(16) float sm[];
    float* Qt  = sm;
    float* KPt = sm + 64 * ATT_STRIDE;
    float* Vs  = sm + 2 * 64 * ATT_STRIDE;

    const int tid = threadIdx.x;
    const int tx = tid & 15, ty = tid >> 4;
    const int bh = blockIdx.y;             // b*H + h
    const int q0 = blockIdx.x * 64;
    const float* Qg = g_Qb + (bh * SEQ + q0) * DHEAD;
    const float* Kg = g_Kb + bh * SEQ * DHEAD;
    const float* Vg = g_Vb + bh * SEQ * DHEAD;

    // load Q transposed: Qt[d][r]
    #pragma unroll
    for (int p = 0; p < 4; p++) {
        const int fid = tid + p * 256;
        const int row = fid >> 4, c4 = (fid & 15) * 4;
        float4 qv = *(const float4*)(Qg + row * DHEAD + c4);
        Qt[(c4+0)*ATT_STRIDE+row] = qv.x; Qt[(c4+1)*ATT_STRIDE+row] = qv.y;
        Qt[(c4+2)*ATT_STRIDE+row] = qv.z; Qt[(c4+3)*ATT_STRIDE+row] = qv.w;
    }

    float m_i[4], l_i[4];
    unsigned long long o2[4][2];
    #pragma unroll
    for (int i = 0; i < 4; i++) {
        m_i[i] = -1e30f; l_i[i] = 0.f; o2[i][0] = 0ULL; o2[i][1] = 0ULL;
    }

    for (int t = 0; t < SEQ / 64; t++) {
        const float* Kt0 = Kg + t * 64 * DHEAD;
        const float* Vt0 = Vg + t * 64 * DHEAD;
        __syncthreads();   // protect KPt/Vs from prior iteration's PV readers
        #pragma unroll
        for (int p = 0; p < 4; p++) {
            const int fid = tid + p * 256;
            const int row = fid >> 4, c4 = (fid & 15) * 4;
            float4 kv = *(const float4*)(Kt0 + row * DHEAD + c4);
            KPt[(c4+0)*ATT_STRIDE+row] = kv.x; KPt[(c4+1)*ATT_STRIDE+row] = kv.y;
            KPt[(c4+2)*ATT_STRIDE+row] = kv.z; KPt[(c4+3)*ATT_STRIDE+row] = kv.w;
            float4 vv = *(const float4*)(Vt0 + row * DHEAD + c4);
            *(float4*)&Vs[row * ATT_STRIDE + c4] = vv;
        }
        __syncthreads();

        // S = Q K^T  (4x4 per thread, f32x2 pairs along columns)
        unsigned long long s2[4][2];
        #pragma unroll
        for (int i = 0; i < 4; i++) { s2[i][0] = 0ULL; s2[i][1] = 0ULL; }
        #pragma unroll 16
        for (int k = 0; k < 64; k++) {
            float4 qv = *(const float4*)&Qt[k * ATT_STRIDE + ty * 4];
            ulonglong2 kp = *(const ulonglong2*)&KPt[k * ATT_STRIDE + tx * 4];
            const float qa[4] = {qv.x, qv.y, qv.z, qv.w};
            #pragma unroll
            for (int i = 0; i < 4; i++) {
                unsigned long long qp = f2pack(qa[i]);
                s2[i][0] = ffma2(qp, kp.x, s2[i][0]);
                s2[i][1] = ffma2(qp, kp.y, s2[i][1]);
            }
        }

        // online softmax (rows reduced across the 16 tx lanes)
        float p4[4][4];
        #pragma unroll
        for (int i = 0; i < 4; i++) {
            float s0, s1, s2f, s3;
            unpack2(s2[i][0], s0, s1);
            unpack2(s2[i][1], s2f, s3);
            s0 *= 0.125f; s1 *= 0.125f; s2f *= 0.125f; s3 *= 0.125f;
            float tmax = fmaxf(fmaxf(s0, s1), fmaxf(s2f, s3));
            #pragma unroll
            for (int off = 8; off >= 1; off >>= 1)
                tmax = fmaxf(tmax, __shfl_xor_sync(0xffffffffu, tmax, off));
            const float nm = fmaxf(m_i[i], tmax);
            const float alpha = __expf(m_i[i] - nm);
            const float e0 = __expf(s0 - nm), e1 = __expf(s1 - nm);
            const float e2 = __expf(s2f - nm), e3 = __expf(s3 - nm);
            float rs = e0 + e1 + e2 + e3;
            #pragma unroll
            for (int off = 8; off >= 1; off >>= 1)
                rs += __shfl_xor_sync(0xffffffffu, rs, off);
            l_i[i] = l_i[i] * alpha + rs;
            m_i[i] = nm;
            p4[i][0] = e0; p4[i][1] = e1; p4[i][2] = e2; p4[i][3] = e3;
            const unsigned long long am = f2pack(alpha);
            o2[i][0] = fmul2(o2[i][0], am);
            o2[i][1] = fmul2(o2[i][1], am);
        }

        __syncthreads();   // done reading K from KPt
        #pragma unroll
        for (int i = 0; i < 4; i++)
            #pragma unroll
            for (int j = 0; j < 4; j++)
                KPt[(tx * 4 + j) * ATT_STRIDE + ty * 4 + i] = p4[i][j];  // P^T
        __syncthreads();

        // O += P V
        #pragma unroll 16
        for (int kv = 0; kv < 64; kv++) {
            float4 pv = *(const float4*)&KPt[kv * ATT_STRIDE + ty * 4];
            ulonglong2 vv = *(const ulonglong2*)&Vs[kv * ATT_STRIDE + tx * 4];
            const float pa[4] = {pv.x, pv.y, pv.z, pv.w};
            #pragma unroll
            for (int i = 0; i < 4; i++) {
                unsigned long long pp = f2pack(pa[i]);
                o2[i][0] = ffma2(pp, vv.x, o2[i][0]);
                o2[i][1] = ffma2(pp, vv.y, o2[i][1]);
            }
        }
    }

    // epilogue: O /= l, write to [b,s,e] layout
    const int b = bh >> 4, h = bh & (HEADS - 1);
    #pragma unroll
    for (int i = 0; i < 4; i++) {
        const float inv = 1.0f / l_i[i];
        float x0, x1, x2, x3;
        unpack2(o2[i][0], x0, x1);
        unpack2(o2[i][1], x2, x3);
        float4 o = make_float4(x0 * inv, x1 * inv, x2 * inv, x3 * inv);
        const int srow = q0 + ty * 4 + i;
        *(float4*)&g_Ob[(b * SEQ + srow) * EDIM + h * DHEAD + tx * 4] = o;
    }
}

// ---------------- kernel 4: output GEMM + residual (M=4096,N=1024,K=1024) ---
__global__ __launch_bounds__(256) void gemm_out_kernel(const float* __restrict__ yres)
{
    __shared__ __align__(16) float As[16][132];
    __shared__ __align__(16) float Bs[16][132];
    const int tid = threadIdx.x;
    const int tx = tid & 15, ty = tid >> 4;
    const int m0 = blockIdx.y * 128, n0 = blockIdx.x * 128;
    const int lrow = tid >> 2;
    const int lk = (tid & 3) * 4;
    const float* Ap = g_Ob + (m0 + lrow) * EDIM + lk;
    const float* Bp = g_Wm + (n0 + lrow) * EDIM + lk;

    unsigned long long acc[8][4];
    #pragma unroll
    for (int i = 0; i < 8; i++)
        #pragma unroll
        for (int j = 0; j < 4; j++) acc[i][j] = 0ULL;

    for (int k0 = 0; k0 < EDIM; k0 += 16) {
        float4 a0 = *(const float4*)(Ap + k0);
        float4 a1 = *(const float4*)(Ap + 64 * EDIM + k0);
        float4 b0 = *(const float4*)(Bp + k0);
        float4 b1 = *(const float4*)(Bp + 64 * EDIM + k0);
        __syncthreads();
        As[lk+0][lrow] = a0.x; As[lk+1][lrow] = a0.y; As[lk+2][lrow] = a0.z; As[lk+3][lrow] = a0.w;
        As[lk+0][lrow+64] = a1.x; As[lk+1][lrow+64] = a1.y; As[lk+2][lrow+64] = a1.z; As[lk+3][lrow+64] = a1.w;
        Bs[lk+0][lrow] = b0.x; Bs[lk+1][lrow] = b0.y; Bs[lk+2][lrow] = b0.z; Bs[lk+3][lrow] = b0.w;
        Bs[lk+0][lrow+64] = b1.x; Bs[lk+1][lrow+64] = b1.y; Bs[lk+2][lrow+64] = b1.z; Bs[lk+3][lrow+64] = b1.w;
        __syncthreads();
        #pragma unroll
        for (int kk = 0; kk < 16; kk++) {
            float4 af0 = *(const float4*)&As[kk][ty * 8];
            float4 af1 = *(const float4*)&As[kk][ty * 8 + 4];
            ulonglong2 bu0 = *(const ulonglong2*)&Bs[kk][tx * 8];
            ulonglong2 bu1 = *(const ulonglong2*)&Bs[kk][tx * 8 + 4];
            unsigned long long bp[4] = {bu0.x, bu0.y, bu1.x, bu1.y};
            float av[8] = {af0.x, af0.y, af0.z, af0.w, af1.x, af1.y, af1.z, af1.w};
            #pragma unroll
            for (int i = 0; i < 8; i++) {
                unsigned long long ap = f2pack(av[i]);
                #pragma unroll
                for (int j = 0; j < 4; j++) acc[i][j] = ffma2(ap, bp[j], acc[i][j]);
            }
        }
    }

    #pragma unroll
    for (int i = 0; i < 8; i++) {
        const int m = m0 + ty * 8 + i;
        #pragma unroll
        for (int j = 0; j < 4; j++) {
            float c0, c1;
            unpack2(acc[i][j], c0, c1);
            const int n = n0 + tx * 8 + j * 2;
            g_Mb[m * EDIM + n]     = c0 + yres[m * EDIM + n];
            g_Mb[m * EDIM + n + 1] = c1 + yres[m * EDIM + n + 1];
        }
    }
}

// ---------------- kernel 5: LayerNorm ---------------------------------------
__global__ __launch_bounds__(256) void ln_kernel(
    const float* __restrict__ gamma, const float* __restrict__ beta,
    float* __restrict__ out)
{
    const int row = blockIdx.x;
    const int tid = threadIdx.x;
    const float4 v = *(const float4*)&g_Mb[row * EDIM + tid * 4];
    float s = v.x + v.y + v.z + v.w;
    float q = v.x * v.x + v.y * v.y + v.z * v.z + v.w * v.w;
    #pragma unroll
    for (int off = 16; off >= 1; off >>= 1) {
        s += __shfl_xor_sync(0xffffffffu, s, off);
        q += __shfl_xor_sync(0xffffffffu, q, off);
    }
    __shared__ float ss[8], sq[8];
    const int w = tid >> 5, lane = tid & 31;
    if (lane == 0) { ss[w] = s; sq[w] = q; }
    __syncthreads();
    float tot = 0.f, totq = 0.f;
    #pragma unroll
    for (int i = 0; i < 8; i++) { tot += ss[i]; totq += sq[i]; }
    const float mu = tot * (1.0f / EDIM);
    const float var = totq * (1.0f / EDIM) - mu * mu;
    const float rs = rsqrtf(var + 1e-6f);
    const float4 g = *(const float4*)&gamma[tid * 4];
    const float4 bb = *(const float4*)&beta[tid * 4];
    float4 o;
    o.x = (v.x - mu) * rs * g.x + bb.x;
    o.y = (v.y - mu) * rs * g.y + bb.y;
    o.z = (v.z - mu) * rs * g.z + bb.z;
    o.w = (v.w - mu) * rs * g.w + bb.w;
    *(float4*)&out[row * EDIM + tid * 4] = o;
}

// ---------------- launcher --------------------------------------------------
extern "C" void kernel_launch(void* const* d_in, const int* in_sizes, int n_in,
                              void* d_out, int out_size)
{
    (void)in_sizes; (void)n_in; (void)out_size;
    const float* y    = (const float*)d_in[0];
    const float* Wqkv = (const float*)d_in[1];
    const float* bqkv = (const float*)d_in[2];
    const float* Wmsa = (const float*)d_in[3];
    const float* Bq   = (const float*)d_in[4];
    const float* Aq   = (const float*)d_in[5];
    const float* Bk   = (const float*)d_in[6];
    const float* Ak   = (const float*)d_in[7];
    const float* Bv   = (const float*)d_in[8];
    const float* Av   = (const float*)d_in[9];
    const float* Bo   = (const float*)d_in[10];
    const float* Ao   = (const float*)d_in[11];
    const float* gamma= (const float*)d_in[12];
    const float* beta = (const float*)d_in[13];
    float* out = (float*)d_out;

    prep_weights<<<(4 * EDIM * EDIM) / 256, 256>>>(Wqkv, Wmsa, Bq, Aq, Bk, Ak, Bv, Av, Bo, Ao);
    gemm_qkv_kernel<<<dim3(3 * EDIM / 128, MTOT / 128), 256>>>(y, bqkv);
    (void)cudaFuncSetAttribute(attn_kernel, cudaFuncAttributeMaxDynamicSharedMemorySize, ATT_SMEM);
    attn_kernel<<<dim3(SEQ / 64, BATCH * HEADS), 256, ATT_SMEM>>>();
    gemm_out_kernel<<<dim3(EDIM / 128, MTOT / 128), 256>>>(y);
    ln_kernel<<<MTOT, 256>>>(gamma, beta, out);
}

// round 5
// speedup vs baseline: 1.5227x; 1.5227x over previous
#include <cuda_runtime.h>
#include <cuda_bf16.h>
#include <cstdint>

#define EDIM   1024
#define HEADS  16
#define DHEAD  64
#define BATCH  2
#define SEQ    2048
#define RANK   8
#define MTOT   (BATCH*SEQ)
#define K2     3072          // extended K: A=[hi|hi|lo], B=[hi|lo|hi]
#define NCHUNK 48            // K2 / 64

// ---------------- scratch (device globals; no allocations allowed) ----------
__device__ unsigned short g_A2y[(size_t)MTOT*K2];      // y split-bf16 extended
__device__ unsigned short g_B2q[(size_t)3*EDIM*K2];    // folded qkv weights split-bf16
__device__ unsigned short g_A2o[(size_t)MTOT*K2];      // attention out split-bf16
__device__ unsigned short g_B2o[(size_t)EDIM*K2];      // folded out-proj weights split-bf16
__device__ float g_Qb[(size_t)BATCH*HEADS*SEQ*DHEAD];  // Q [b,h,s,d]
__device__ float g_Kb[(size_t)BATCH*HEADS*SEQ*DHEAD];
__device__ float g_Vb[(size_t)BATCH*HEADS*SEQ*DHEAD];
__device__ float g_Mb[(size_t)MTOT*EDIM];              // msa + residual

// ---------------- bf16 split helpers ----------------------------------------
static __device__ __forceinline__ unsigned short bf_hi(float x) {
    return __bfloat16_as_ushort(__float2bfloat16(x));
}
static __device__ __forceinline__ unsigned short bf_lo(float x, unsigned short h) {
    float hf = __bfloat162float(__ushort_as_bfloat16(h));
    return __bfloat16_as_ushort(__float2bfloat16(x - hf));
}

// ---------------- f32x2 helpers (attention kernel) ---------------------------
static __device__ __forceinline__ unsigned long long f2pack(float x) {
    unsigned long long r;
    asm("mov.b64 %0, {%1, %2};" : "=l"(r) : "f"(x), "f"(x));
    return r;
}
static __device__ __forceinline__ unsigned long long ffma2(
    unsigned long long a, unsigned long long b, unsigned long long c) {
    unsigned long long d;
    asm("fma.rn.f32x2 %0, %1, %2, %3;" : "=l"(d) : "l"(a), "l"(b), "l"(c));
    return d;
}
static __device__ __forceinline__ unsigned long long fmul2(
    unsigned long long a, unsigned long long b) {
    unsigned long long d;
    asm("mul.rn.f32x2 %0, %1, %2;" : "=l"(d) : "l"(a), "l"(b));
    return d;
}
static __device__ __forceinline__ void unpack2(unsigned long long v, float& lo, float& hi) {
    asm("mov.b64 {%0, %1}, %2;" : "=f"(lo), "=f"(hi) : "l"(v));
}

// ---------------- mma.sync helpers -------------------------------------------
static __device__ __forceinline__ uint32_t smem_u32(const void* p) {
    uint32_t a;
    asm("{ .reg .u64 t; cvta.to.shared.u64 t, %1; cvt.u32.u64 %0, t; }" : "=r"(a) : "l"(p));
    return a;
}
static __device__ __forceinline__ void ldmx4(
    uint32_t& r0, uint32_t& r1, uint32_t& r2, uint32_t& r3, uint32_t a) {
    asm volatile("ldmatrix.sync.aligned.m8n8.x4.shared.b16 {%0,%1,%2,%3}, [%4];"
                 : "=r"(r0), "=r"(r1), "=r"(r2), "=r"(r3) : "r"(a));
}
static __device__ __forceinline__ void ldmx2(
    uint32_t& r0, uint32_t& r1, uint32_t a) {
    asm volatile("ldmatrix.sync.aligned.m8n8.x2.shared.b16 {%0,%1}, [%2];"
                 : "=r"(r0), "=r"(r1) : "r"(a));
}
static __device__ __forceinline__ void mma16816(
    float& d0, float& d1, float& d2, float& d3,
    uint32_t a0, uint32_t a1, uint32_t a2, uint32_t a3,
    uint32_t b0, uint32_t b1) {
    asm volatile("mma.sync.aligned.m16n8k16.row.col.f32.bf16.bf16.f32 "
                 "{%0,%1,%2,%3}, {%4,%5,%6,%7}, {%8,%9}, {%0,%1,%2,%3};"
                 : "+f"(d0), "+f"(d1), "+f"(d2), "+f"(d3)
                 : "r"(a0), "r"(a1), "r"(a2), "r"(a3), "r"(b0), "r"(b1));
}

// ---------------- kernel 1: fold LoRA + split weights to bf16 ---------------
__global__ __launch_bounds__(256) void prep_weights(
    const float* __restrict__ Wqkv, const float* __restrict__ Wmsa,
    const float* __restrict__ Bq, const float* __restrict__ Aq,
    const float* __restrict__ Bk, const float* __restrict__ Ak,
    const float* __restrict__ Bv, const float* __restrict__ Av,
    const float* __restrict__ Bo, const float* __restrict__ Ao)
{
    const int idx = blockIdx.x * blockDim.x + threadIdx.x;
    const int NQKV = 3 * EDIM * EDIM;
    if (idx < NQKV) {
        const int o = idx >> 10;          // output row [0,3E)
        const int i = idx & (EDIM - 1);   // input col
        const int which = o >> 10;
        const int e = o & (EDIM - 1);
        const float* Bw = (which == 0) ? Bq : (which == 1) ? Bk : Bv;
        const float* Aw = (which == 0) ? Aq : (which == 1) ? Ak : Av;
        float acc = Wqkv[idx];
        #pragma unroll
        for (int r = 0; r < RANK; r++) acc += Bw[i * RANK + r] * Aw[r * EDIM + e];
        unsigned short h = bf_hi(acc), l = bf_lo(acc, h);
        unsigned short* row = g_B2q + (size_t)o * K2;
        row[i] = h; row[EDIM + i] = l; row[2 * EDIM + i] = h;   // B2 = [hi|lo|hi]
    } else {
        const int j = idx - NQKV;
        const int o = j >> 10;
        const int i = j & (EDIM - 1);
        float acc = Wmsa[j];
        #pragma unroll
        for (int r = 0; r < RANK; r++) acc += Bo[i * RANK + r] * Ao[r * EDIM + o];
        unsigned short h = bf_hi(acc), l = bf_lo(acc, h);
        unsigned short* row = g_B2o + (size_t)o * K2;
        row[i] = h; row[EDIM + i] = l; row[2 * EDIM + i] = h;
    }
}

// ---------------- kernel 1b: split y to bf16 extended -----------------------
__global__ __launch_bounds__(256) void convert_y(const float* __restrict__ y)
{
    const int idx = blockIdx.x * blockDim.x + threadIdx.x;   // one per 4 floats
    const int m = idx >> 8;
    const int c = (idx & 255) * 4;
    float4 v = *(const float4*)(y + (size_t)m * EDIM + c);
    unsigned short h0 = bf_hi(v.x), h1 = bf_hi(v.y), h2 = bf_hi(v.z), h3 = bf_hi(v.w);
    unsigned short l0 = bf_lo(v.x, h0), l1 = bf_lo(v.y, h1), l2 = bf_lo(v.z, h2), l3 = bf_lo(v.w, h3);
    uint2 hp = make_uint2((uint32_t)h0 | ((uint32_t)h1 << 16), (uint32_t)h2 | ((uint32_t)h3 << 16));
    uint2 lp = make_uint2((uint32_t)l0 | ((uint32_t)l1 << 16), (uint32_t)l2 | ((uint32_t)l3 << 16));
    unsigned short* row = g_A2y + (size_t)m * K2 + c;          // A2 = [hi|hi|lo]
    *(uint2*)(row) = hp;
    *(uint2*)(row + EDIM) = hp;
    *(uint2*)(row + 2 * EDIM) = lp;
}

// ---------------- mma GEMM mainloop (128x128 tile over K2) ------------------
// smem tiles [128 rows][64 cols bf16] = [128][8] 16B groups, swizzle g^=(row&7)
#define SW_ADDR(base, row, g) ((base) + (row) * 128u + (uint32_t)(((g) ^ ((row) & 7)) << 4))

static __device__ __forceinline__ void mma_mainloop(
    const unsigned short* __restrict__ Ag, const unsigned short* __restrict__ Bg,
    uint32_t smA_a, uint32_t smB_a, float acc[4][4][4],
    int tid, int lane, int wm, int wn)
{
    const int ldrow = tid >> 3;          // 0..31 base row (x4 strided by 32)
    const int ldg   = tid & 7;           // 16B group 0..7
    const unsigned short* Ap = Ag + (size_t)ldrow * K2 + ldg * 8;
    const unsigned short* Bp = Bg + (size_t)ldrow * K2 + ldg * 8;

    uint4 va[4], vb[4];
    #pragma unroll
    for (int i = 0; i < 4; i++) {
        va[i] = *(const uint4*)(Ap + (size_t)(i * 32) * K2);
        vb[i] = *(const uint4*)(Bp + (size_t)(i * 32) * K2);
    }

    for (int kc = 0; kc < NCHUNK; kc++) {
        __syncthreads();
        #pragma unroll
        for (int i = 0; i < 4; i++) {
            const int row = ldrow + i * 32;
            *(uint4*)(uintptr_t)0;  // (placeholder removed below)
        }
        // store to smem (swizzled) -- generic smem pointers
        #pragma unroll
        for (int i = 0; i < 4; i++) {
            const int row = ldrow + i * 32;
            asm volatile("st.shared.v4.b32 [%0], {%1,%2,%3,%4};"
                :: "r"(SW_ADDR(smA_a, row, ldg)),
                   "r"(va[i].x), "r"(va[i].y), "r"(va[i].z), "r"(va[i].w));
            asm volatile("st.shared.v4.b32 [%0], {%1,%2,%3,%4};"
                :: "r"(SW_ADDR(smB_a, row, ldg)),
                   "r"(vb[i].x), "r"(vb[i].y), "r"(vb[i].z), "r"(vb[i].w));
        }
        __syncthreads();

        if (kc + 1 < NCHUNK) {           // prefetch next chunk
            const unsigned short* Ap2 = Ap + (kc + 1) * 64;
            const unsigned short* Bp2 = Bp + (kc + 1) * 64;
            #pragma unroll
            for (int i = 0; i < 4; i++) {
                va[i] = *(const uint4*)(Ap2 + (size_t)(i * 32) * K2);
                vb[i] = *(const uint4*)(Bp2 + (size_t)(i * 32) * K2);
            }
        }

        #pragma unroll
        for (int ks = 0; ks < 4; ks++) {
            // B fragments: 4 n-tiles of n8 x k16
            uint32_t b0[4], b1[4];
            #pragma unroll
            for (int ni = 0; ni < 4; ni++) {
                const int row = wn * 32 + ni * 8 + (lane & 7);
                const int g = ks * 2 + ((lane >> 3) & 1);
                ldmx2(b0[ni], b1[ni], SW_ADDR(smB_a, row, g));
            }
            #pragma unroll
            for (int mi = 0; mi < 4; mi++) {
                const int row = wm * 64 + mi * 16 + (lane & 15);
                const int g = ks * 2 + (lane >> 4);
                uint32_t a0, a1, a2, a3;
                ldmx4(a0, a1, a2, a3, SW_ADDR(smA_a, row, g));
                #pragma unroll
                for (int ni = 0; ni < 4; ni++)
                    mma16816(acc[mi][ni][0], acc[mi][ni][1], acc[mi][ni][2], acc[mi][ni][3],
                             a0, a1, a2, a3, b0[ni], b1[ni]);
            }
        }
    }
}

// ---------------- kernel 2: QKV GEMM (mma.sync bf16) -------------------------
__global__ __launch_bounds__(256) void gemm_qkv_mma(const float* __restrict__ bias)
{
    __shared__ __align__(16) unsigned short smA[128 * 64];
    __shared__ __align__(16) unsigned short smB[128 * 64];
    const int tid = threadIdx.x, lane = tid & 31, wid = tid >> 5;
    const int wm = wid >> 2, wn = wid & 3;
    const int m0 = blockIdx.y * 128, n0 = blockIdx.x * 128;

    float acc[4][4][4];
    #pragma unroll
    for (int i = 0; i < 4; i++)
        #pragma unroll
        for (int j = 0; j < 4; j++)
            #pragma unroll
            for (int c = 0; c < 4; c++) acc[i][j][c] = 0.f;

    mma_mainloop(g_A2y + (size_t)m0 * K2, g_B2q + (size_t)n0 * K2,
                 smem_u32(smA), smem_u32(smB), acc, tid, lane, wm, wn);

    // epilogue: bias + scatter to Q/K/V [b,h,s,d]
    const int gid = lane >> 2, tin = lane & 3;
    const int which = n0 >> 10;                   // tile fully inside one of q/k/v
    float* dstA = (which == 0) ? g_Qb : (which == 1) ? g_Kb : g_Vb;
    #pragma unroll
    for (int mi = 0; mi < 4; mi++) {
        #pragma unroll
        for (int half = 0; half < 2; half++) {
            const int m = m0 + wm * 64 + mi * 16 + gid + half * 8;
            const int b = m >> 11, s = m & (SEQ - 1);
            #pragma unroll
            for (int ni = 0; ni < 4; ni++) {
                const int n = n0 + wn * 32 + ni * 8 + tin * 2;
                const int e = n & (EDIM - 1);
                const int h = e >> 6, d = e & (DHEAD - 1);
                float2 v;
                v.x = acc[mi][ni][half * 2 + 0] + bias[n];
                v.y = acc[mi][ni][half * 2 + 1] + bias[n + 1];
                *(float2*)(dstA + (size_t)((b * HEADS + h) * SEQ + s) * DHEAD + d) = v;
            }
        }
    }
}

// ---------------- kernel 4: out-proj GEMM (mma.sync) + residual --------------
__global__ __launch_bounds__(256) void gemm_out_mma(const float* __restrict__ yres)
{
    __shared__ __align__(16) unsigned short smA[128 * 64];
    __shared__ __align__(16) unsigned short smB[128 * 64];
    const int tid = threadIdx.x, lane = tid & 31, wid = tid >> 5;
    const int wm = wid >> 2, wn = wid & 3;
    const int m0 = blockIdx.y * 128, n0 = blockIdx.x * 128;

    float acc[4][4][4];
    #pragma unroll
    for (int i = 0; i < 4; i++)
        #pragma unroll
        for (int j = 0; j < 4; j++)
            #pragma unroll
            for (int c = 0; c < 4; c++) acc[i][j][c] = 0.f;

    mma_mainloop(g_A2o + (size_t)m0 * K2, g_B2o + (size_t)n0 * K2,
                 smem_u32(smA), smem_u32(smB), acc, tid, lane, wm, wn);

    const int gid = lane >> 2, tin = lane & 3;
    #pragma unroll
    for (int mi = 0; mi < 4; mi++) {
        #pragma unroll
        for (int half = 0; half < 2; half++) {
            const int m = m0 + wm * 64 + mi * 16 + gid + half * 8;
            #pragma unroll
            for (int ni = 0; ni < 4; ni++) {
                const int n = n0 + wn * 32 + ni * 8 + tin * 2;
                float2 r = *(const float2*)(yres + (size_t)m * EDIM + n);
                float2 v;
                v.x = acc[mi][ni][half * 2 + 0] + r.x;
                v.y = acc[mi][ni][half * 2 + 1] + r.y;
                *(float2*)(g_Mb + (size_t)m * EDIM + n) = v;
            }
        }
    }
}

// ---------------- kernel 3: flash attention (fp32, f32x2) --------------------
#define ATT_STRIDE 68
#define ATT_SMEM   (3 * 64 * ATT_STRIDE * 4)
__global__ __launch_bounds__(256) void attn_kernel()
{
    extern __shared__ __align__(16) float sm[];
    float* Qt  = sm;
    float* KPt = sm + 64 * ATT_STRIDE;
    float* Vs  = sm + 2 * 64 * ATT_STRIDE;

    const int tid = threadIdx.x;
    const int tx = tid & 15, ty = tid >> 4;
    const int bh = blockIdx.y;
    const int q0 = blockIdx.x * 64;
    const float* Qg = g_Qb + ((size_t)bh * SEQ + q0) * DHEAD;
    const float* Kg = g_Kb + (size_t)bh * SEQ * DHEAD;
    const float* Vg = g_Vb + (size_t)bh * SEQ * DHEAD;

    #pragma unroll
    for (int p = 0; p < 4; p++) {
        const int fid = tid + p * 256;
        const int row = fid >> 4, c4 = (fid & 15) * 4;
        float4 qv = *(const float4*)(Qg + row * DHEAD + c4);
        Qt[(c4+0)*ATT_STRIDE+row] = qv.x; Qt[(c4+1)*ATT_STRIDE+row] = qv.y;
        Qt[(c4+2)*ATT_STRIDE+row] = qv.z; Qt[(c4+3)*ATT_STRIDE+row] = qv.w;
    }

    float m_i[4], l_i[4];
    unsigned long long o2[4][2];
    #pragma unroll
    for (int i = 0; i < 4; i++) {
        m_i[i] = -1e30f; l_i[i] = 0.f; o2[i][0] = 0ULL; o2[i][1] = 0ULL;
    }

    for (int t = 0; t < SEQ / 64; t++) {
        const float* Kt0 = Kg + t * 64 * DHEAD;
        const float* Vt0 = Vg + t * 64 * DHEAD;
        __syncthreads();
        #pragma unroll
        for (int p = 0; p < 4; p++) {
            const int fid = tid + p * 256;
            const int row = fid >> 4, c4 = (fid & 15) * 4;
            float4 kv = *(const float4*)(Kt0 + row * DHEAD + c4);
            KPt[(c4+0)*ATT_STRIDE+row] = kv.x; KPt[(c4+1)*ATT_STRIDE+row] = kv.y;
            KPt[(c4+2)*ATT_STRIDE+row] = kv.z; KPt[(c4+3)*ATT_STRIDE+row] = kv.w;
            float4 vv = *(const float4*)(Vt0 + row * DHEAD + c4);
            *(float4*)&Vs[row * ATT_STRIDE + c4] = vv;
        }
        __syncthreads();

        unsigned long long s2[4][2];
        #pragma unroll
        for (int i = 0; i < 4; i++) { s2[i][0] = 0ULL; s2[i][1] = 0ULL; }
        #pragma unroll 16
        for (int k = 0; k < 64; k++) {
            float4 qv = *(const float4*)&Qt[k * ATT_STRIDE + ty * 4];
            ulonglong2 kp = *(const ulonglong2*)&KPt[k * ATT_STRIDE + tx * 4];
            const float qa[4] = {qv.x, qv.y, qv.z, qv.w};
            #pragma unroll
            for (int i = 0; i < 4; i++) {
                unsigned long long qp = f2pack(qa[i]);
                s2[i][0] = ffma2(qp, kp.x, s2[i][0]);
                s2[i][1] = ffma2(qp, kp.y, s2[i][1]);
            }
        }

        float p4[4][4];
        #pragma unroll
        for (int i = 0; i < 4; i++) {
            float s0, s1, s2f, s3;
            unpack2(s2[i][0], s0, s1);
            unpack2(s2[i][1], s2f, s3);
            s0 *= 0.125f; s1 *= 0.125f; s2f *= 0.125f; s3 *= 0.125f;
            float tmax = fmaxf(fmaxf(s0, s1), fmaxf(s2f, s3));
            #pragma unroll
            for (int off = 8; off >= 1; off >>= 1)
                tmax = fmaxf(tmax, __shfl_xor_sync(0xffffffffu, tmax, off));
            const float nm = fmaxf(m_i[i], tmax);
            const float alpha = __expf(m_i[i] - nm);
            const float e0 = __expf(s0 - nm), e1 = __expf(s1 - nm);
            const float e2 = __expf(s2f - nm), e3 = __expf(s3 - nm);
            float rs = e0 + e1 + e2 + e3;
            #pragma unroll
            for (int off = 8; off >= 1; off >>= 1)
                rs += __shfl_xor_sync(0xffffffffu, rs, off);
            l_i[i] = l_i[i] * alpha + rs;
            m_i[i] = nm;
            p4[i][0] = e0; p4[i][1] = e1; p4[i][2] = e2; p4[i][3] = e3;
            const unsigned long long am = f2pack(alpha);
            o2[i][0] = fmul2(o2[i][0], am);
            o2[i][1] = fmul2(o2[i][1], am);
        }

        __syncthreads();
        #pragma unroll
        for (int i = 0; i < 4; i++)
            #pragma unroll
            for (int j = 0; j < 4; j++)
                KPt[(tx * 4 + j) * ATT_STRIDE + ty * 4 + i] = p4[i][j];
        __syncthreads();

        #pragma unroll 16
        for (int kv = 0; kv < 64; kv++) {
            float4 pv = *(const float4*)&KPt[kv * ATT_STRIDE + ty * 4];
            ulonglong2 vv = *(const ulonglong2*)&Vs[kv * ATT_STRIDE + tx * 4];
            const float pa[4] = {pv.x, pv.y, pv.z, pv.w};
            #pragma unroll
            for (int i = 0; i < 4; i++) {
                unsigned long long pp = f2pack(pa[i]);
                o2[i][0] = ffma2(pp, vv.x, o2[i][0]);
                o2[i][1] = ffma2(pp, vv.y, o2[i][1]);
            }
        }
    }

    // epilogue: O /= l, write split-bf16 directly into A2o extended layout
    const int b = bh >> 4, h = bh & (HEADS - 1);
    #pragma unroll
    for (int i = 0; i < 4; i++) {
        const float inv = 1.0f / l_i[i];
        float x0, x1, x2, x3;
        unpack2(o2[i][0], x0, x1);
        unpack2(o2[i][1], x2, x3);
        x0 *= inv; x1 *= inv; x2 *= inv; x3 *= inv;
        unsigned short h0 = bf_hi(x0), h1 = bf_hi(x1), h2 = bf_hi(x2), h3 = bf_hi(x3);
        unsigned short l0 = bf_lo(x0, h0), l1 = bf_lo(x1, h1), l2 = bf_lo(x2, h2), l3 = bf_lo(x3, h3);
        uint2 hp = make_uint2((uint32_t)h0 | ((uint32_t)h1 << 16), (uint32_t)h2 | ((uint32_t)h3 << 16));
        uint2 lp = make_uint2((uint32_t)l0 | ((uint32_t)l1 << 16), (uint32_t)l2 | ((uint32_t)l3 << 16));
        const int srow = q0 + ty * 4 + i;
        unsigned short* row = g_A2o + (size_t)(b * SEQ + srow) * K2 + h * DHEAD + tx * 4;
        *(uint2*)(row) = hp;
        *(uint2*)(row + EDIM) = hp;
        *(uint2*)(row + 2 * EDIM) = lp;
    }
}

// ---------------- kernel 5: LayerNorm ---------------------------------------
__global__ __launch_bounds__(256) void ln_kernel(
    const float* __restrict__ gamma, const float* __restrict__ beta,
    float* __restrict__ out)
{
    const int row = blockIdx.x;
    const int tid = threadIdx.x;
    const float4 v = *(const float4*)&g_Mb[(size_t)row * EDIM + tid * 4];
    float s = v.x + v.y + v.z + v.w;
    float q = v.x * v.x + v.y * v.y + v.z * v.z + v.w * v.w;
    #pragma unroll
    for (int off = 16; off >= 1; off >>= 1) {
        s += __shfl_xor_sync(0xffffffffu, s, off);
        q += __shfl_xor_sync(0xffffffffu, q, off);
    }
    __shared__ float ss[8], sq[8];
    const int w = tid >> 5, lane = tid & 31;
    if (lane == 0) { ss[w] = s; sq[w] = q; }
    __syncthreads();
    float tot = 0.f, totq = 0.f;
    #pragma unroll
    for (int i = 0; i < 8; i++) { tot += ss[i]; totq += sq[i]; }
    const float mu = tot * (1.0f / EDIM);
    const float var = totq * (1.0f / EDIM) - mu * mu;
    const float rs = rsqrtf(var + 1e-6f);
    const float4 g = *(const float4*)&gamma[tid * 4];
    const float4 bb = *(const float4*)&beta[tid * 4];
    float4 o;
    o.x = (v.x - mu) * rs * g.x + bb.x;
    o.y = (v.y - mu) * rs * g.y + bb.y;
    o.z = (v.z - mu) * rs * g.z + bb.z;
    o.w = (v.w - mu) * rs * g.w + bb.w;
    *(float4*)&out[(size_t)row * EDIM + tid * 4] = o;
}

// ---------------- launcher --------------------------------------------------
extern "C" void kernel_launch(void* const* d_in, const int* in_sizes, int n_in,
                              void* d_out, int out_size)
{
    (void)in_sizes; (void)n_in; (void)out_size;
    const float* y    = (const float*)d_in[0];
    const float* Wqkv = (const float*)d_in[1];
    const float* bqkv = (const float*)d_in[2];
    const float* Wmsa = (const float*)d_in[3];
    const float* Bq   = (const float*)d_in[4];
    const float* Aq   = (const float*)d_in[5];
    const float* Bk   = (const float*)d_in[6];
    const float* Ak   = (const float*)d_in[7];
    const float* Bv   = (const float*)d_in[8];
    const float* Av   = (const float*)d_in[9];
    const float* Bo   = (const float*)d_in[10];
    const float* Ao   = (const float*)d_in[11];
    const float* gamma= (const float*)d_in[12];
    const float* beta = (const float*)d_in[13];
    float* out = (float*)d_out;

    prep_weights<<<(4 * EDIM * EDIM) / 256, 256>>>(Wqkv, Wmsa, Bq, Aq, Bk, Ak, Bv, Av, Bo, Ao);
    convert_y<<<(MTOT * EDIM / 4) / 256, 256>>>(y);
    gemm_qkv_mma<<<dim3(3 * EDIM / 128, MTOT / 128), 256>>>(bqkv);
    (void)cudaFuncSetAttribute(attn_kernel, cudaFuncAttributeMaxDynamicSharedMemorySize, ATT_SMEM);
    attn_kernel<<<dim3(SEQ / 64, BATCH * HEADS), 256, ATT_SMEM>>>();
    gemm_out_mma<<<dim3(EDIM / 128, MTOT / 128), 256>>>(y);
    ln_kernel<<<MTOT, 256>>>(gamma, beta, out);
}

// round 6
// speedup vs baseline: 2.6888x; 1.7658x over previous
#include <cuda_runtime.h>
#include <cuda_bf16.h>
#include <cstdint>

#define EDIM   1024
#define HEADS  16
#define DHEAD  64
#define BATCH  2
#define SEQ    2048
#define RANK   8
#define MTOT   (BATCH*SEQ)
#define K2     3072          // extended K: A=[hi|hi|lo], B=[hi|lo|hi]
#define NCHUNK 48            // K2 / 64

// ---------------- scratch (device globals; no allocations allowed) ----------
__device__ unsigned short g_A2y[(size_t)MTOT*K2];      // y split-bf16 extended
__device__ unsigned short g_B2q[(size_t)3*EDIM*K2];    // folded qkv weights split-bf16
__device__ unsigned short g_A2o[(size_t)MTOT*K2];      // attention out split-bf16
__device__ unsigned short g_B2o[(size_t)EDIM*K2];      // folded out-proj weights split-bf16
__device__ unsigned short g_Qh[(size_t)BATCH*HEADS*SEQ*DHEAD];  // Q/8 hi  [bh][s][d]
__device__ unsigned short g_Ql[(size_t)BATCH*HEADS*SEQ*DHEAD];  // Q/8 lo
__device__ unsigned short g_Kh[(size_t)BATCH*HEADS*SEQ*DHEAD];
__device__ unsigned short g_Kl[(size_t)BATCH*HEADS*SEQ*DHEAD];
__device__ unsigned short g_Vh[(size_t)BATCH*HEADS*SEQ*DHEAD];
__device__ unsigned short g_Vl[(size_t)BATCH*HEADS*SEQ*DHEAD];
__device__ float g_Mb[(size_t)MTOT*EDIM];              // msa + residual

// ---------------- bf16 split helpers ----------------------------------------
static __device__ __forceinline__ unsigned short bf_hi(float x) {
    return __bfloat16_as_ushort(__float2bfloat16(x));
}
static __device__ __forceinline__ unsigned short bf_lo(float x, unsigned short h) {
    float hf = __bfloat162float(__ushort_as_bfloat16(h));
    return __bfloat16_as_ushort(__float2bfloat16(x - hf));
}
// pack two fp32 -> bf16x2 (lo in low half)
static __device__ __forceinline__ uint32_t cvt_bf2(float lo, float hi) {
    uint32_t r;
    asm("cvt.rn.bf16x2.f32 %0, %1, %2;" : "=r"(r) : "f"(hi), "f"(lo));
    return r;
}

// ---------------- mma.sync helpers -------------------------------------------
static __device__ __forceinline__ uint32_t smem_u32(const void* p) {
    uint32_t a;
    asm("{ .reg .u64 t; cvta.to.shared.u64 t, %1; cvt.u32.u64 %0, t; }" : "=r"(a) : "l"(p));
    return a;
}
static __device__ __forceinline__ void ldmx4(
    uint32_t& r0, uint32_t& r1, uint32_t& r2, uint32_t& r3, uint32_t a) {
    asm volatile("ldmatrix.sync.aligned.m8n8.x4.shared.b16 {%0,%1,%2,%3}, [%4];"
                 : "=r"(r0), "=r"(r1), "=r"(r2), "=r"(r3) : "r"(a));
}
static __device__ __forceinline__ void ldmx4t(
    uint32_t& r0, uint32_t& r1, uint32_t& r2, uint32_t& r3, uint32_t a) {
    asm volatile("ldmatrix.sync.aligned.m8n8.x4.trans.shared.b16 {%0,%1,%2,%3}, [%4];"
                 : "=r"(r0), "=r"(r1), "=r"(r2), "=r"(r3) : "r"(a));
}
static __device__ __forceinline__ void ldmx2(
    uint32_t& r0, uint32_t& r1, uint32_t a) {
    asm volatile("ldmatrix.sync.aligned.m8n8.x2.shared.b16 {%0,%1}, [%2];"
                 : "=r"(r0), "=r"(r1) : "r"(a));
}
static __device__ __forceinline__ void mma16816(
    float& d0, float& d1, float& d2, float& d3,
    uint32_t a0, uint32_t a1, uint32_t a2, uint32_t a3,
    uint32_t b0, uint32_t b1) {
    asm volatile("mma.sync.aligned.m16n8k16.row.col.f32.bf16.bf16.f32 "
                 "{%0,%1,%2,%3}, {%4,%5,%6,%7}, {%8,%9}, {%0,%1,%2,%3};"
                 : "+f"(d0), "+f"(d1), "+f"(d2), "+f"(d3)
                 : "r"(a0), "r"(a1), "r"(a2), "r"(a3), "r"(b0), "r"(b1));
}

// smem tiles [rows][64 cols bf16] = [rows][8] 16B groups, swizzle g^=(row&7)
#define SW_ADDR(base, row, g) ((base) + (row) * 128u + (uint32_t)(((g) ^ ((row) & 7)) << 4))

// ---------------- kernel 1: fold LoRA + split weights to bf16 ---------------
__global__ __launch_bounds__(256) void prep_weights(
    const float* __restrict__ Wqkv, const float* __restrict__ Wmsa,
    const float* __restrict__ Bq, const float* __restrict__ Aq,
    const float* __restrict__ Bk, const float* __restrict__ Ak,
    const float* __restrict__ Bv, const float* __restrict__ Av,
    const float* __restrict__ Bo, const float* __restrict__ Ao)
{
    const int idx = blockIdx.x * blockDim.x + threadIdx.x;
    const int NQKV = 3 * EDIM * EDIM;
    if (idx < NQKV) {
        const int o = idx >> 10;          // output row [0,3E)
        const int i = idx & (EDIM - 1);   // input col
        const int which = o >> 10;
        const int e = o & (EDIM - 1);
        const float* Bw = (which == 0) ? Bq : (which == 1) ? Bk : Bv;
        const float* Aw = (which == 0) ? Aq : (which == 1) ? Ak : Av;
        float acc = Wqkv[idx];
        #pragma unroll
        for (int r = 0; r < RANK; r++) acc += Bw[i * RANK + r] * Aw[r * EDIM + e];
        unsigned short h = bf_hi(acc), l = bf_lo(acc, h);
        unsigned short* row = g_B2q + (size_t)o * K2;
        row[i] = h; row[EDIM + i] = l; row[2 * EDIM + i] = h;   // B2 = [hi|lo|hi]
    } else {
        const int j = idx - NQKV;
        const int o = j >> 10;
        const int i = j & (EDIM - 1);
        float acc = Wmsa[j];
        #pragma unroll
        for (int r = 0; r < RANK; r++) acc += Bo[i * RANK + r] * Ao[r * EDIM + o];
        unsigned short h = bf_hi(acc), l = bf_lo(acc, h);
        unsigned short* row = g_B2o + (size_t)o * K2;
        row[i] = h; row[EDIM + i] = l; row[2 * EDIM + i] = h;
    }
}

// ---------------- kernel 1b: split y to bf16 extended -----------------------
__global__ __launch_bounds__(256) void convert_y(const float* __restrict__ y)
{
    const int idx = blockIdx.x * blockDim.x + threadIdx.x;   // one per 4 floats
    const int m = idx >> 8;
    const int c = (idx & 255) * 4;
    float4 v = *(const float4*)(y + (size_t)m * EDIM + c);
    unsigned short h0 = bf_hi(v.x), h1 = bf_hi(v.y), h2 = bf_hi(v.z), h3 = bf_hi(v.w);
    unsigned short l0 = bf_lo(v.x, h0), l1 = bf_lo(v.y, h1), l2 = bf_lo(v.z, h2), l3 = bf_lo(v.w, h3);
    uint2 hp = make_uint2((uint32_t)h0 | ((uint32_t)h1 << 16), (uint32_t)h2 | ((uint32_t)h3 << 16));
    uint2 lp = make_uint2((uint32_t)l0 | ((uint32_t)l1 << 16), (uint32_t)l2 | ((uint32_t)l3 << 16));
    unsigned short* row = g_A2y + (size_t)m * K2 + c;          // A2 = [hi|hi|lo]
    *(uint2*)(row) = hp;
    *(uint2*)(row + EDIM) = hp;
    *(uint2*)(row + 2 * EDIM) = lp;
}

// ---------------- mma GEMM mainloop (128x128 tile over K2) ------------------
static __device__ __forceinline__ void mma_mainloop(
    const unsigned short* __restrict__ Ag, const unsigned short* __restrict__ Bg,
    uint32_t smA_a, uint32_t smB_a, float acc[4][4][4],
    int tid, int lane, int wm, int wn)
{
    const int ldrow = tid >> 3;          // 0..31 base row (x4 strided by 32)
    const int ldg   = tid & 7;           // 16B group 0..7
    const unsigned short* Ap = Ag + (size_t)ldrow * K2 + ldg * 8;
    const unsigned short* Bp = Bg + (size_t)ldrow * K2 + ldg * 8;

    uint4 va[4], vb[4];
    #pragma unroll
    for (int i = 0; i < 4; i++) {
        va[i] = *(const uint4*)(Ap + (size_t)(i * 32) * K2);
        vb[i] = *(const uint4*)(Bp + (size_t)(i * 32) * K2);
    }

    for (int kc = 0; kc < NCHUNK; kc++) {
        __syncthreads();
        #pragma unroll
        for (int i = 0; i < 4; i++) {
            const int row = ldrow + i * 32;
            asm volatile("st.shared.v4.b32 [%0], {%1,%2,%3,%4};"
                :: "r"(SW_ADDR(smA_a, row, ldg)),
                   "r"(va[i].x), "r"(va[i].y), "r"(va[i].z), "r"(va[i].w));
            asm volatile("st.shared.v4.b32 [%0], {%1,%2,%3,%4};"
                :: "r"(SW_ADDR(smB_a, row, ldg)),
                   "r"(vb[i].x), "r"(vb[i].y), "r"(vb[i].z), "r"(vb[i].w));
        }
        __syncthreads();

        if (kc + 1 < NCHUNK) {           // prefetch next chunk
            const unsigned short* Ap2 = Ap + (kc + 1) * 64;
            const unsigned short* Bp2 = Bp + (kc + 1) * 64;
            #pragma unroll
            for (int i = 0; i < 4; i++) {
                va[i] = *(const uint4*)(Ap2 + (size_t)(i * 32) * K2);
                vb[i] = *(const uint4*)(Bp2 + (size_t)(i * 32) * K2);
            }
        }

        #pragma unroll
        for (int ks = 0; ks < 4; ks++) {
            uint32_t b0[4], b1[4];
            #pragma unroll
            for (int ni = 0; ni < 4; ni++) {
                const int row = wn * 32 + ni * 8 + (lane & 7);
                const int g = ks * 2 + ((lane >> 3) & 1);
                ldmx2(b0[ni], b1[ni], SW_ADDR(smB_a, row, g));
            }
            #pragma unroll
            for (int mi = 0; mi < 4; mi++) {
                const int row = wm * 64 + mi * 16 + (lane & 15);
                const int g = ks * 2 + (lane >> 4);
                uint32_t a0, a1, a2, a3;
                ldmx4(a0, a1, a2, a3, SW_ADDR(smA_a, row, g));
                #pragma unroll
                for (int ni = 0; ni < 4; ni++)
                    mma16816(acc[mi][ni][0], acc[mi][ni][1], acc[mi][ni][2], acc[mi][ni][3],
                             a0, a1, a2, a3, b0[ni], b1[ni]);
            }
        }
    }
}

// ---------------- kernel 2: QKV GEMM (mma.sync bf16) -------------------------
// epilogue: bias, Q scaled by 1/8, split to hi/lo bf16 [bh][s][d] arrays
__global__ __launch_bounds__(256) void gemm_qkv_mma(const float* __restrict__ bias)
{
    __shared__ __align__(16) unsigned short smA[128 * 64];
    __shared__ __align__(16) unsigned short smB[128 * 64];
    const int tid = threadIdx.x, lane = tid & 31, wid = tid >> 5;
    const int wm = wid >> 2, wn = wid & 3;
    const int m0 = blockIdx.y * 128, n0 = blockIdx.x * 128;

    float acc[4][4][4];
    #pragma unroll
    for (int i = 0; i < 4; i++)
        #pragma unroll
        for (int j = 0; j < 4; j++)
            #pragma unroll
            for (int c = 0; c < 4; c++) acc[i][j][c] = 0.f;

    mma_mainloop(g_A2y + (size_t)m0 * K2, g_B2q + (size_t)n0 * K2,
                 smem_u32(smA), smem_u32(smB), acc, tid, lane, wm, wn);

    const int gid = lane >> 2, tin = lane & 3;
    const int which = n0 >> 10;                   // 0=q 1=k 2=v (tile within one)
    unsigned short* Ha = (which == 0) ? g_Qh : (which == 1) ? g_Kh : g_Vh;
    unsigned short* La = (which == 0) ? g_Ql : (which == 1) ? g_Kl : g_Vl;
    const float qscale = (which == 0) ? 0.125f : 1.0f;
    #pragma unroll
    for (int mi = 0; mi < 4; mi++) {
        #pragma unroll
        for (int half = 0; half < 2; half++) {
            const int m = m0 + wm * 64 + mi * 16 + gid + half * 8;
            const int b = m >> 11, s = m & (SEQ - 1);
            #pragma unroll
            for (int ni = 0; ni < 4; ni++) {
                const int n = n0 + wn * 32 + ni * 8 + tin * 2;
                const int e = n & (EDIM - 1);
                const int h = e >> 6, d = e & (DHEAD - 1);
                float vx = (acc[mi][ni][half * 2 + 0] + bias[n]) * qscale;
                float vy = (acc[mi][ni][half * 2 + 1] + bias[n + 1]) * qscale;
                unsigned short h0 = bf_hi(vx), h1 = bf_hi(vy);
                unsigned short l0 = bf_lo(vx, h0), l1 = bf_lo(vy, h1);
                const size_t off = (size_t)((b * HEADS + h) * SEQ + s) * DHEAD + d;
                *(uint32_t*)(Ha + off) = (uint32_t)h0 | ((uint32_t)h1 << 16);
                *(uint32_t*)(La + off) = (uint32_t)l0 | ((uint32_t)l1 << 16);
            }
        }
    }
}

// ---------------- kernel 4: out-proj GEMM (mma.sync) + residual --------------
__global__ __launch_bounds__(256) void gemm_out_mma(const float* __restrict__ yres)
{
    __shared__ __align__(16) unsigned short smA[128 * 64];
    __shared__ __align__(16) unsigned short smB[128 * 64];
    const int tid = threadIdx.x, lane = tid & 31, wid = tid >> 5;
    const int wm = wid >> 2, wn = wid & 3;
    const int m0 = blockIdx.y * 128, n0 = blockIdx.x * 128;

    float acc[4][4][4];
    #pragma unroll
    for (int i = 0; i < 4; i++)
        #pragma unroll
        for (int j = 0; j < 4; j++)
            #pragma unroll
            for (int c = 0; c < 4; c++) acc[i][j][c] = 0.f;

    mma_mainloop(g_A2o + (size_t)m0 * K2, g_B2o + (size_t)n0 * K2,
                 smem_u32(smA), smem_u32(smB), acc, tid, lane, wm, wn);

    const int gid = lane >> 2, tin = lane & 3;
    #pragma unroll
    for (int mi = 0; mi < 4; mi++) {
        #pragma unroll
        for (int half = 0; half < 2; half++) {
            const int m = m0 + wm * 64 + mi * 16 + gid + half * 8;
            #pragma unroll
            for (int ni = 0; ni < 4; ni++) {
                const int n = n0 + wn * 32 + ni * 8 + tin * 2;
                float2 r = *(const float2*)(yres + (size_t)m * EDIM + n);
                float2 v;
                v.x = acc[mi][ni][half * 2 + 0] + r.x;
                v.y = acc[mi][ni][half * 2 + 1] + r.y;
                *(float2*)(g_Mb + (size_t)m * EDIM + n) = v;
            }
        }
    }
}

// ---------------- kernel 3: flash attention (mma.sync bf16 split) ------------
// grid (SEQ/128, B*H), 256 thr, 8 warps: warp w owns q-rows [w*16, w*16+16)
#define ATTN_SMEM (6 * 128 * 64 * 2)   // Qh Ql Kh Kl Vh Vl tiles, 96 KB
__global__ __launch_bounds__(256, 1) void attn_mma()
{
    extern __shared__ __align__(16) unsigned short smatt[];
    unsigned short* sQh = smatt;
    unsigned short* sQl = smatt + 8192;
    unsigned short* sKh = smatt + 2 * 8192;
    unsigned short* sKl = smatt + 3 * 8192;
    unsigned short* sVh = smatt + 4 * 8192;
    unsigned short* sVl = smatt + 5 * 8192;

    const int tid = threadIdx.x, lane = tid & 31, w = tid >> 5;
    const int gid = lane >> 2, tin = lane & 3;
    const int bh = blockIdx.y, q0 = blockIdx.x * 128;
    const size_t hbase = (size_t)bh * SEQ * DHEAD;

    // load Q tiles (scaled by 1/8 already)
    {
        const int row = tid >> 3, g = tid & 7;
        #pragma unroll
        for (int i = 0; i < 4; i++) {
            const int r = row + i * 32;
            const size_t src = hbase + (size_t)(q0 + r) * DHEAD + g * 8;
            uint4 vh = *(const uint4*)(g_Qh + src);
            uint4 vl = *(const uint4*)(g_Ql + src);
            asm volatile("st.shared.v4.b32 [%0], {%1,%2,%3,%4};"
                :: "r"(SW_ADDR(smem_u32(sQh), r, g)), "r"(vh.x), "r"(vh.y), "r"(vh.z), "r"(vh.w));
            asm volatile("st.shared.v4.b32 [%0], {%1,%2,%3,%4};"
                :: "r"(SW_ADDR(smem_u32(sQl), r, g)), "r"(vl.x), "r"(vl.y), "r"(vl.z), "r"(vl.w));
        }
    }
    __syncthreads();

    // Q fragments in registers (A-frags, m16k16 per kstep)
    uint32_t qh[4][4], ql[4][4];
    #pragma unroll
    for (int ks = 0; ks < 4; ks++) {
        const int row = w * 16 + (lane & 15);
        const int g = ks * 2 + (lane >> 4);
        ldmx4(qh[ks][0], qh[ks][1], qh[ks][2], qh[ks][3], SW_ADDR(smem_u32(sQh), row, g));
        ldmx4(ql[ks][0], ql[ks][1], ql[ks][2], ql[ks][3], SW_ADDR(smem_u32(sQl), row, g));
    }

    const uint32_t aKh = smem_u32(sKh), aKl = smem_u32(sKl);
    const uint32_t aVh = smem_u32(sVh), aVl = smem_u32(sVl);

    float ma = -1e30f, mb = -1e30f, la = 0.f, lb = 0.f;
    float o[8][4];
    #pragma unroll
    for (int i = 0; i < 8; i++)
        #pragma unroll
        for (int c = 0; c < 4; c++) o[i][c] = 0.f;

    for (int t = 0; t < SEQ / 128; t++) {
        __syncthreads();   // previous iteration's ldmatrix reads done
        {
            const int row = tid >> 3, g = tid & 7;
            #pragma unroll
            for (int i = 0; i < 4; i++) {
                const int r = row + i * 32;
                const size_t src = hbase + (size_t)(t * 128 + r) * DHEAD + g * 8;
                uint4 kh = *(const uint4*)(g_Kh + src);
                uint4 kl = *(const uint4*)(g_Kl + src);
                uint4 vh = *(const uint4*)(g_Vh + src);
                uint4 vl = *(const uint4*)(g_Vl + src);
                asm volatile("st.shared.v4.b32 [%0], {%1,%2,%3,%4};"
                    :: "r"(SW_ADDR(aKh, r, g)), "r"(kh.x), "r"(kh.y), "r"(kh.z), "r"(kh.w));
                asm volatile("st.shared.v4.b32 [%0], {%1,%2,%3,%4};"
                    :: "r"(SW_ADDR(aKl, r, g)), "r"(kl.x), "r"(kl.y), "r"(kl.z), "r"(kl.w));
                asm volatile("st.shared.v4.b32 [%0], {%1,%2,%3,%4};"
                    :: "r"(SW_ADDR(aVh, r, g)), "r"(vh.x), "r"(vh.y), "r"(vh.z), "r"(vh.w));
                asm volatile("st.shared.v4.b32 [%0], {%1,%2,%3,%4};"
                    :: "r"(SW_ADDR(aVl, r, g)), "r"(vl.x), "r"(vl.y), "r"(vl.z), "r"(vl.w));
            }
        }
        __syncthreads();

        // ---- S = Q K^T (3-term split), per warp 16 x 128 -------------------
        float s[16][4];
        #pragma unroll
        for (int i = 0; i < 16; i++)
            #pragma unroll
            for (int c = 0; c < 4; c++) s[i][c] = 0.f;

        const int q4 = lane >> 3;
        #pragma unroll
        for (int ks = 0; ks < 4; ks++) {
            #pragma unroll
            for (int nio = 0; nio < 8; nio++) {
                const int krow = (2 * nio + (q4 >> 1)) * 8 + (lane & 7);
                const int kg = ks * 2 + (q4 & 1);
                uint32_t b0, b1, b2, b3;
                ldmx4(b0, b1, b2, b3, SW_ADDR(aKh, krow, kg));
                mma16816(s[2*nio][0], s[2*nio][1], s[2*nio][2], s[2*nio][3],
                         qh[ks][0], qh[ks][1], qh[ks][2], qh[ks][3], b0, b1);
                mma16816(s[2*nio+1][0], s[2*nio+1][1], s[2*nio+1][2], s[2*nio+1][3],
                         qh[ks][0], qh[ks][1], qh[ks][2], qh[ks][3], b2, b3);
                mma16816(s[2*nio][0], s[2*nio][1], s[2*nio][2], s[2*nio][3],
                         ql[ks][0], ql[ks][1], ql[ks][2], ql[ks][3], b0, b1);
                mma16816(s[2*nio+1][0], s[2*nio+1][1], s[2*nio+1][2], s[2*nio+1][3],
                         ql[ks][0], ql[ks][1], ql[ks][2], ql[ks][3], b2, b3);
                uint32_t c0, c1, c2, c3;
                ldmx4(c0, c1, c2, c3, SW_ADDR(aKl, krow, kg));
                mma16816(s[2*nio][0], s[2*nio][1], s[2*nio][2], s[2*nio][3],
                         qh[ks][0], qh[ks][1], qh[ks][2], qh[ks][3], c0, c1);
                mma16816(s[2*nio+1][0], s[2*nio+1][1], s[2*nio+1][2], s[2*nio+1][3],
                         qh[ks][0], qh[ks][1], qh[ks][2], qh[ks][3], c2, c3);
            }
        }

        // ---- online softmax (rows: a = gid, b = gid+8, within warp) --------
        float mxa = -1e30f, mxb = -1e30f;
        #pragma unroll
        for (int i = 0; i < 16; i++) {
            mxa = fmaxf(mxa, fmaxf(s[i][0], s[i][1]));
            mxb = fmaxf(mxb, fmaxf(s[i][2], s[i][3]));
        }
        mxa = fmaxf(mxa, __shfl_xor_sync(0xffffffffu, mxa, 1));
        mxa = fmaxf(mxa, __shfl_xor_sync(0xffffffffu, mxa, 2));
        mxb = fmaxf(mxb, __shfl_xor_sync(0xffffffffu, mxb, 1));
        mxb = fmaxf(mxb, __shfl_xor_sync(0xffffffffu, mxb, 2));
        const float nma = fmaxf(ma, mxa), nmb = fmaxf(mb, mxb);
        const float alfa = __expf(ma - nma), alfb = __expf(mb - nmb);
        ma = nma; mb = nmb;
        float sa = 0.f, sb = 0.f;
        #pragma unroll
        for (int i = 0; i < 16; i++) {
            s[i][0] = __expf(s[i][0] - nma); sa += s[i][0];
            s[i][1] = __expf(s[i][1] - nma); sa += s[i][1];
            s[i][2] = __expf(s[i][2] - nmb); sb += s[i][2];
            s[i][3] = __expf(s[i][3] - nmb); sb += s[i][3];
        }
        sa += __shfl_xor_sync(0xffffffffu, sa, 1);
        sa += __shfl_xor_sync(0xffffffffu, sa, 2);
        sb += __shfl_xor_sync(0xffffffffu, sb, 1);
        sb += __shfl_xor_sync(0xffffffffu, sb, 2);
        la = la * alfa + sa;
        lb = lb * alfb + sb;
        #pragma unroll
        for (int i = 0; i < 8; i++) {
            o[i][0] *= alfa; o[i][1] *= alfa;
            o[i][2] *= alfb; o[i][3] *= alfb;
        }

        // ---- O += P V (3-term split, P in registers) -----------------------
        #pragma unroll
        for (int kj = 0; kj < 8; kj++) {
            // P A-frags: hi and lo
            uint32_t ph[4], pl[4];
            #pragma unroll
            for (int u = 0; u < 4; u++) {
                const int ni = 2 * kj + (u >> 1);
                const float p0 = s[ni][(u & 1) * 2 + 0];
                const float p1 = s[ni][(u & 1) * 2 + 1];
                const uint32_t hp = cvt_bf2(p0, p1);
                ph[u] = hp;
                const float f0 = __uint_as_float(hp << 16);
                const float f1 = __uint_as_float(hp & 0xffff0000u);
                pl[u] = cvt_bf2(p0 - f0, p1 - f1);
            }
            #pragma unroll
            for (int ndo = 0; ndo < 4; ndo++) {
                const int vrow = kj * 16 + (q4 & 1) * 8 + (lane & 7);
                const int vg = 2 * ndo + (q4 >> 1);
                uint32_t v0, v1, v2, v3;
                ldmx4t(v0, v1, v2, v3, SW_ADDR(aVh, vrow, vg));
                mma16816(o[2*ndo][0], o[2*ndo][1], o[2*ndo][2], o[2*ndo][3],
                         ph[0], ph[1], ph[2], ph[3], v0, v1);
                mma16816(o[2*ndo+1][0], o[2*ndo+1][1], o[2*ndo+1][2], o[2*ndo+1][3],
                         ph[0], ph[1], ph[2], ph[3], v2, v3);
                mma16816(o[2*ndo][0], o[2*ndo][1], o[2*ndo][2], o[2*ndo][3],
                         pl[0], pl[1], pl[2], pl[3], v0, v1);
                mma16816(o[2*ndo+1][0], o[2*ndo+1][1], o[2*ndo+1][2], o[2*ndo+1][3],
                         pl[0], pl[1], pl[2], pl[3], v2, v3);
                uint32_t u0, u1, u2, u3;
                ldmx4t(u0, u1, u2, u3, SW_ADDR(aVl, vrow, vg));
                mma16816(o[2*ndo][0], o[2*ndo][1], o[2*ndo][2], o[2*ndo][3],
                         ph[0], ph[1], ph[2], ph[3], u0, u1);
                mma16816(o[2*ndo+1][0], o[2*ndo+1][1], o[2*ndo+1][2], o[2*ndo+1][3],
                         ph[0], ph[1], ph[2], ph[3], u2, u3);
            }
        }
    }

    // ---- epilogue: O /= l, write split-bf16 into A2o extended layout -------
    const float inva = 1.0f / la, invb = 1.0f / lb;
    const int b = bh >> 4, h = bh & (HEADS - 1);
    const int ra = q0 + w * 16 + gid, rb = ra + 8;
    unsigned short* rowA = g_A2o + (size_t)(b * SEQ + ra) * K2 + h * DHEAD;
    unsigned short* rowB = g_A2o + (size_t)(b * SEQ + rb) * K2 + h * DHEAD;
    #pragma unroll
    for (int nd = 0; nd < 8; nd++) {
        const int d = nd * 8 + tin * 2;
        const float x0 = o[nd][0] * inva, x1 = o[nd][1] * inva;
        const float x2 = o[nd][2] * invb, x3 = o[nd][3] * invb;
        unsigned short h0 = bf_hi(x0), h1 = bf_hi(x1);
        unsigned short l0 = bf_lo(x0, h0), l1 = bf_lo(x1, h1);
        unsigned short h2 = bf_hi(x2), h3 = bf_hi(x3);
        unsigned short l2 = bf_lo(x2, h2), l3 = bf_lo(x3, h3);
        const uint32_t hpA = (uint32_t)h0 | ((uint32_t)h1 << 16);
        const uint32_t lpA = (uint32_t)l0 | ((uint32_t)l1 << 16);
        const uint32_t hpB = (uint32_t)h2 | ((uint32_t)h3 << 16);
        const uint32_t lpB = (uint32_t)l2 | ((uint32_t)l3 << 16);
        *(uint32_t*)(rowA + d) = hpA;
        *(uint32_t*)(rowA + EDIM + d) = hpA;
        *(uint32_t*)(rowA + 2 * EDIM + d) = lpA;
        *(uint32_t*)(rowB + d) = hpB;
        *(uint32_t*)(rowB + EDIM + d) = hpB;
        *(uint32_t*)(rowB + 2 * EDIM + d) = lpB;
    }
}

// ---------------- kernel 5: LayerNorm ---------------------------------------
__global__ __launch_bounds__(256) void ln_kernel(
    const float* __restrict__ gamma, const float* __restrict__ beta,
    float* __restrict__ out)
{
    const int row = blockIdx.x;
    const int tid = threadIdx.x;
    const float4 v = *(const float4*)&g_Mb[(size_t)row * EDIM + tid * 4];
    float s = v.x + v.y + v.z + v.w;
    float q = v.x * v.x + v.y * v.y + v.z * v.z + v.w * v.w;
    #pragma unroll
    for (int off = 16; off >= 1; off >>= 1) {
        s += __shfl_xor_sync(0xffffffffu, s, off);
        q += __shfl_xor_sync(0xffffffffu, q, off);
    }
    __shared__ float ss[8], sq[8];
    const int w = tid >> 5, lane = tid & 31;
    if (lane == 0) { ss[w] = s; sq[w] = q; }
    __syncthreads();
    float tot = 0.f, totq = 0.f;
    #pragma unroll
    for (int i = 0; i < 8; i++) { tot += ss[i]; totq += sq[i]; }
    const float mu = tot * (1.0f / EDIM);
    const float var = totq * (1.0f / EDIM) - mu * mu;
    const float rs = rsqrtf(var + 1e-6f);
    const float4 g = *(const float4*)&gamma[tid * 4];
    const float4 bb = *(const float4*)&beta[tid * 4];
    float4 o;
    o.x = (v.x - mu) * rs * g.x + bb.x;
    o.y = (v.y - mu) * rs * g.y + bb.y;
    o.z = (v.z - mu) * rs * g.z + bb.z;
    o.w = (v.w - mu) * rs * g.w + bb.w;
    *(float4*)&out[(size_t)row * EDIM + tid * 4] = o;
}

// ---------------- launcher --------------------------------------------------
extern "C" void kernel_launch(void* const* d_in, const int* in_sizes, int n_in,
                              void* d_out, int out_size)
{
    (void)in_sizes; (void)n_in; (void)out_size;
    const float* y    = (const float*)d_in[0];
    const float* Wqkv = (const float*)d_in[1];
    const float* bqkv = (const float*)d_in[2];
    const float* Wmsa = (const float*)d_in[3];
    const float* Bq   = (const float*)d_in[4];
    const float* Aq   = (const float*)d_in[5];
    const float* Bk   = (const float*)d_in[6];
    const float* Ak   = (const float*)d_in[7];
    const float* Bv   = (const float*)d_in[8];
    const float* Av   = (const float*)d_in[9];
    const float* Bo   = (const float*)d_in[10];
    const float* Ao   = (const float*)d_in[11];
    const float* gamma= (const float*)d_in[12];
    const float* beta = (const float*)d_in[13];
    float* out = (float*)d_out;

    prep_weights<<<(4 * EDIM * EDIM) / 256, 256>>>(Wqkv, Wmsa, Bq, Aq, Bk, Ak, Bv, Av, Bo, Ao);
    convert_y<<<(MTOT * EDIM / 4) / 256, 256>>>(y);
    gemm_qkv_mma<<<dim3(3 * EDIM / 128, MTOT / 128), 256>>>(bqkv);
    (void)cudaFuncSetAttribute(attn_mma, cudaFuncAttributeMaxDynamicSharedMemorySize, ATTN_SMEM);
    attn_mma<<<dim3(SEQ / 128, BATCH * HEADS), 256, ATTN_SMEM>>>();
    gemm_out_mma<<<dim3(EDIM / 128, MTOT / 128), 256>>>(y);
    ln_kernel<<<MTOT, 256>>>(gamma, beta, out);
}

// round 7
// speedup vs baseline: 2.9539x; 1.0986x over previous
#include <cuda_runtime.h>
#include <cuda_bf16.h>
#include <cstdint>

#define EDIM   1024
#define HEADS  16
#define DHEAD  64
#define BATCH  2
#define SEQ    2048
#define RANK   8
#define MTOT   (BATCH*SEQ)
#define K2     3072          // extended K: A=[hi|hi|lo], B=[hi|lo|hi]
#define NCHUNK 48            // K2 / 64

// ---------------- scratch (device globals; no allocations allowed) ----------
__device__ unsigned short g_A2y[(size_t)MTOT*K2];      // y split-bf16 extended
__device__ unsigned short g_B2q[(size_t)3*EDIM*K2];    // folded qkv weights split-bf16
__device__ unsigned short g_A2o[(size_t)MTOT*K2];      // attention out split-bf16
__device__ unsigned short g_B2o[(size_t)EDIM*K2];      // folded out-proj weights split-bf16
__device__ unsigned short g_Qh[(size_t)BATCH*HEADS*SEQ*DHEAD];  // Q/8 hi  [bh][s][d]
__device__ unsigned short g_Ql[(size_t)BATCH*HEADS*SEQ*DHEAD];  // Q/8 lo
__device__ unsigned short g_Kh[(size_t)BATCH*HEADS*SEQ*DHEAD];
__device__ unsigned short g_Kl[(size_t)BATCH*HEADS*SEQ*DHEAD];
__device__ unsigned short g_Vh[(size_t)BATCH*HEADS*SEQ*DHEAD];
__device__ unsigned short g_Vl[(size_t)BATCH*HEADS*SEQ*DHEAD];
__device__ float g_Mb[(size_t)MTOT*EDIM];              // msa + residual

// ---------------- bf16 split helpers ----------------------------------------
static __device__ __forceinline__ unsigned short bf_hi(float x) {
    return __bfloat16_as_ushort(__float2bfloat16(x));
}
static __device__ __forceinline__ unsigned short bf_lo(float x, unsigned short h) {
    float hf = __bfloat162float(__ushort_as_bfloat16(h));
    return __bfloat16_as_ushort(__float2bfloat16(x - hf));
}
static __device__ __forceinline__ uint32_t cvt_bf2(float lo, float hi) {
    uint32_t r;
    asm("cvt.rn.bf16x2.f32 %0, %1, %2;" : "=r"(r) : "f"(hi), "f"(lo));
    return r;
}

// ---------------- mma.sync helpers -------------------------------------------
static __device__ __forceinline__ uint32_t smem_u32(const void* p) {
    uint32_t a;
    asm("{ .reg .u64 t; cvta.to.shared.u64 t, %1; cvt.u32.u64 %0, t; }" : "=r"(a) : "l"(p));
    return a;
}
static __device__ __forceinline__ void ldmx4(
    uint32_t& r0, uint32_t& r1, uint32_t& r2, uint32_t& r3, uint32_t a) {
    asm volatile("ldmatrix.sync.aligned.m8n8.x4.shared.b16 {%0,%1,%2,%3}, [%4];"
                 : "=r"(r0), "=r"(r1), "=r"(r2), "=r"(r3) : "r"(a));
}
static __device__ __forceinline__ void ldmx4t(
    uint32_t& r0, uint32_t& r1, uint32_t& r2, uint32_t& r3, uint32_t a) {
    asm volatile("ldmatrix.sync.aligned.m8n8.x4.trans.shared.b16 {%0,%1,%2,%3}, [%4];"
                 : "=r"(r0), "=r"(r1), "=r"(r2), "=r"(r3) : "r"(a));
}
static __device__ __forceinline__ void mma16816(
    float& d0, float& d1, float& d2, float& d3,
    uint32_t a0, uint32_t a1, uint32_t a2, uint32_t a3,
    uint32_t b0, uint32_t b1) {
    asm volatile("mma.sync.aligned.m16n8k16.row.col.f32.bf16.bf16.f32 "
                 "{%0,%1,%2,%3}, {%4,%5,%6,%7}, {%8,%9}, {%0,%1,%2,%3};"
                 : "+f"(d0), "+f"(d1), "+f"(d2), "+f"(d3)
                 : "r"(a0), "r"(a1), "r"(a2), "r"(a3), "r"(b0), "r"(b1));
}
#define CP_ASYNC16(dst, src) \
    asm volatile("cp.async.cg.shared.global [%0], [%1], 16;" :: "r"(dst), "l"(src))
#define CP_COMMIT() asm volatile("cp.async.commit_group;" ::: "memory")
#define CP_WAIT1()  asm volatile("cp.async.wait_group 1;" ::: "memory")
#define CP_WAIT0()  asm volatile("cp.async.wait_group 0;" ::: "memory")

// smem tiles [rows][64 cols bf16] = [rows][8] 16B groups, swizzle g^=(row&7)
#define SW_ADDR(base, row, g) ((base) + (row) * 128u + (uint32_t)(((g) ^ ((row) & 7)) << 4))

// ---------------- kernel 1: fold LoRA + split weights to bf16 ---------------
__global__ __launch_bounds__(256) void prep_weights(
    const float* __restrict__ Wqkv, const float* __restrict__ Wmsa,
    const float* __restrict__ Bq, const float* __restrict__ Aq,
    const float* __restrict__ Bk, const float* __restrict__ Ak,
    const float* __restrict__ Bv, const float* __restrict__ Av,
    const float* __restrict__ Bo, const float* __restrict__ Ao)
{
    const int idx = blockIdx.x * blockDim.x + threadIdx.x;
    const int NQKV = 3 * EDIM * EDIM;
    if (idx < NQKV) {
        const int o = idx >> 10;
        const int i = idx & (EDIM - 1);
        const int which = o >> 10;
        const int e = o & (EDIM - 1);
        const float* Bw = (which == 0) ? Bq : (which == 1) ? Bk : Bv;
        const float* Aw = (which == 0) ? Aq : (which == 1) ? Ak : Av;
        float acc = Wqkv[idx];
        #pragma unroll
        for (int r = 0; r < RANK; r++) acc += Bw[i * RANK + r] * Aw[r * EDIM + e];
        unsigned short h = bf_hi(acc), l = bf_lo(acc, h);
        unsigned short* row = g_B2q + (size_t)o * K2;
        row[i] = h; row[EDIM + i] = l; row[2 * EDIM + i] = h;   // B2 = [hi|lo|hi]
    } else {
        const int j = idx - NQKV;
        const int o = j >> 10;
        const int i = j & (EDIM - 1);
        float acc = Wmsa[j];
        #pragma unroll
        for (int r = 0; r < RANK; r++) acc += Bo[i * RANK + r] * Ao[r * EDIM + o];
        unsigned short h = bf_hi(acc), l = bf_lo(acc, h);
        unsigned short* row = g_B2o + (size_t)o * K2;
        row[i] = h; row[EDIM + i] = l; row[2 * EDIM + i] = h;
    }
}

// ---------------- kernel 1b: split y to bf16 extended -----------------------
__global__ __launch_bounds__(256) void convert_y(const float* __restrict__ y)
{
    const int idx = blockIdx.x * blockDim.x + threadIdx.x;
    const int m = idx >> 8;
    const int c = (idx & 255) * 4;
    float4 v = *(const float4*)(y + (size_t)m * EDIM + c);
    unsigned short h0 = bf_hi(v.x), h1 = bf_hi(v.y), h2 = bf_hi(v.z), h3 = bf_hi(v.w);
    unsigned short l0 = bf_lo(v.x, h0), l1 = bf_lo(v.y, h1), l2 = bf_lo(v.z, h2), l3 = bf_lo(v.w, h3);
    uint2 hp = make_uint2((uint32_t)h0 | ((uint32_t)h1 << 16), (uint32_t)h2 | ((uint32_t)h3 << 16));
    uint2 lp = make_uint2((uint32_t)l0 | ((uint32_t)l1 << 16), (uint32_t)l2 | ((uint32_t)l3 << 16));
    unsigned short* row = g_A2y + (size_t)m * K2 + c;          // A2 = [hi|hi|lo]
    *(uint2*)(row) = hp;
    *(uint2*)(row + EDIM) = hp;
    *(uint2*)(row + 2 * EDIM) = lp;
}

// ---------------- big-tile GEMM mainloop: 256x128 tile, cp.async x2 ----------
// dynamic smem (ushort offsets): A0=0 (256x64), B0=16384 (128x64), A1=24576, B1=40960
static __device__ __forceinline__ void issue_loads(
    const unsigned short* __restrict__ Ag, const unsigned short* __restrict__ Bg,
    uint32_t sa, uint32_t sb, int kc, int tid)
{
    const int r0 = tid >> 3, g = tid & 7;
    const int koff = kc * 64 + g * 8;
    #pragma unroll
    for (int p = 0; p < 8; p++) {
        const int row = p * 32 + r0;
        CP_ASYNC16(SW_ADDR(sa, row, g), Ag + (size_t)row * K2 + koff);
    }
    #pragma unroll
    for (int p = 0; p < 4; p++) {
        const int row = p * 32 + r0;
        CP_ASYNC16(SW_ADDR(sb, row, g), Bg + (size_t)row * K2 + koff);
    }
    CP_COMMIT();
}

static __device__ __forceinline__ void mma_mainloop_big(
    const unsigned short* __restrict__ Ag, const unsigned short* __restrict__ Bg,
    uint32_t smbase, float acc[4][8][4], int tid, int lane, int wm, int wn)
{
    const uint32_t sA[2] = {smbase, smbase + 49152u};           // bytes
    const uint32_t sB[2] = {smbase + 32768u, smbase + 81920u};

    issue_loads(Ag, Bg, sA[0], sB[0], 0, tid);
    issue_loads(Ag, Bg, sA[1], sB[1], 1, tid);

    const int q = lane >> 3;                 // 0..3 quad-of-8
    for (int kc = 0; kc < NCHUNK; kc++) {
        const int st = kc & 1;
        if (kc >= NCHUNK - 2) { CP_WAIT0(); } else { CP_WAIT1(); }
        __syncthreads();

        #pragma unroll
        for (int ks = 0; ks < 4; ks++) {
            uint32_t bf[4][4];
            #pragma unroll
            for (int p = 0; p < 4; p++) {
                const int brow = wn * 64 + p * 16 + (q >> 1) * 8 + (lane & 7);
                const int bg = ks * 2 + (q & 1);
                ldmx4(bf[p][0], bf[p][1], bf[p][2], bf[p][3], SW_ADDR(sB[st], brow, bg));
            }
            #pragma unroll
            for (int mi = 0; mi < 4; mi++) {
                const int arow = wm * 64 + mi * 16 + (lane & 15);
                const int ag = ks * 2 + (lane >> 4);
                uint32_t a0, a1, a2, a3;
                ldmx4(a0, a1, a2, a3, SW_ADDR(sA[st], arow, ag));
                #pragma unroll
                for (int p = 0; p < 4; p++) {
                    mma16816(acc[mi][2*p][0], acc[mi][2*p][1], acc[mi][2*p][2], acc[mi][2*p][3],
                             a0, a1, a2, a3, bf[p][0], bf[p][1]);
                    mma16816(acc[mi][2*p+1][0], acc[mi][2*p+1][1], acc[mi][2*p+1][2], acc[mi][2*p+1][3],
                             a0, a1, a2, a3, bf[p][2], bf[p][3]);
                }
            }
        }
        __syncthreads();
        if (kc + 2 < NCHUNK)
            issue_loads(Ag, Bg, sA[st], sB[st], kc + 2, tid);
    }
}

// ---------------- kernel 2: QKV GEMM (256x128, cp.async) ---------------------
// grid (3072/128=24, 4096/256=16); epilogue: bias, Q*(1/8), split hi/lo
__global__ __launch_bounds__(256, 1) void gemm_qkv_mma(const float* __restrict__ bias)
{
    extern __shared__ __align__(16) unsigned short smg[];
    const int tid = threadIdx.x, lane = tid & 31, wid = tid >> 5;
    const int wm = wid >> 1, wn = wid & 1;
    const int m0 = blockIdx.y * 256, n0 = blockIdx.x * 128;

    float acc[4][8][4];
    #pragma unroll
    for (int i = 0; i < 4; i++)
        #pragma unroll
        for (int j = 0; j < 8; j++)
            #pragma unroll
            for (int c = 0; c < 4; c++) acc[i][j][c] = 0.f;

    mma_mainloop_big(g_A2y + (size_t)m0 * K2, g_B2q + (size_t)n0 * K2,
                     smem_u32(smg), acc, tid, lane, wm, wn);

    const int gid = lane >> 2, tin = lane & 3;
    const int which = n0 >> 10;                   // 0=q 1=k 2=v
    unsigned short* Ha = (which == 0) ? g_Qh : (which == 1) ? g_Kh : g_Vh;
    unsigned short* La = (which == 0) ? g_Ql : (which == 1) ? g_Kl : g_Vl;
    const float qscale = (which == 0) ? 0.125f : 1.0f;
    #pragma unroll
    for (int mi = 0; mi < 4; mi++) {
        #pragma unroll
        for (int half = 0; half < 2; half++) {
            const int m = m0 + wm * 64 + mi * 16 + gid + half * 8;
            const int b = m >> 11, s = m & (SEQ - 1);
            #pragma unroll
            for (int ni = 0; ni < 8; ni++) {
                const int n = n0 + wn * 64 + ni * 8 + tin * 2;
                const int e = n & (EDIM - 1);
                const int h = e >> 6, d = e & (DHEAD - 1);
                float vx = (acc[mi][ni][half * 2 + 0] + bias[n]) * qscale;
                float vy = (acc[mi][ni][half * 2 + 1] + bias[n + 1]) * qscale;
                unsigned short h0 = bf_hi(vx), h1 = bf_hi(vy);
                unsigned short l0 = bf_lo(vx, h0), l1 = bf_lo(vy, h1);
                const size_t off = (size_t)((b * HEADS + h) * SEQ + s) * DHEAD + d;
                *(uint32_t*)(Ha + off) = (uint32_t)h0 | ((uint32_t)h1 << 16);
                *(uint32_t*)(La + off) = (uint32_t)l0 | ((uint32_t)l1 << 16);
            }
        }
    }
}

// ---------------- kernel 4: out-proj GEMM (256x128) + residual ---------------
// grid (1024/128=8, 4096/256=16)
__global__ __launch_bounds__(256, 1) void gemm_out_mma(const float* __restrict__ yres)
{
    extern __shared__ __align__(16) unsigned short smg[];
    const int tid = threadIdx.x, lane = tid & 31, wid = tid >> 5;
    const int wm = wid >> 1, wn = wid & 1;
    const int m0 = blockIdx.y * 256, n0 = blockIdx.x * 128;

    float acc[4][8][4];
    #pragma unroll
    for (int i = 0; i < 4; i++)
        #pragma unroll
        for (int j = 0; j < 8; j++)
            #pragma unroll
            for (int c = 0; c < 4; c++) acc[i][j][c] = 0.f;

    mma_mainloop_big(g_A2o + (size_t)m0 * K2, g_B2o + (size_t)n0 * K2,
                     smem_u32(smg), acc, tid, lane, wm, wn);

    const int gid = lane >> 2, tin = lane & 3;
    #pragma unroll
    for (int mi = 0; mi < 4; mi++) {
        #pragma unroll
        for (int half = 0; half < 2; half++) {
            const int m = m0 + wm * 64 + mi * 16 + gid + half * 8;
            #pragma unroll
            for (int ni = 0; ni < 8; ni++) {
                const int n = n0 + wn * 64 + ni * 8 + tin * 2;
                float2 r = *(const float2*)(yres + (size_t)m * EDIM + n);
                float2 v;
                v.x = acc[mi][ni][half * 2 + 0] + r.x;
                v.y = acc[mi][ni][half * 2 + 1] + r.y;
                *(float2*)(g_Mb + (size_t)m * EDIM + n) = v;
            }
        }
    }
}

// ---------------- kernel 3: flash attention (mma.sync bf16 split) ------------
#define ATTN_SMEM (6 * 128 * 64 * 2)   // Qh Ql Kh Kl Vh Vl tiles, 96 KB
__global__ __launch_bounds__(256, 1) void attn_mma()
{
    extern __shared__ __align__(16) unsigned short smatt[];
    unsigned short* sQh = smatt;
    unsigned short* sQl = smatt + 8192;
    unsigned short* sKh = smatt + 2 * 8192;
    unsigned short* sKl = smatt + 3 * 8192;
    unsigned short* sVh = smatt + 4 * 8192;
    unsigned short* sVl = smatt + 5 * 8192;

    const int tid = threadIdx.x, lane = tid & 31, w = tid >> 5;
    const int gid = lane >> 2, tin = lane & 3;
    const int bh = blockIdx.y, q0 = blockIdx.x * 128;
    const size_t hbase = (size_t)bh * SEQ * DHEAD;

    {
        const int row = tid >> 3, g = tid & 7;
        #pragma unroll
        for (int i = 0; i < 4; i++) {
            const int r = row + i * 32;
            const size_t src = hbase + (size_t)(q0 + r) * DHEAD + g * 8;
            uint4 vh = *(const uint4*)(g_Qh + src);
            uint4 vl = *(const uint4*)(g_Ql + src);
            asm volatile("st.shared.v4.b32 [%0], {%1,%2,%3,%4};"
                :: "r"(SW_ADDR(smem_u32(sQh), r, g)), "r"(vh.x), "r"(vh.y), "r"(vh.z), "r"(vh.w));
            asm volatile("st.shared.v4.b32 [%0], {%1,%2,%3,%4};"
                :: "r"(SW_ADDR(smem_u32(sQl), r, g)), "r"(vl.x), "r"(vl.y), "r"(vl.z), "r"(vl.w));
        }
    }
    __syncthreads();

    uint32_t qh[4][4], ql[4][4];
    #pragma unroll
    for (int ks = 0; ks < 4; ks++) {
        const int row = w * 16 + (lane & 15);
        const int g = ks * 2 + (lane >> 4);
        ldmx4(qh[ks][0], qh[ks][1], qh[ks][2], qh[ks][3], SW_ADDR(smem_u32(sQh), row, g));
        ldmx4(ql[ks][0], ql[ks][1], ql[ks][2], ql[ks][3], SW_ADDR(smem_u32(sQl), row, g));
    }

    const uint32_t aKh = smem_u32(sKh), aKl = smem_u32(sKl);
    const uint32_t aVh = smem_u32(sVh), aVl = smem_u32(sVl);

    float ma = -1e30f, mb = -1e30f, la = 0.f, lb = 0.f;
    float o[8][4];
    #pragma unroll
    for (int i = 0; i < 8; i++)
        #pragma unroll
        for (int c = 0; c < 4; c++) o[i][c] = 0.f;

    for (int t = 0; t < SEQ / 128; t++) {
        __syncthreads();
        {
            const int row = tid >> 3, g = tid & 7;
            #pragma unroll
            for (int i = 0; i < 4; i++) {
                const int r = row + i * 32;
                const size_t src = hbase + (size_t)(t * 128 + r) * DHEAD + g * 8;
                uint4 kh = *(const uint4*)(g_Kh + src);
                uint4 kl = *(const uint4*)(g_Kl + src);
                uint4 vh = *(const uint4*)(g_Vh + src);
                uint4 vl = *(const uint4*)(g_Vl + src);
                asm volatile("st.shared.v4.b32 [%0], {%1,%2,%3,%4};"
                    :: "r"(SW_ADDR(aKh, r, g)), "r"(kh.x), "r"(kh.y), "r"(kh.z), "r"(kh.w));
                asm volatile("st.shared.v4.b32 [%0], {%1,%2,%3,%4};"
                    :: "r"(SW_ADDR(aKl, r, g)), "r"(kl.x), "r"(kl.y), "r"(kl.z), "r"(kl.w));
                asm volatile("st.shared.v4.b32 [%0], {%1,%2,%3,%4};"
                    :: "r"(SW_ADDR(aVh, r, g)), "r"(vh.x), "r"(vh.y), "r"(vh.z), "r"(vh.w));
                asm volatile("st.shared.v4.b32 [%0], {%1,%2,%3,%4};"
                    :: "r"(SW_ADDR(aVl, r, g)), "r"(vl.x), "r"(vl.y), "r"(vl.z), "r"(vl.w));
            }
        }
        __syncthreads();

        float s[16][4];
        #pragma unroll
        for (int i = 0; i < 16; i++)
            #pragma unroll
            for (int c = 0; c < 4; c++) s[i][c] = 0.f;

        const int q4 = lane >> 3;
        #pragma unroll
        for (int ks = 0; ks < 4; ks++) {
            #pragma unroll
            for (int nio = 0; nio < 8; nio++) {
                const int krow = (2 * nio + (q4 >> 1)) * 8 + (lane & 7);
                const int kg = ks * 2 + (q4 & 1);
                uint32_t b0, b1, b2, b3;
                ldmx4(b0, b1, b2, b3, SW_ADDR(aKh, krow, kg));
                mma16816(s[2*nio][0], s[2*nio][1], s[2*nio][2], s[2*nio][3],
                         qh[ks][0], qh[ks][1], qh[ks][2], qh[ks][3], b0, b1);
                mma16816(s[2*nio+1][0], s[2*nio+1][1], s[2*nio+1][2], s[2*nio+1][3],
                         qh[ks][0], qh[ks][1], qh[ks][2], qh[ks][3], b2, b3);
                mma16816(s[2*nio][0], s[2*nio][1], s[2*nio][2], s[2*nio][3],
                         ql[ks][0], ql[ks][1], ql[ks][2], ql[ks][3], b0, b1);
                mma16816(s[2*nio+1][0], s[2*nio+1][1], s[2*nio+1][2], s[2*nio+1][3],
                         ql[ks][0], ql[ks][1], ql[ks][2], ql[ks][3], b2, b3);
                uint32_t c0, c1, c2, c3;
                ldmx4(c0, c1, c2, c3, SW_ADDR(aKl, krow, kg));
                mma16816(s[2*nio][0], s[2*nio][1], s[2*nio][2], s[2*nio][3],
                         qh[ks][0], qh[ks][1], qh[ks][2], qh[ks][3], c0, c1);
                mma16816(s[2*nio+1][0], s[2*nio+1][1], s[2*nio+1][2], s[2*nio+1][3],
                         qh[ks][0], qh[ks][1], qh[ks][2], qh[ks][3], c2, c3);
            }
        }

        float mxa = -1e30f, mxb = -1e30f;
        #pragma unroll
        for (int i = 0; i < 16; i++) {
            mxa = fmaxf(mxa, fmaxf(s[i][0], s[i][1]));
            mxb = fmaxf(mxb, fmaxf(s[i][2], s[i][3]));
        }
        mxa = fmaxf(mxa, __shfl_xor_sync(0xffffffffu, mxa, 1));
        mxa = fmaxf(mxa, __shfl_xor_sync(0xffffffffu, mxa, 2));
        mxb = fmaxf(mxb, __shfl_xor_sync(0xffffffffu, mxb, 1));
        mxb = fmaxf(mxb, __shfl_xor_sync(0xffffffffu, mxb, 2));
        const float nma = fmaxf(ma, mxa), nmb = fmaxf(mb, mxb);
        const float alfa = __expf(ma - nma), alfb = __expf(mb - nmb);
        ma = nma; mb = nmb;
        float sa = 0.f, sb = 0.f;
        #pragma unroll
        for (int i = 0; i < 16; i++) {
            s[i][0] = __expf(s[i][0] - nma); sa += s[i][0];
            s[i][1] = __expf(s[i][1] - nma); sa += s[i][1];
            s[i][2] = __expf(s[i][2] - nmb); sb += s[i][2];
            s[i][3] = __expf(s[i][3] - nmb); sb += s[i][3];
        }
        sa += __shfl_xor_sync(0xffffffffu, sa, 1);
        sa += __shfl_xor_sync(0xffffffffu, sa, 2);
        sb += __shfl_xor_sync(0xffffffffu, sb, 1);
        sb += __shfl_xor_sync(0xffffffffu, sb, 2);
        la = la * alfa + sa;
        lb = lb * alfb + sb;
        #pragma unroll
        for (int i = 0; i < 8; i++) {
            o[i][0] *= alfa; o[i][1] *= alfa;
            o[i][2] *= alfb; o[i][3] *= alfb;
        }

        #pragma unroll
        for (int kj = 0; kj < 8; kj++) {
            uint32_t ph[4], pl[4];
            #pragma unroll
            for (int u = 0; u < 4; u++) {
                const int ni = 2 * kj + (u >> 1);
                const float p0 = s[ni][(u & 1) * 2 + 0];
                const float p1 = s[ni][(u & 1) * 2 + 1];
                const uint32_t hp = cvt_bf2(p0, p1);
                ph[u] = hp;
                const float f0 = __uint_as_float(hp << 16);
                const float f1 = __uint_as_float(hp & 0xffff0000u);
                pl[u] = cvt_bf2(p0 - f0, p1 - f1);
            }
            #pragma unroll
            for (int ndo = 0; ndo < 4; ndo++) {
                const int vrow = kj * 16 + (q4 & 1) * 8 + (lane & 7);
                const int vg = 2 * ndo + (q4 >> 1);
                uint32_t v0, v1, v2, v3;
                ldmx4t(v0, v1, v2, v3, SW_ADDR(aVh, vrow, vg));
                mma16816(o[2*ndo][0], o[2*ndo][1], o[2*ndo][2], o[2*ndo][3],
                         ph[0], ph[1], ph[2], ph[3], v0, v1);
                mma16816(o[2*ndo+1][0], o[2*ndo+1][1], o[2*ndo+1][2], o[2*ndo+1][3],
                         ph[0], ph[1], ph[2], ph[3], v2, v3);
                mma16816(o[2*ndo][0], o[2*ndo][1], o[2*ndo][2], o[2*ndo][3],
                         pl[0], pl[1], pl[2], pl[3], v0, v1);
                mma16816(o[2*ndo+1][0], o[2*ndo+1][1], o[2*ndo+1][2], o[2*ndo+1][3],
                         pl[0], pl[1], pl[2], pl[3], v2, v3);
                uint32_t u0, u1, u2, u3;
                ldmx4t(u0, u1, u2, u3, SW_ADDR(aVl, vrow, vg));
                mma16816(o[2*ndo][0], o[2*ndo][1], o[2*ndo][2], o[2*ndo][3],
                         ph[0], ph[1], ph[2], ph[3], u0, u1);
                mma16816(o[2*ndo+1][0], o[2*ndo+1][1], o[2*ndo+1][2], o[2*ndo+1][3],
                         ph[0], ph[1], ph[2], ph[3], u2, u3);
            }
        }
    }

    const float inva = 1.0f / la, invb = 1.0f / lb;
    const int b = bh >> 4, h = bh & (HEADS - 1);
    const int ra = q0 + w * 16 + gid, rb = ra + 8;
    unsigned short* rowA = g_A2o + (size_t)(b * SEQ + ra) * K2 + h * DHEAD;
    unsigned short* rowB = g_A2o + (size_t)(b * SEQ + rb) * K2 + h * DHEAD;
    #pragma unroll
    for (int nd = 0; nd < 8; nd++) {
        const int d = nd * 8 + tin * 2;
        const float x0 = o[nd][0] * inva, x1 = o[nd][1] * inva;
        const float x2 = o[nd][2] * invb, x3 = o[nd][3] * invb;
        unsigned short h0 = bf_hi(x0), h1 = bf_hi(x1);
        unsigned short l0 = bf_lo(x0, h0), l1 = bf_lo(x1, h1);
        unsigned short h2 = bf_hi(x2), h3 = bf_hi(x3);
        unsigned short l2 = bf_lo(x2, h2), l3 = bf_lo(x3, h3);
        const uint32_t hpA = (uint32_t)h0 | ((uint32_t)h1 << 16);
        const uint32_t lpA = (uint32_t)l0 | ((uint32_t)l1 << 16);
        const uint32_t hpB = (uint32_t)h2 | ((uint32_t)h3 << 16);
        const uint32_t lpB = (uint32_t)l2 | ((uint32_t)l3 << 16);
        *(uint32_t*)(rowA + d) = hpA;
        *(uint32_t*)(rowA + EDIM + d) = hpA;
        *(uint32_t*)(rowA + 2 * EDIM + d) = lpA;
        *(uint32_t*)(rowB + d) = hpB;
        *(uint32_t*)(rowB + EDIM + d) = hpB;
        *(uint32_t*)(rowB + 2 * EDIM + d) = lpB;
    }
}

// ---------------- kernel 5: LayerNorm ---------------------------------------
__global__ __launch_bounds__(256) void ln_kernel(
    const float* __restrict__ gamma, const float* __restrict__ beta,
    float* __restrict__ out)
{
    const int row = blockIdx.x;
    const int tid = threadIdx.x;
    const float4 v = *(const float4*)&g_Mb[(size_t)row * EDIM + tid * 4];
    float s = v.x + v.y + v.z + v.w;
    float q = v.x * v.x + v.y * v.y + v.z * v.z + v.w * v.w;
    #pragma unroll
    for (int off = 16; off >= 1; off >>= 1) {
        s += __shfl_xor_sync(0xffffffffu, s, off);
        q += __shfl_xor_sync(0xffffffffu, q, off);
    }
    __shared__ float ss[8], sq[8];
    const int w = tid >> 5, lane = tid & 31;
    if (lane == 0) { ss[w] = s; sq[w] = q; }
    __syncthreads();
    float tot = 0.f, totq = 0.f;
    #pragma unroll
    for (int i = 0; i < 8; i++) { tot += ss[i]; totq += sq[i]; }
    const float mu = tot * (1.0f / EDIM);
    const float var = totq * (1.0f / EDIM) - mu * mu;
    const float rs = rsqrtf(var + 1e-6f);
    const float4 g = *(const float4*)&gamma[tid * 4];
    const float4 bb = *(const float4*)&beta[tid * 4];
    float4 o;
    o.x = (v.x - mu) * rs * g.x + bb.x;
    o.y = (v.y - mu) * rs * g.y + bb.y;
    o.z = (v.z - mu) * rs * g.z + bb.z;
    o.w = (v.w - mu) * rs * g.w + bb.w;
    *(float4*)&out[(size_t)row * EDIM + tid * 4] = o;
}

// ---------------- launcher --------------------------------------------------
#define GEMM_SMEM (2 * (256 + 128) * 64 * 2)   // 96 KB

extern "C" void kernel_launch(void* const* d_in, const int* in_sizes, int n_in,
                              void* d_out, int out_size)
{
    (void)in_sizes; (void)n_in; (void)out_size;
    const float* y    = (const float*)d_in[0];
    const float* Wqkv = (const float*)d_in[1];
    const float* bqkv = (const float*)d_in[2];
    const float* Wmsa = (const float*)d_in[3];
    const float* Bq   = (const float*)d_in[4];
    const float* Aq   = (const float*)d_in[5];
    const float* Bk   = (const float*)d_in[6];
    const float* Ak   = (const float*)d_in[7];
    const float* Bv   = (const float*)d_in[8];
    const float* Av   = (const float*)d_in[9];
    const float* Bo   = (const float*)d_in[10];
    const float* Ao   = (const float*)d_in[11];
    const float* gamma= (const float*)d_in[12];
    const float* beta = (const float*)d_in[13];
    float* out = (float*)d_out;

    prep_weights<<<(4 * EDIM * EDIM) / 256, 256>>>(Wqkv, Wmsa, Bq, Aq, Bk, Ak, Bv, Av, Bo, Ao);
    convert_y<<<(MTOT * EDIM / 4) / 256, 256>>>(y);
    (void)cudaFuncSetAttribute(gemm_qkv_mma, cudaFuncAttributeMaxDynamicSharedMemorySize, GEMM_SMEM);
    (void)cudaFuncSetAttribute(gemm_out_mma, cudaFuncAttributeMaxDynamicSharedMemorySize, GEMM_SMEM);
    (void)cudaFuncSetAttribute(attn_mma, cudaFuncAttributeMaxDynamicSharedMemorySize, ATTN_SMEM);
    gemm_qkv_mma<<<dim3(3 * EDIM / 128, MTOT / 256), 256, GEMM_SMEM>>>(bqkv);
    attn_mma<<<dim3(SEQ / 128, BATCH * HEADS), 256, ATTN_SMEM>>>();
    gemm_out_mma<<<dim3(EDIM / 128, MTOT / 256), 256, GEMM_SMEM>>>(y);
    ln_kernel<<<MTOT, 256>>>(gamma, beta, out);
}

// round 8
// speedup vs baseline: 3.1516x; 1.0669x over previous
#include <cuda_runtime.h>
#include <cuda_bf16.h>
#include <cstdint>

#define EDIM   1024
#define HEADS  16
#define DHEAD  64
#define BATCH  2
#define SEQ    2048
#define RANK   8
#define MTOT   (BATCH*SEQ)
#define K2     3072          // extended K: A=[hi|hi|lo], B=[hi|lo|hi]
#define NCHUNK 48            // K2 / 64

// ---------------- scratch (device globals; no allocations allowed) ----------
__device__ unsigned short g_A2y[(size_t)MTOT*K2];      // y split-bf16 extended
__device__ unsigned short g_B2q[(size_t)3*EDIM*K2];    // folded qkv weights split-bf16
__device__ unsigned short g_A2o[(size_t)MTOT*K2];      // attention out split-bf16
__device__ unsigned short g_B2o[(size_t)EDIM*K2];      // folded out-proj weights split-bf16
__device__ unsigned short g_Qh[(size_t)BATCH*HEADS*SEQ*DHEAD];  // Q/8 hi  [bh][s][d]
__device__ unsigned short g_Ql[(size_t)BATCH*HEADS*SEQ*DHEAD];  // Q/8 lo
__device__ unsigned short g_Kh[(size_t)BATCH*HEADS*SEQ*DHEAD];
__device__ unsigned short g_Kl[(size_t)BATCH*HEADS*SEQ*DHEAD];
__device__ unsigned short g_Vh[(size_t)BATCH*HEADS*SEQ*DHEAD];
__device__ unsigned short g_Vl[(size_t)BATCH*HEADS*SEQ*DHEAD];
__device__ float g_Mb[(size_t)MTOT*EDIM];              // msa + residual

// ---------------- bf16 split helpers ----------------------------------------
static __device__ __forceinline__ unsigned short bf_hi(float x) {
    return __bfloat16_as_ushort(__float2bfloat16(x));
}
static __device__ __forceinline__ unsigned short bf_lo(float x, unsigned short h) {
    float hf = __bfloat162float(__ushort_as_bfloat16(h));
    return __bfloat16_as_ushort(__float2bfloat16(x - hf));
}
static __device__ __forceinline__ uint32_t cvt_bf2(float lo, float hi) {
    uint32_t r;
    asm("cvt.rn.bf16x2.f32 %0, %1, %2;" : "=r"(r) : "f"(hi), "f"(lo));
    return r;
}

// ---------------- mma.sync helpers -------------------------------------------
static __device__ __forceinline__ uint32_t smem_u32(const void* p) {
    uint32_t a;
    asm("{ .reg .u64 t; cvta.to.shared.u64 t, %1; cvt.u32.u64 %0, t; }" : "=r"(a) : "l"(p));
    return a;
}
static __device__ __forceinline__ void ldmx4(
    uint32_t& r0, uint32_t& r1, uint32_t& r2, uint32_t& r3, uint32_t a) {
    asm volatile("ldmatrix.sync.aligned.m8n8.x4.shared.b16 {%0,%1,%2,%3}, [%4];"
                 : "=r"(r0), "=r"(r1), "=r"(r2), "=r"(r3) : "r"(a));
}
static __device__ __forceinline__ void ldmx4t(
    uint32_t& r0, uint32_t& r1, uint32_t& r2, uint32_t& r3, uint32_t a) {
    asm volatile("ldmatrix.sync.aligned.m8n8.x4.trans.shared.b16 {%0,%1,%2,%3}, [%4];"
                 : "=r"(r0), "=r"(r1), "=r"(r2), "=r"(r3) : "r"(a));
}
static __device__ __forceinline__ void mma16816(
    float& d0, float& d1, float& d2, float& d3,
    uint32_t a0, uint32_t a1, uint32_t a2, uint32_t a3,
    uint32_t b0, uint32_t b1) {
    asm volatile("mma.sync.aligned.m16n8k16.row.col.f32.bf16.bf16.f32 "
                 "{%0,%1,%2,%3}, {%4,%5,%6,%7}, {%8,%9}, {%0,%1,%2,%3};"
                 : "+f"(d0), "+f"(d1), "+f"(d2), "+f"(d3)
                 : "r"(a0), "r"(a1), "r"(a2), "r"(a3), "r"(b0), "r"(b1));
}
#define CP_ASYNC16(dst, src) \
    asm volatile("cp.async.cg.shared.global [%0], [%1], 16;" :: "r"(dst), "l"(src))
#define CP_COMMIT() asm volatile("cp.async.commit_group;" ::: "memory")
#define CP_WAIT1()  asm volatile("cp.async.wait_group 1;" ::: "memory")
#define CP_WAIT0()  asm volatile("cp.async.wait_group 0;" ::: "memory")

// smem tiles [rows][64 cols bf16] = [rows][8] 16B groups, swizzle g^=(row&7)
#define SW_ADDR(base, row, g) ((base) + (row) * 128u + (uint32_t)(((g) ^ ((row) & 7)) << 4))

// ---------------- kernel 1: fold LoRA + split weights to bf16 ---------------
__global__ __launch_bounds__(256) void prep_weights(
    const float* __restrict__ Wqkv, const float* __restrict__ Wmsa,
    const float* __restrict__ Bq, const float* __restrict__ Aq,
    const float* __restrict__ Bk, const float* __restrict__ Ak,
    const float* __restrict__ Bv, const float* __restrict__ Av,
    const float* __restrict__ Bo, const float* __restrict__ Ao)
{
    const int idx = blockIdx.x * blockDim.x + threadIdx.x;
    const int NQKV = 3 * EDIM * EDIM;
    if (idx < NQKV) {
        const int o = idx >> 10;
        const int i = idx & (EDIM - 1);
        const int which = o >> 10;
        const int e = o & (EDIM - 1);
        const float* Bw = (which == 0) ? Bq : (which == 1) ? Bk : Bv;
        const float* Aw = (which == 0) ? Aq : (which == 1) ? Ak : Av;
        float acc = Wqkv[idx];
        #pragma unroll
        for (int r = 0; r < RANK; r++) acc += Bw[i * RANK + r] * Aw[r * EDIM + e];
        unsigned short h = bf_hi(acc), l = bf_lo(acc, h);
        unsigned short* row = g_B2q + (size_t)o * K2;
        row[i] = h; row[EDIM + i] = l; row[2 * EDIM + i] = h;   // B2 = [hi|lo|hi]
    } else {
        const int j = idx - NQKV;
        const int o = j >> 10;
        const int i = j & (EDIM - 1);
        float acc = Wmsa[j];
        #pragma unroll
        for (int r = 0; r < RANK; r++) acc += Bo[i * RANK + r] * Ao[r * EDIM + o];
        unsigned short h = bf_hi(acc), l = bf_lo(acc, h);
        unsigned short* row = g_B2o + (size_t)o * K2;
        row[i] = h; row[EDIM + i] = l; row[2 * EDIM + i] = h;
    }
}

// ---------------- kernel 1b: split y to bf16 extended -----------------------
__global__ __launch_bounds__(256) void convert_y(const float* __restrict__ y)
{
    const int idx = blockIdx.x * blockDim.x + threadIdx.x;
    const int m = idx >> 8;
    const int c = (idx & 255) * 4;
    float4 v = *(const float4*)(y + (size_t)m * EDIM + c);
    unsigned short h0 = bf_hi(v.x), h1 = bf_hi(v.y), h2 = bf_hi(v.z), h3 = bf_hi(v.w);
    unsigned short l0 = bf_lo(v.x, h0), l1 = bf_lo(v.y, h1), l2 = bf_lo(v.z, h2), l3 = bf_lo(v.w, h3);
    uint2 hp = make_uint2((uint32_t)h0 | ((uint32_t)h1 << 16), (uint32_t)h2 | ((uint32_t)h3 << 16));
    uint2 lp = make_uint2((uint32_t)l0 | ((uint32_t)l1 << 16), (uint32_t)l2 | ((uint32_t)l3 << 16));
    unsigned short* row = g_A2y + (size_t)m * K2 + c;          // A2 = [hi|hi|lo]
    *(uint2*)(row) = hp;
    *(uint2*)(row + EDIM) = hp;
    *(uint2*)(row + 2 * EDIM) = lp;
}

// ---------------- big-tile GEMM mainloop: 256x128 tile, cp.async x2 ----------
static __device__ __forceinline__ void issue_loads(
    const unsigned short* __restrict__ Ag, const unsigned short* __restrict__ Bg,
    uint32_t sa, uint32_t sb, int kc, int tid)
{
    const int r0 = tid >> 3, g = tid & 7;
    const int koff = kc * 64 + g * 8;
    #pragma unroll
    for (int p = 0; p < 8; p++) {
        const int row = p * 32 + r0;
        CP_ASYNC16(SW_ADDR(sa, row, g), Ag + (size_t)row * K2 + koff);
    }
    #pragma unroll
    for (int p = 0; p < 4; p++) {
        const int row = p * 32 + r0;
        CP_ASYNC16(SW_ADDR(sb, row, g), Bg + (size_t)row * K2 + koff);
    }
    CP_COMMIT();
}

static __device__ __forceinline__ void mma_mainloop_big(
    const unsigned short* __restrict__ Ag, const unsigned short* __restrict__ Bg,
    uint32_t smbase, float acc[4][8][4], int tid, int lane, int wm, int wn)
{
    const uint32_t sA[2] = {smbase, smbase + 49152u};           // bytes
    const uint32_t sB[2] = {smbase + 32768u, smbase + 81920u};

    issue_loads(Ag, Bg, sA[0], sB[0], 0, tid);
    issue_loads(Ag, Bg, sA[1], sB[1], 1, tid);

    const int q = lane >> 3;                 // 0..3 quad-of-8
    for (int kc = 0; kc < NCHUNK; kc++) {
        const int st = kc & 1;
        if (kc >= NCHUNK - 2) { CP_WAIT0(); } else { CP_WAIT1(); }
        __syncthreads();

        #pragma unroll
        for (int ks = 0; ks < 4; ks++) {
            uint32_t bf[4][4];
            #pragma unroll
            for (int p = 0; p < 4; p++) {
                const int brow = wn * 64 + p * 16 + (q >> 1) * 8 + (lane & 7);
                const int bg = ks * 2 + (q & 1);
                ldmx4(bf[p][0], bf[p][1], bf[p][2], bf[p][3], SW_ADDR(sB[st], brow, bg));
            }
            #pragma unroll
            for (int mi = 0; mi < 4; mi++) {
                const int arow = wm * 64 + mi * 16 + (lane & 15);
                const int ag = ks * 2 + (lane >> 4);
                uint32_t a0, a1, a2, a3;
                ldmx4(a0, a1, a2, a3, SW_ADDR(sA[st], arow, ag));
                #pragma unroll
                for (int p = 0; p < 4; p++) {
                    mma16816(acc[mi][2*p][0], acc[mi][2*p][1], acc[mi][2*p][2], acc[mi][2*p][3],
                             a0, a1, a2, a3, bf[p][0], bf[p][1]);
                    mma16816(acc[mi][2*p+1][0], acc[mi][2*p+1][1], acc[mi][2*p+1][2], acc[mi][2*p+1][3],
                             a0, a1, a2, a3, bf[p][2], bf[p][3]);
                }
            }
        }
        __syncthreads();
        if (kc + 2 < NCHUNK)
            issue_loads(Ag, Bg, sA[st], sB[st], kc + 2, tid);
    }
}

// ---------------- kernel 2: QKV GEMM (256x128, cp.async) ---------------------
__global__ __launch_bounds__(256, 1) void gemm_qkv_mma(const float* __restrict__ bias)
{
    extern __shared__ __align__(16) unsigned short smg[];
    const int tid = threadIdx.x, lane = tid & 31, wid = tid >> 5;
    const int wm = wid >> 1, wn = wid & 1;
    const int m0 = blockIdx.y * 256, n0 = blockIdx.x * 128;

    float acc[4][8][4];
    #pragma unroll
    for (int i = 0; i < 4; i++)
        #pragma unroll
        for (int j = 0; j < 8; j++)
            #pragma unroll
            for (int c = 0; c < 4; c++) acc[i][j][c] = 0.f;

    mma_mainloop_big(g_A2y + (size_t)m0 * K2, g_B2q + (size_t)n0 * K2,
                     smem_u32(smg), acc, tid, lane, wm, wn);

    const int gid = lane >> 2, tin = lane & 3;
    const int which = n0 >> 10;                   // 0=q 1=k 2=v
    unsigned short* Ha = (which == 0) ? g_Qh : (which == 1) ? g_Kh : g_Vh;
    unsigned short* La = (which == 0) ? g_Ql : (which == 1) ? g_Kl : g_Vl;
    const float qscale = (which == 0) ? 0.125f : 1.0f;
    #pragma unroll
    for (int mi = 0; mi < 4; mi++) {
        #pragma unroll
        for (int half = 0; half < 2; half++) {
            const int m = m0 + wm * 64 + mi * 16 + gid + half * 8;
            const int b = m >> 11, s = m & (SEQ - 1);
            #pragma unroll
            for (int ni = 0; ni < 8; ni++) {
                const int n = n0 + wn * 64 + ni * 8 + tin * 2;
                const int e = n & (EDIM - 1);
                const int h = e >> 6, d = e & (DHEAD - 1);
                float vx = (acc[mi][ni][half * 2 + 0] + bias[n]) * qscale;
                float vy = (acc[mi][ni][half * 2 + 1] + bias[n + 1]) * qscale;
                unsigned short h0 = bf_hi(vx), h1 = bf_hi(vy);
                unsigned short l0 = bf_lo(vx, h0), l1 = bf_lo(vy, h1);
                const size_t off = (size_t)((b * HEADS + h) * SEQ + s) * DHEAD + d;
                *(uint32_t*)(Ha + off) = (uint32_t)h0 | ((uint32_t)h1 << 16);
                *(uint32_t*)(La + off) = (uint32_t)l0 | ((uint32_t)l1 << 16);
            }
        }
    }
}

// ---------------- kernel 4: out-proj GEMM (256x128) + residual ---------------
__global__ __launch_bounds__(256, 1) void gemm_out_mma(const float* __restrict__ yres)
{
    extern __shared__ __align__(16) unsigned short smg[];
    const int tid = threadIdx.x, lane = tid & 31, wid = tid >> 5;
    const int wm = wid >> 1, wn = wid & 1;
    const int m0 = blockIdx.y * 256, n0 = blockIdx.x * 128;

    float acc[4][8][4];
    #pragma unroll
    for (int i = 0; i < 4; i++)
        #pragma unroll
        for (int j = 0; j < 8; j++)
            #pragma unroll
            for (int c = 0; c < 4; c++) acc[i][j][c] = 0.f;

    mma_mainloop_big(g_A2o + (size_t)m0 * K2, g_B2o + (size_t)n0 * K2,
                     smem_u32(smg), acc, tid, lane, wm, wn);

    const int gid = lane >> 2, tin = lane & 3;
    #pragma unroll
    for (int mi = 0; mi < 4; mi++) {
        #pragma unroll
        for (int half = 0; half < 2; half++) {
            const int m = m0 + wm * 64 + mi * 16 + gid + half * 8;
            #pragma unroll
            for (int ni = 0; ni < 8; ni++) {
                const int n = n0 + wn * 64 + ni * 8 + tin * 2;
                float2 r = *(const float2*)(yres + (size_t)m * EDIM + n);
                float2 v;
                v.x = acc[mi][ni][half * 2 + 0] + r.x;
                v.y = acc[mi][ni][half * 2 + 1] + r.y;
                *(float2*)(g_Mb + (size_t)m * EDIM + n) = v;
            }
        }
    }
}

// ---------------- kernel 3: flash attention (mma.sync, cp.async x2) ----------
// smem (ushort units): Qh=0, Ql=8192, KV stage s at 16384+s*32768:
//   Kh=+0, Kl=+8192, Vh=+16384, Vl=+24576.  Total 160 KB.
#define ATTN_SMEM (160 * 1024)
#define NT (SEQ / 128)

static __device__ __forceinline__ void attn_issue_kv(
    size_t hbase, int t, uint32_t stg, int tid)
{
    const int row = tid >> 3, g = tid & 7;
    const uint32_t aKh = stg, aKl = stg + 16384u, aVh = stg + 32768u, aVl = stg + 49152u;
    #pragma unroll
    for (int i = 0; i < 4; i++) {
        const int r = row + i * 32;
        const size_t src = hbase + (size_t)(t * 128 + r) * DHEAD + g * 8;
        CP_ASYNC16(SW_ADDR(aKh, r, g), g_Kh + src);
        CP_ASYNC16(SW_ADDR(aKl, r, g), g_Kl + src);
        CP_ASYNC16(SW_ADDR(aVh, r, g), g_Vh + src);
        CP_ASYNC16(SW_ADDR(aVl, r, g), g_Vl + src);
    }
    CP_COMMIT();
}

__global__ __launch_bounds__(256, 1) void attn_mma()
{
    extern __shared__ __align__(16) unsigned short smatt[];
    unsigned short* sQh = smatt;
    unsigned short* sQl = smatt + 8192;

    const int tid = threadIdx.x, lane = tid & 31, w = tid >> 5;
    const int gid = lane >> 2, tin = lane & 3;
    const int bh = blockIdx.y, q0 = blockIdx.x * 128;
    const size_t hbase = (size_t)bh * SEQ * DHEAD;
    const uint32_t smbase = smem_u32(smatt);
    const uint32_t stg[2] = {smbase + 32768u, smbase + 98304u};   // byte addrs

    // prologue: start KV tiles 0,1 while we stage Q
    attn_issue_kv(hbase, 0, stg[0], tid);
    attn_issue_kv(hbase, 1, stg[1], tid);

    {
        const int row = tid >> 3, g = tid & 7;
        #pragma unroll
        for (int i = 0; i < 4; i++) {
            const int r = row + i * 32;
            const size_t src = hbase + (size_t)(q0 + r) * DHEAD + g * 8;
            uint4 vh = *(const uint4*)(g_Qh + src);
            uint4 vl = *(const uint4*)(g_Ql + src);
            asm volatile("st.shared.v4.b32 [%0], {%1,%2,%3,%4};"
                :: "r"(SW_ADDR(smem_u32(sQh), r, g)), "r"(vh.x), "r"(vh.y), "r"(vh.z), "r"(vh.w));
            asm volatile("st.shared.v4.b32 [%0], {%1,%2,%3,%4};"
                :: "r"(SW_ADDR(smem_u32(sQl), r, g)), "r"(vl.x), "r"(vl.y), "r"(vl.z), "r"(vl.w));
        }
    }
    __syncthreads();

    uint32_t qh[4][4], ql[4][4];
    #pragma unroll
    for (int ks = 0; ks < 4; ks++) {
        const int row = w * 16 + (lane & 15);
        const int g = ks * 2 + (lane >> 4);
        ldmx4(qh[ks][0], qh[ks][1], qh[ks][2], qh[ks][3], SW_ADDR(smem_u32(sQh), row, g));
        ldmx4(ql[ks][0], ql[ks][1], ql[ks][2], ql[ks][3], SW_ADDR(smem_u32(sQl), row, g));
    }

    float ma = -1e30f, mb = -1e30f, la = 0.f, lb = 0.f;
    float o[8][4];
    #pragma unroll
    for (int i = 0; i < 8; i++)
        #pragma unroll
        for (int c = 0; c < 4; c++) o[i][c] = 0.f;

    const int q4 = lane >> 3;
    for (int t = 0; t < NT; t++) {
        const uint32_t sg = stg[t & 1];
        const uint32_t aKh = sg, aKl = sg + 16384u, aVh = sg + 32768u, aVl = sg + 49152u;
        if (t >= NT - 2) { CP_WAIT0(); } else { CP_WAIT1(); }
        __syncthreads();

        float s[16][4];
        #pragma unroll
        for (int i = 0; i < 16; i++)
            #pragma unroll
            for (int c = 0; c < 4; c++) s[i][c] = 0.f;

        #pragma unroll
        for (int ks = 0; ks < 4; ks++) {
            #pragma unroll
            for (int nio = 0; nio < 8; nio++) {
                const int krow = (2 * nio + (q4 >> 1)) * 8 + (lane & 7);
                const int kg = ks * 2 + (q4 & 1);
                uint32_t b0, b1, b2, b3;
                ldmx4(b0, b1, b2, b3, SW_ADDR(aKh, krow, kg));
                mma16816(s[2*nio][0], s[2*nio][1], s[2*nio][2], s[2*nio][3],
                         qh[ks][0], qh[ks][1], qh[ks][2], qh[ks][3], b0, b1);
                mma16816(s[2*nio+1][0], s[2*nio+1][1], s[2*nio+1][2], s[2*nio+1][3],
                         qh[ks][0], qh[ks][1], qh[ks][2], qh[ks][3], b2, b3);
                mma16816(s[2*nio][0], s[2*nio][1], s[2*nio][2], s[2*nio][3],
                         ql[ks][0], ql[ks][1], ql[ks][2], ql[ks][3], b0, b1);
                mma16816(s[2*nio+1][0], s[2*nio+1][1], s[2*nio+1][2], s[2*nio+1][3],
                         ql[ks][0], ql[ks][1], ql[ks][2], ql[ks][3], b2, b3);
                uint32_t c0, c1, c2, c3;
                ldmx4(c0, c1, c2, c3, SW_ADDR(aKl, krow, kg));
                mma16816(s[2*nio][0], s[2*nio][1], s[2*nio][2], s[2*nio][3],
                         qh[ks][0], qh[ks][1], qh[ks][2], qh[ks][3], c0, c1);
                mma16816(s[2*nio+1][0], s[2*nio+1][1], s[2*nio+1][2], s[2*nio+1][3],
                         qh[ks][0], qh[ks][1], qh[ks][2], qh[ks][3], c2, c3);
            }
        }

        float mxa = -1e30f, mxb = -1e30f;
        #pragma unroll
        for (int i = 0; i < 16; i++) {
            mxa = fmaxf(mxa, fmaxf(s[i][0], s[i][1]));
            mxb = fmaxf(mxb, fmaxf(s[i][2], s[i][3]));
        }
        mxa = fmaxf(mxa, __shfl_xor_sync(0xffffffffu, mxa, 1));
        mxa = fmaxf(mxa, __shfl_xor_sync(0xffffffffu, mxa, 2));
        mxb = fmaxf(mxb, __shfl_xor_sync(0xffffffffu, mxb, 1));
        mxb = fmaxf(mxb, __shfl_xor_sync(0xffffffffu, mxb, 2));
        const float nma = fmaxf(ma, mxa), nmb = fmaxf(mb, mxb);
        const float alfa = __expf(ma - nma), alfb = __expf(mb - nmb);
        ma = nma; mb = nmb;
        float sa = 0.f, sb = 0.f;
        #pragma unroll
        for (int i = 0; i < 16; i++) {
            s[i][0] = __expf(s[i][0] - nma); sa += s[i][0];
            s[i][1] = __expf(s[i][1] - nma); sa += s[i][1];
            s[i][2] = __expf(s[i][2] - nmb); sb += s[i][2];
            s[i][3] = __expf(s[i][3] - nmb); sb += s[i][3];
        }
        sa += __shfl_xor_sync(0xffffffffu, sa, 1);
        sa += __shfl_xor_sync(0xffffffffu, sa, 2);
        sb += __shfl_xor_sync(0xffffffffu, sb, 1);
        sb += __shfl_xor_sync(0xffffffffu, sb, 2);
        la = la * alfa + sa;
        lb = lb * alfb + sb;
        #pragma unroll
        for (int i = 0; i < 8; i++) {
            o[i][0] *= alfa; o[i][1] *= alfa;
            o[i][2] *= alfb; o[i][3] *= alfb;
        }

        #pragma unroll
        for (int kj = 0; kj < 8; kj++) {
            uint32_t ph[4], pl[4];
            #pragma unroll
            for (int u = 0; u < 4; u++) {
                const int ni = 2 * kj + (u >> 1);
                const float p0 = s[ni][(u & 1) * 2 + 0];
                const float p1 = s[ni][(u & 1) * 2 + 1];
                const uint32_t hp = cvt_bf2(p0, p1);
                ph[u] = hp;
                const float f0 = __uint_as_float(hp << 16);
                const float f1 = __uint_as_float(hp & 0xffff0000u);
                pl[u] = cvt_bf2(p0 - f0, p1 - f1);
            }
            #pragma unroll
            for (int ndo = 0; ndo < 4; ndo++) {
                const int vrow = kj * 16 + (q4 & 1) * 8 + (lane & 7);
                const int vg = 2 * ndo + (q4 >> 1);
                uint32_t v0, v1, v2, v3;
                ldmx4t(v0, v1, v2, v3, SW_ADDR(aVh, vrow, vg));
                mma16816(o[2*ndo][0], o[2*ndo][1], o[2*ndo][2], o[2*ndo][3],
                         ph[0], ph[1], ph[2], ph[3], v0, v1);
                mma16816(o[2*ndo+1][0], o[2*ndo+1][1], o[2*ndo+1][2], o[2*ndo+1][3],
                         ph[0], ph[1], ph[2], ph[3], v2, v3);
                mma16816(o[2*ndo][0], o[2*ndo][1], o[2*ndo][2], o[2*ndo][3],
                         pl[0], pl[1], pl[2], pl[3], v0, v1);
                mma16816(o[2*ndo+1][0], o[2*ndo+1][1], o[2*ndo+1][2], o[2*ndo+1][3],
                         pl[0], pl[1], pl[2], pl[3], v2, v3);
                uint32_t u0, u1, u2, u3;
                ldmx4t(u0, u1, u2, u3, SW_ADDR(aVl, vrow, vg));
                mma16816(o[2*ndo][0], o[2*ndo][1], o[2*ndo][2], o[2*ndo][3],
                         ph[0], ph[1], ph[2], ph[3], u0, u1);
                mma16816(o[2*ndo+1][0], o[2*ndo+1][1], o[2*ndo+1][2], o[2*ndo+1][3],
                         ph[0], ph[1], ph[2], ph[3], u2, u3);
            }
        }

        __syncthreads();
        if (t + 2 < NT)
            attn_issue_kv(hbase, t + 2, stg[t & 1], tid);
    }

    const float inva = 1.0f / la, invb = 1.0f / lb;
    const int b = bh >> 4, h = bh & (HEADS - 1);
    const int ra = q0 + w * 16 + gid, rb = ra + 8;
    unsigned short* rowA = g_A2o + (size_t)(b * SEQ + ra) * K2 + h * DHEAD;
    unsigned short* rowB = g_A2o + (size_t)(b * SEQ + rb) * K2 + h * DHEAD;
    #pragma unroll
    for (int nd = 0; nd < 8; nd++) {
        const int d = nd * 8 + tin * 2;
        const float x0 = o[nd][0] * inva, x1 = o[nd][1] * inva;
        const float x2 = o[nd][2] * invb, x3 = o[nd][3] * invb;
        unsigned short h0 = bf_hi(x0), h1 = bf_hi(x1);
        unsigned short l0 = bf_lo(x0, h0), l1 = bf_lo(x1, h1);
        unsigned short h2 = bf_hi(x2), h3 = bf_hi(x3);
        unsigned short l2 = bf_lo(x2, h2), l3 = bf_lo(x3, h3);
        const uint32_t hpA = (uint32_t)h0 | ((uint32_t)h1 << 16);
        const uint32_t lpA = (uint32_t)l0 | ((uint32_t)l1 << 16);
        const uint32_t hpB = (uint32_t)h2 | ((uint32_t)h3 << 16);
        const uint32_t lpB = (uint32_t)l2 | ((uint32_t)l3 << 16);
        *(uint32_t*)(rowA + d) = hpA;
        *(uint32_t*)(rowA + EDIM + d) = hpA;
        *(uint32_t*)(rowA + 2 * EDIM + d) = lpA;
        *(uint32_t*)(rowB + d) = hpB;
        *(uint32_t*)(rowB + EDIM + d) = hpB;
        *(uint32_t*)(rowB + 2 * EDIM + d) = lpB;
    }
}

// ---------------- kernel 5: LayerNorm ---------------------------------------
__global__ __launch_bounds__(256) void ln_kernel(
    const float* __restrict__ gamma, const float* __restrict__ beta,
    float* __restrict__ out)
{
    const int row = blockIdx.x;
    const int tid = threadIdx.x;
    const float4 v = *(const float4*)&g_Mb[(size_t)row * EDIM + tid * 4];
    float s = v.x + v.y + v.z + v.w;
    float q = v.x * v.x + v.y * v.y + v.z * v.z + v.w * v.w;
    #pragma unroll
    for (int off = 16; off >= 1; off >>= 1) {
        s += __shfl_xor_sync(0xffffffffu, s, off);
        q += __shfl_xor_sync(0xffffffffu, q, off);
    }
    __shared__ float ss[8], sq[8];
    const int w = tid >> 5, lane = tid & 31;
    if (lane == 0) { ss[w] = s; sq[w] = q; }
    __syncthreads();
    float tot = 0.f, totq = 0.f;
    #pragma unroll
    for (int i = 0; i < 8; i++) { tot += ss[i]; totq += sq[i]; }
    const float mu = tot * (1.0f / EDIM);
    const float var = totq * (1.0f / EDIM) - mu * mu;
    const float rs = rsqrtf(var + 1e-6f);
    const float4 g = *(const float4*)&gamma[tid * 4];
    const float4 bb = *(const float4*)&beta[tid * 4];
    float4 o;
    o.x = (v.x - mu) * rs * g.x + bb.x;
    o.y = (v.y - mu) * rs * g.y + bb.y;
    o.z = (v.z - mu) * rs * g.z + bb.z;
    o.w = (v.w - mu) * rs * g.w + bb.w;
    *(float4*)&out[(size_t)row * EDIM + tid * 4] = o;
}

// ---------------- launcher --------------------------------------------------
#define GEMM_SMEM (2 * (256 + 128) * 64 * 2)   // 96 KB

extern "C" void kernel_launch(void* const* d_in, const int* in_sizes, int n_in,
                              void* d_out, int out_size)
{
    (void)in_sizes; (void)n_in; (void)out_size;
    const float* y    = (const float*)d_in[0];
    const float* Wqkv = (const float*)d_in[1];
    const float* bqkv = (const float*)d_in[2];
    const float* Wmsa = (const float*)d_in[3];
    const float* Bq   = (const float*)d_in[4];
    const float* Aq   = (const float*)d_in[5];
    const float* Bk   = (const float*)d_in[6];
    const float* Ak   = (const float*)d_in[7];
    const float* Bv   = (const float*)d_in[8];
    const float* Av   = (const float*)d_in[9];
    const float* Bo   = (const float*)d_in[10];
    const float* Ao   = (const float*)d_in[11];
    const float* gamma= (const float*)d_in[12];
    const float* beta = (const float*)d_in[13];
    float* out = (float*)d_out;

    prep_weights<<<(4 * EDIM * EDIM) / 256, 256>>>(Wqkv, Wmsa, Bq, Aq, Bk, Ak, Bv, Av, Bo, Ao);
    convert_y<<<(MTOT * EDIM / 4) / 256, 256>>>(y);
    (void)cudaFuncSetAttribute(gemm_qkv_mma, cudaFuncAttributeMaxDynamicSharedMemorySize, GEMM_SMEM);
    (void)cudaFuncSetAttribute(gemm_out_mma, cudaFuncAttributeMaxDynamicSharedMemorySize, GEMM_SMEM);
    (void)cudaFuncSetAttribute(attn_mma, cudaFuncAttributeMaxDynamicSharedMemorySize, ATTN_SMEM);
    gemm_qkv_mma<<<dim3(3 * EDIM / 128, MTOT / 256), 256, GEMM_SMEM>>>(bqkv);
    attn_mma<<<dim3(SEQ / 128, BATCH * HEADS), 256, ATTN_SMEM>>>();
    gemm_out_mma<<<dim3(EDIM / 128, MTOT / 256), 256, GEMM_SMEM>>>(y);
    ln_kernel<<<MTOT, 256>>>(gamma, beta, out);
}

// round 9
// speedup vs baseline: 3.2699x; 1.0376x over previous
#include <cuda_runtime.h>
#include <cuda_bf16.h>
#include <cstdint>

#define EDIM   1024
#define HEADS  16
#define DHEAD  64
#define BATCH  2
#define SEQ    2048
#define RANK   8
#define MTOT   (BATCH*SEQ)
#define K2     3072          // extended K: A=[hi|hi|lo], B=[hi|lo|hi]
#define NCHUNK 48            // K2 / 64

// ---------------- scratch (device globals; no allocations allowed) ----------
__device__ unsigned short g_A2y[(size_t)MTOT*K2];      // y split-bf16 extended
__device__ unsigned short g_B2q[(size_t)3*EDIM*K2];    // folded qkv weights split-bf16
__device__ unsigned short g_A2o[(size_t)MTOT*K2];      // attention out split-bf16
__device__ unsigned short g_B2o[(size_t)EDIM*K2];      // folded out-proj weights split-bf16
__device__ unsigned short g_Qh[(size_t)BATCH*HEADS*SEQ*DHEAD];  // Q*(log2e/8) hi [bh][s][d]
__device__ unsigned short g_Ql[(size_t)BATCH*HEADS*SEQ*DHEAD];  // Q*(log2e/8) lo
__device__ unsigned short g_Kh[(size_t)BATCH*HEADS*SEQ*DHEAD];
__device__ unsigned short g_Kl[(size_t)BATCH*HEADS*SEQ*DHEAD];
__device__ unsigned short g_Vh[(size_t)BATCH*HEADS*SEQ*DHEAD];
__device__ unsigned short g_Vl[(size_t)BATCH*HEADS*SEQ*DHEAD];
__device__ float g_Mb[(size_t)MTOT*EDIM];              // msa + residual

// ---------------- bf16 split helpers ----------------------------------------
static __device__ __forceinline__ unsigned short bf_hi(float x) {
    return __bfloat16_as_ushort(__float2bfloat16(x));
}
static __device__ __forceinline__ unsigned short bf_lo(float x, unsigned short h) {
    float hf = __bfloat162float(__ushort_as_bfloat16(h));
    return __bfloat16_as_ushort(__float2bfloat16(x - hf));
}
static __device__ __forceinline__ uint32_t cvt_bf2(float lo, float hi) {
    uint32_t r;
    asm("cvt.rn.bf16x2.f32 %0, %1, %2;" : "=r"(r) : "f"(hi), "f"(lo));
    return r;
}

// ---------------- mma.sync helpers -------------------------------------------
static __device__ __forceinline__ uint32_t smem_u32(const void* p) {
    uint32_t a;
    asm("{ .reg .u64 t; cvta.to.shared.u64 t, %1; cvt.u32.u64 %0, t; }" : "=r"(a) : "l"(p));
    return a;
}
static __device__ __forceinline__ void ldmx4(
    uint32_t& r0, uint32_t& r1, uint32_t& r2, uint32_t& r3, uint32_t a) {
    asm volatile("ldmatrix.sync.aligned.m8n8.x4.shared.b16 {%0,%1,%2,%3}, [%4];"
                 : "=r"(r0), "=r"(r1), "=r"(r2), "=r"(r3) : "r"(a));
}
static __device__ __forceinline__ void ldmx4t(
    uint32_t& r0, uint32_t& r1, uint32_t& r2, uint32_t& r3, uint32_t a) {
    asm volatile("ldmatrix.sync.aligned.m8n8.x4.trans.shared.b16 {%0,%1,%2,%3}, [%4];"
                 : "=r"(r0), "=r"(r1), "=r"(r2), "=r"(r3) : "r"(a));
}
static __device__ __forceinline__ void mma16816(
    float& d0, float& d1, float& d2, float& d3,
    uint32_t a0, uint32_t a1, uint32_t a2, uint32_t a3,
    uint32_t b0, uint32_t b1) {
    asm volatile("mma.sync.aligned.m16n8k16.row.col.f32.bf16.bf16.f32 "
                 "{%0,%1,%2,%3}, {%4,%5,%6,%7}, {%8,%9}, {%0,%1,%2,%3};"
                 : "+f"(d0), "+f"(d1), "+f"(d2), "+f"(d3)
                 : "r"(a0), "r"(a1), "r"(a2), "r"(a3), "r"(b0), "r"(b1));
}
#define CP_ASYNC16(dst, src) \
    asm volatile("cp.async.cg.shared.global [%0], [%1], 16;" :: "r"(dst), "l"(src))
#define CP_COMMIT() asm volatile("cp.async.commit_group;" ::: "memory")
#define CP_WAIT1()  asm volatile("cp.async.wait_group 1;" ::: "memory")
#define CP_WAIT0()  asm volatile("cp.async.wait_group 0;" ::: "memory")

// smem tiles [rows][64 cols bf16] = [rows][8] 16B groups, swizzle g^=(row&7)
#define SW_ADDR(base, row, g) ((base) + (row) * 128u + (uint32_t)(((g) ^ ((row) & 7)) << 4))

// ---------------- kernel 1: fold LoRA + split weights to bf16 ---------------
__global__ __launch_bounds__(256) void prep_weights(
    const float* __restrict__ Wqkv, const float* __restrict__ Wmsa,
    const float* __restrict__ Bq, const float* __restrict__ Aq,
    const float* __restrict__ Bk, const float* __restrict__ Ak,
    const float* __restrict__ Bv, const float* __restrict__ Av,
    const float* __restrict__ Bo, const float* __restrict__ Ao)
{
    const int idx = blockIdx.x * blockDim.x + threadIdx.x;
    const int NQKV = 3 * EDIM * EDIM;
    if (idx < NQKV) {
        const int o = idx >> 10;
        const int i = idx & (EDIM - 1);
        const int which = o >> 10;
        const int e = o & (EDIM - 1);
        const float* Bw = (which == 0) ? Bq : (which == 1) ? Bk : Bv;
        const float* Aw = (which == 0) ? Aq : (which == 1) ? Ak : Av;
        float acc = Wqkv[idx];
        #pragma unroll
        for (int r = 0; r < RANK; r++) acc += Bw[i * RANK + r] * Aw[r * EDIM + e];
        unsigned short h = bf_hi(acc), l = bf_lo(acc, h);
        unsigned short* row = g_B2q + (size_t)o * K2;
        row[i] = h; row[EDIM + i] = l; row[2 * EDIM + i] = h;   // B2 = [hi|lo|hi]
    } else {
        const int j = idx - NQKV;
        const int o = j >> 10;
        const int i = j & (EDIM - 1);
        float acc = Wmsa[j];
        #pragma unroll
        for (int r = 0; r < RANK; r++) acc += Bo[i * RANK + r] * Ao[r * EDIM + o];
        unsigned short h = bf_hi(acc), l = bf_lo(acc, h);
        unsigned short* row = g_B2o + (size_t)o * K2;
        row[i] = h; row[EDIM + i] = l; row[2 * EDIM + i] = h;
    }
}

// ---------------- kernel 1b: split y to bf16 extended -----------------------
__global__ __launch_bounds__(256) void convert_y(const float* __restrict__ y)
{
    const int idx = blockIdx.x * blockDim.x + threadIdx.x;
    const int m = idx >> 8;
    const int c = (idx & 255) * 4;
    float4 v = *(const float4*)(y + (size_t)m * EDIM + c);
    unsigned short h0 = bf_hi(v.x), h1 = bf_hi(v.y), h2 = bf_hi(v.z), h3 = bf_hi(v.w);
    unsigned short l0 = bf_lo(v.x, h0), l1 = bf_lo(v.y, h1), l2 = bf_lo(v.z, h2), l3 = bf_lo(v.w, h3);
    uint2 hp = make_uint2((uint32_t)h0 | ((uint32_t)h1 << 16), (uint32_t)h2 | ((uint32_t)h3 << 16));
    uint2 lp = make_uint2((uint32_t)l0 | ((uint32_t)l1 << 16), (uint32_t)l2 | ((uint32_t)l3 << 16));
    unsigned short* row = g_A2y + (size_t)m * K2 + c;          // A2 = [hi|hi|lo]
    *(uint2*)(row) = hp;
    *(uint2*)(row + EDIM) = hp;
    *(uint2*)(row + 2 * EDIM) = lp;
}

// ---------------- big-tile GEMM mainloop: 256x128 tile, cp.async x3 ----------
// stage s (bytes): A at smbase + s*49152, B at smbase + s*49152 + 32768
static __device__ __forceinline__ void issue_loads(
    const unsigned short* __restrict__ Ag, const unsigned short* __restrict__ Bg,
    uint32_t sa, uint32_t sb, int kc, int tid)
{
    const int r0 = tid >> 3, g = tid & 7;
    const int koff = kc * 64 + g * 8;
    #pragma unroll
    for (int p = 0; p < 8; p++) {
        const int row = p * 32 + r0;
        CP_ASYNC16(SW_ADDR(sa, row, g), Ag + (size_t)row * K2 + koff);
    }
    #pragma unroll
    for (int p = 0; p < 4; p++) {
        const int row = p * 32 + r0;
        CP_ASYNC16(SW_ADDR(sb, row, g), Bg + (size_t)row * K2 + koff);
    }
    CP_COMMIT();
}

static __device__ __forceinline__ void mma_mainloop_big(
    const unsigned short* __restrict__ Ag, const unsigned short* __restrict__ Bg,
    uint32_t smbase, float acc[4][8][4], int tid, int lane, int wm, int wn)
{
    issue_loads(Ag, Bg, smbase, smbase + 32768u, 0, tid);
    issue_loads(Ag, Bg, smbase + 49152u, smbase + 81920u, 1, tid);

    const int q = lane >> 3;                 // 0..3 quad-of-8
    for (int kc = 0; kc < NCHUNK; kc++) {
        const int st = kc % 3;
        const uint32_t sa = smbase + (uint32_t)st * 49152u;
        const uint32_t sb = sa + 32768u;
        if (kc == NCHUNK - 1) { CP_WAIT0(); } else { CP_WAIT1(); }
        __syncthreads();
        if (kc + 2 < NCHUNK) {
            const int ns = (kc + 2) % 3;
            issue_loads(Ag, Bg, smbase + (uint32_t)ns * 49152u,
                        smbase + (uint32_t)ns * 49152u + 32768u, kc + 2, tid);
        }

        #pragma unroll
        for (int ks = 0; ks < 4; ks++) {
            uint32_t bf[4][4];
            #pragma unroll
            for (int p = 0; p < 4; p++) {
                const int brow = wn * 64 + p * 16 + (q >> 1) * 8 + (lane & 7);
                const int bg = ks * 2 + (q & 1);
                ldmx4(bf[p][0], bf[p][1], bf[p][2], bf[p][3], SW_ADDR(sb, brow, bg));
            }
            #pragma unroll
            for (int mi = 0; mi < 4; mi++) {
                const int arow = wm * 64 + mi * 16 + (lane & 15);
                const int ag = ks * 2 + (lane >> 4);
                uint32_t a0, a1, a2, a3;
                ldmx4(a0, a1, a2, a3, SW_ADDR(sa, arow, ag));
                #pragma unroll
                for (int p = 0; p < 4; p++) {
                    mma16816(acc[mi][2*p][0], acc[mi][2*p][1], acc[mi][2*p][2], acc[mi][2*p][3],
                             a0, a1, a2, a3, bf[p][0], bf[p][1]);
                    mma16816(acc[mi][2*p+1][0], acc[mi][2*p+1][1], acc[mi][2*p+1][2], acc[mi][2*p+1][3],
                             a0, a1, a2, a3, bf[p][2], bf[p][3]);
                }
            }
        }
    }
}

// ---------------- kernel 2: QKV GEMM (256x128, cp.async x3) ------------------
#define QSCALE_LOG2E 0.18033688011112042f   // (1/8) * log2(e)
__global__ __launch_bounds__(256, 1) void gemm_qkv_mma(const float* __restrict__ bias)
{
    extern __shared__ __align__(16) unsigned short smg[];
    const int tid = threadIdx.x, lane = tid & 31, wid = tid >> 5;
    const int wm = wid >> 1, wn = wid & 1;
    const int m0 = blockIdx.y * 256, n0 = blockIdx.x * 128;

    float acc[4][8][4];
    #pragma unroll
    for (int i = 0; i < 4; i++)
        #pragma unroll
        for (int j = 0; j < 8; j++)
            #pragma unroll
            for (int c = 0; c < 4; c++) acc[i][j][c] = 0.f;

    mma_mainloop_big(g_A2y + (size_t)m0 * K2, g_B2q + (size_t)n0 * K2,
                     smem_u32(smg), acc, tid, lane, wm, wn);

    const int gid = lane >> 2, tin = lane & 3;
    const int which = n0 >> 10;                   // 0=q 1=k 2=v
    unsigned short* Ha = (which == 0) ? g_Qh : (which == 1) ? g_Kh : g_Vh;
    unsigned short* La = (which == 0) ? g_Ql : (which == 1) ? g_Kl : g_Vl;
    const float qscale = (which == 0) ? QSCALE_LOG2E : 1.0f;
    #pragma unroll
    for (int mi = 0; mi < 4; mi++) {
        #pragma unroll
        for (int half = 0; half < 2; half++) {
            const int m = m0 + wm * 64 + mi * 16 + gid + half * 8;
            const int b = m >> 11, s = m & (SEQ - 1);
            #pragma unroll
            for (int ni = 0; ni < 8; ni++) {
                const int n = n0 + wn * 64 + ni * 8 + tin * 2;
                const int e = n & (EDIM - 1);
                const int h = e >> 6, d = e & (DHEAD - 1);
                float vx = (acc[mi][ni][half * 2 + 0] + bias[n]) * qscale;
                float vy = (acc[mi][ni][half * 2 + 1] + bias[n + 1]) * qscale;
                unsigned short h0 = bf_hi(vx), h1 = bf_hi(vy);
                unsigned short l0 = bf_lo(vx, h0), l1 = bf_lo(vy, h1);
                const size_t off = (size_t)((b * HEADS + h) * SEQ + s) * DHEAD + d;
                *(uint32_t*)(Ha + off) = (uint32_t)h0 | ((uint32_t)h1 << 16);
                *(uint32_t*)(La + off) = (uint32_t)l0 | ((uint32_t)l1 << 16);
            }
        }
    }
}

// ---------------- kernel 4: out-proj GEMM (256x128) + residual ---------------
__global__ __launch_bounds__(256, 1) void gemm_out_mma(const float* __restrict__ yres)
{
    extern __shared__ __align__(16) unsigned short smg[];
    const int tid = threadIdx.x, lane = tid & 31, wid = tid >> 5;
    const int wm = wid >> 1, wn = wid & 1;
    const int m0 = blockIdx.y * 256, n0 = blockIdx.x * 128;

    float acc[4][8][4];
    #pragma unroll
    for (int i = 0; i < 4; i++)
        #pragma unroll
        for (int j = 0; j < 8; j++)
            #pragma unroll
            for (int c = 0; c < 4; c++) acc[i][j][c] = 0.f;

    mma_mainloop_big(g_A2o + (size_t)m0 * K2, g_B2o + (size_t)n0 * K2,
                     smem_u32(smg), acc, tid, lane, wm, wn);

    const int gid = lane >> 2, tin = lane & 3;
    #pragma unroll
    for (int mi = 0; mi < 4; mi++) {
        #pragma unroll
        for (int half = 0; half < 2; half++) {
            const int m = m0 + wm * 64 + mi * 16 + gid + half * 8;
            #pragma unroll
            for (int ni = 0; ni < 8; ni++) {
                const int n = n0 + wn * 64 + ni * 8 + tin * 2;
                float2 r = *(const float2*)(yres + (size_t)m * EDIM + n);
                float2 v;
                v.x = acc[mi][ni][half * 2 + 0] + r.x;
                v.y = acc[mi][ni][half * 2 + 1] + r.y;
                *(float2*)(g_Mb + (size_t)m * EDIM + n) = v;
            }
        }
    }
}

// ---------------- kernel 3: flash attention (mma.sync, cp.async x3) ----------
// smem bytes: Q hi at +0 (16KB), Q lo at +16384; KV stage s at 32768 + s*65536:
//   Kh=+0, Kl=+16384, Vh=+32768, Vl=+49152.  Total 224 KB.
#define ATTN_SMEM (224 * 1024)
#define NT (SEQ / 128)

static __device__ __forceinline__ void attn_issue_kv(
    size_t hbase, int t, uint32_t stg, int tid)
{
    const int row = tid >> 3, g = tid & 7;
    const uint32_t aKh = stg, aKl = stg + 16384u, aVh = stg + 32768u, aVl = stg + 49152u;
    #pragma unroll
    for (int i = 0; i < 4; i++) {
        const int r = row + i * 32;
        const size_t src = hbase + (size_t)(t * 128 + r) * DHEAD + g * 8;
        CP_ASYNC16(SW_ADDR(aKh, r, g), g_Kh + src);
        CP_ASYNC16(SW_ADDR(aKl, r, g), g_Kl + src);
        CP_ASYNC16(SW_ADDR(aVh, r, g), g_Vh + src);
        CP_ASYNC16(SW_ADDR(aVl, r, g), g_Vl + src);
    }
    CP_COMMIT();
}

__global__ __launch_bounds__(256, 1) void attn_mma()
{
    extern __shared__ __align__(16) unsigned short smatt[];
    unsigned short* sQh = smatt;
    unsigned short* sQl = smatt + 8192;

    const int tid = threadIdx.x, lane = tid & 31, w = tid >> 5;
    const int gid = lane >> 2, tin = lane & 3;
    const int bh = blockIdx.y, q0 = blockIdx.x * 128;
    const size_t hbase = (size_t)bh * SEQ * DHEAD;
    const uint32_t smbase = smem_u32(smatt);

    // prologue: start KV tiles 0,1 while we stage Q
    attn_issue_kv(hbase, 0, smbase + 32768u, tid);
    attn_issue_kv(hbase, 1, smbase + 98304u, tid);

    {
        const int row = tid >> 3, g = tid & 7;
        #pragma unroll
        for (int i = 0; i < 4; i++) {
            const int r = row + i * 32;
            const size_t src = hbase + (size_t)(q0 + r) * DHEAD + g * 8;
            uint4 vh = *(const uint4*)(g_Qh + src);
            uint4 vl = *(const uint4*)(g_Ql + src);
            asm volatile("st.shared.v4.b32 [%0], {%1,%2,%3,%4};"
                :: "r"(SW_ADDR(smem_u32(sQh), r, g)), "r"(vh.x), "r"(vh.y), "r"(vh.z), "r"(vh.w));
            asm volatile("st.shared.v4.b32 [%0], {%1,%2,%3,%4};"
                :: "r"(SW_ADDR(smem_u32(sQl), r, g)), "r"(vl.x), "r"(vl.y), "r"(vl.z), "r"(vl.w));
        }
    }
    __syncthreads();

    uint32_t qh[4][4], ql[4][4];
    #pragma unroll
    for (int ks = 0; ks < 4; ks++) {
        const int row = w * 16 + (lane & 15);
        const int g = ks * 2 + (lane >> 4);
        ldmx4(qh[ks][0], qh[ks][1], qh[ks][2], qh[ks][3], SW_ADDR(smem_u32(sQh), row, g));
        ldmx4(ql[ks][0], ql[ks][1], ql[ks][2], ql[ks][3], SW_ADDR(smem_u32(sQl), row, g));
    }

    float ma = -1e30f, mb = -1e30f, la = 0.f, lb = 0.f;
    float o[8][4];
    #pragma unroll
    for (int i = 0; i < 8; i++)
        #pragma unroll
        for (int c = 0; c < 4; c++) o[i][c] = 0.f;

    const int q4 = lane >> 3;
    for (int t = 0; t < NT; t++) {
        const uint32_t sg = smbase + 32768u + (uint32_t)(t % 3) * 65536u;
        const uint32_t aKh = sg, aKl = sg + 16384u, aVh = sg + 32768u, aVl = sg + 49152u;
        if (t == NT - 1) { CP_WAIT0(); } else { CP_WAIT1(); }
        __syncthreads();
        if (t + 2 < NT)
            attn_issue_kv(hbase, t + 2, smbase + 32768u + (uint32_t)((t + 2) % 3) * 65536u, tid);

        float s[16][4];
        #pragma unroll
        for (int i = 0; i < 16; i++)
            #pragma unroll
            for (int c = 0; c < 4; c++) s[i][c] = 0.f;

        #pragma unroll
        for (int ks = 0; ks < 4; ks++) {
            #pragma unroll
            for (int nio = 0; nio < 8; nio++) {
                const int krow = (2 * nio + (q4 >> 1)) * 8 + (lane & 7);
                const int kg = ks * 2 + (q4 & 1);
                uint32_t b0, b1, b2, b3;
                ldmx4(b0, b1, b2, b3, SW_ADDR(aKh, krow, kg));
                mma16816(s[2*nio][0], s[2*nio][1], s[2*nio][2], s[2*nio][3],
                         qh[ks][0], qh[ks][1], qh[ks][2], qh[ks][3], b0, b1);
                mma16816(s[2*nio+1][0], s[2*nio+1][1], s[2*nio+1][2], s[2*nio+1][3],
                         qh[ks][0], qh[ks][1], qh[ks][2], qh[ks][3], b2, b3);
                mma16816(s[2*nio][0], s[2*nio][1], s[2*nio][2], s[2*nio][3],
                         ql[ks][0], ql[ks][1], ql[ks][2], ql[ks][3], b0, b1);
                mma16816(s[2*nio+1][0], s[2*nio+1][1], s[2*nio+1][2], s[2*nio+1][3],
                         ql[ks][0], ql[ks][1], ql[ks][2], ql[ks][3], b2, b3);
                uint32_t c0, c1, c2, c3;
                ldmx4(c0, c1, c2, c3, SW_ADDR(aKl, krow, kg));
                mma16816(s[2*nio][0], s[2*nio][1], s[2*nio][2], s[2*nio][3],
                         qh[ks][0], qh[ks][1], qh[ks][2], qh[ks][3], c0, c1);
                mma16816(s[2*nio+1][0], s[2*nio+1][1], s[2*nio+1][2], s[2*nio+1][3],
                         qh[ks][0], qh[ks][1], qh[ks][2], qh[ks][3], c2, c3);
            }
        }

        // scores are in log2 domain (log2e folded into Q scale) -> exp2f
        float mxa = -1e30f, mxb = -1e30f;
        #pragma unroll
        for (int i = 0; i < 16; i++) {
            mxa = fmaxf(mxa, fmaxf(s[i][0], s[i][1]));
            mxb = fmaxf(mxb, fmaxf(s[i][2], s[i][3]));
        }
        mxa = fmaxf(mxa, __shfl_xor_sync(0xffffffffu, mxa, 1));
        mxa = fmaxf(mxa, __shfl_xor_sync(0xffffffffu, mxa, 2));
        mxb = fmaxf(mxb, __shfl_xor_sync(0xffffffffu, mxb, 1));
        mxb = fmaxf(mxb, __shfl_xor_sync(0xffffffffu, mxb, 2));
        const float nma = fmaxf(ma, mxa), nmb = fmaxf(mb, mxb);
        const float alfa = exp2f(ma - nma), alfb = exp2f(mb - nmb);
        ma = nma; mb = nmb;
        float sa = 0.f, sb = 0.f;
        #pragma unroll
        for (int i = 0; i < 16; i++) {
            s[i][0] = exp2f(s[i][0] - nma); sa += s[i][0];
            s[i][1] = exp2f(s[i][1] - nma); sa += s[i][1];
            s[i][2] = exp2f(s[i][2] - nmb); sb += s[i][2];
            s[i][3] = exp2f(s[i][3] - nmb); sb += s[i][3];
        }
        sa += __shfl_xor_sync(0xffffffffu, sa, 1);
        sa += __shfl_xor_sync(0xffffffffu, sa, 2);
        sb += __shfl_xor_sync(0xffffffffu, sb, 1);
        sb += __shfl_xor_sync(0xffffffffu, sb, 2);
        la = la * alfa + sa;
        lb = lb * alfb + sb;
        #pragma unroll
        for (int i = 0; i < 8; i++) {
            o[i][0] *= alfa; o[i][1] *= alfa;
            o[i][2] *= alfb; o[i][3] *= alfb;
        }

        #pragma unroll
        for (int kj = 0; kj < 8; kj++) {
            uint32_t ph[4], pl[4];
            #pragma unroll
            for (int u = 0; u < 4; u++) {
                const int ni = 2 * kj + (u >> 1);
                const float p0 = s[ni][(u & 1) * 2 + 0];
                const float p1 = s[ni][(u & 1) * 2 + 1];
                const uint32_t hp = cvt_bf2(p0, p1);
                ph[u] = hp;
                const float f0 = __uint_as_float(hp << 16);
                const float f1 = __uint_as_float(hp & 0xffff0000u);
                pl[u] = cvt_bf2(p0 - f0, p1 - f1);
            }
            #pragma unroll
            for (int ndo = 0; ndo < 4; ndo++) {
                const int vrow = kj * 16 + (q4 & 1) * 8 + (lane & 7);
                const int vg = 2 * ndo + (q4 >> 1);
                uint32_t v0, v1, v2, v3;
                ldmx4t(v0, v1, v2, v3, SW_ADDR(aVh, vrow, vg));
                mma16816(o[2*ndo][0], o[2*ndo][1], o[2*ndo][2], o[2*ndo][3],
                         ph[0], ph[1], ph[2], ph[3], v0, v1);
                mma16816(o[2*ndo+1][0], o[2*ndo+1][1], o[2*ndo+1][2], o[2*ndo+1][3],
                         ph[0], ph[1], ph[2], ph[3], v2, v3);
                mma16816(o[2*ndo][0], o[2*ndo][1], o[2*ndo][2], o[2*ndo][3],
                         pl[0], pl[1], pl[2], pl[3], v0, v1);
                mma16816(o[2*ndo+1][0], o[2*ndo+1][1], o[2*ndo+1][2], o[2*ndo+1][3],
                         pl[0], pl[1], pl[2], pl[3], v2, v3);
                uint32_t u0, u1, u2, u3;
                ldmx4t(u0, u1, u2, u3, SW_ADDR(aVl, vrow, vg));
                mma16816(o[2*ndo][0], o[2*ndo][1], o[2*ndo][2], o[2*ndo][3],
                         ph[0], ph[1], ph[2], ph[3], u0, u1);
                mma16816(o[2*ndo+1][0], o[2*ndo+1][1], o[2*ndo+1][2], o[2*ndo+1][3],
                         ph[0], ph[1], ph[2], ph[3], u2, u3);
            }
        }
    }

    const float inva = 1.0f / la, invb = 1.0f / lb;
    const int b = bh >> 4, h = bh & (HEADS - 1);
    const int ra = q0 + w * 16 + gid, rb = ra + 8;
    unsigned short* rowA = g_A2o + (size_t)(b * SEQ + ra) * K2 + h * DHEAD;
    unsigned short* rowB = g_A2o + (size_t)(b * SEQ + rb) * K2 + h * DHEAD;
    #pragma unroll
    for (int nd = 0; nd < 8; nd++) {
        const int d = nd * 8 + tin * 2;
        const float x0 = o[nd][0] * inva, x1 = o[nd][1] * inva;
        const float x2 = o[nd][2] * invb, x3 = o[nd][3] * invb;
        unsigned short h0 = bf_hi(x0), h1 = bf_hi(x1);
        unsigned short l0 = bf_lo(x0, h0), l1 = bf_lo(x1, h1);
        unsigned short h2 = bf_hi(x2), h3 = bf_hi(x3);
        unsigned short l2 = bf_lo(x2, h2), l3 = bf_lo(x3, h3);
        const uint32_t hpA = (uint32_t)h0 | ((uint32_t)h1 << 16);
        const uint32_t lpA = (uint32_t)l0 | ((uint32_t)l1 << 16);
        const uint32_t hpB = (uint32_t)h2 | ((uint32_t)h3 << 16);
        const uint32_t lpB = (uint32_t)l2 | ((uint32_t)l3 << 16);
        *(uint32_t*)(rowA + d) = hpA;
        *(uint32_t*)(rowA + EDIM + d) = hpA;
        *(uint32_t*)(rowA + 2 * EDIM + d) = lpA;
        *(uint32_t*)(rowB + d) = hpB;
        *(uint32_t*)(rowB + EDIM + d) = hpB;
        *(uint32_t*)(rowB + 2 * EDIM + d) = lpB;
    }
}

// ---------------- kernel 5: LayerNorm ---------------------------------------
__global__ __launch_bounds__(256) void ln_kernel(
    const float* __restrict__ gamma, const float* __restrict__ beta,
    float* __restrict__ out)
{
    const int row = blockIdx.x;
    const int tid = threadIdx.x;
    const float4 v = *(const float4*)&g_Mb[(size_t)row * EDIM + tid * 4];
    float s = v.x + v.y + v.z + v.w;
    float q = v.x * v.x + v.y * v.y + v.z * v.z + v.w * v.w;
    #pragma unroll
    for (int off = 16; off >= 1; off >>= 1) {
        s += __shfl_xor_sync(0xffffffffu, s, off);
        q += __shfl_xor_sync(0xffffffffu, q, off);
    }
    __shared__ float ss[8], sq[8];
    const int w = tid >> 5, lane = tid & 31;
    if (lane == 0) { ss[w] = s; sq[w] = q; }
    __syncthreads();
    float tot = 0.f, totq = 0.f;
    #pragma unroll
    for (int i = 0; i < 8; i++) { tot += ss[i]; totq += sq[i]; }
    const float mu = tot * (1.0f / EDIM);
    const float var = totq * (1.0f / EDIM) - mu * mu;
    const float rs = rsqrtf(var + 1e-6f);
    const float4 g = *(const float4*)&gamma[tid * 4];
    const float4 bb = *(const float4*)&beta[tid * 4];
    float4 o;
    o.x = (v.x - mu) * rs * g.x + bb.x;
    o.y = (v.y - mu) * rs * g.y + bb.y;
    o.z = (v.z - mu) * rs * g.z + bb.z;
    o.w = (v.w - mu) * rs * g.w + bb.w;
    *(float4*)&out[(size_t)row * EDIM + tid * 4] = o;
}

// ---------------- launcher --------------------------------------------------
#define GEMM_SMEM (3 * (256 + 128) * 64 * 2)   // 144 KB

extern "C" void kernel_launch(void* const* d_in, const int* in_sizes, int n_in,
                              void* d_out, int out_size)
{
    (void)in_sizes; (void)n_in; (void)out_size;
    const float* y    = (const float*)d_in[0];
    const float* Wqkv = (const float*)d_in[1];
    const float* bqkv = (const float*)d_in[2];
    const float* Wmsa = (const float*)d_in[3];
    const float* Bq   = (const float*)d_in[4];
    const float* Aq   = (const float*)d_in[5];
    const float* Bk   = (const float*)d_in[6];
    const float* Ak   = (const float*)d_in[7];
    const float* Bv   = (const float*)d_in[8];
    const float* Av   = (const float*)d_in[9];
    const float* Bo   = (const float*)d_in[10];
    const float* Ao   = (const float*)d_in[11];
    const float* gamma= (const float*)d_in[12];
    const float* beta = (const float*)d_in[13];
    float* out = (float*)d_out;

    prep_weights<<<(4 * EDIM * EDIM) / 256, 256>>>(Wqkv, Wmsa, Bq, Aq, Bk, Ak, Bv, Av, Bo, Ao);
    convert_y<<<(MTOT * EDIM / 4) / 256, 256>>>(y);
    (void)cudaFuncSetAttribute(gemm_qkv_mma, cudaFuncAttributeMaxDynamicSharedMemorySize, GEMM_SMEM);
    (void)cudaFuncSetAttribute(gemm_out_mma, cudaFuncAttributeMaxDynamicSharedMemorySize, GEMM_SMEM);
    (void)cudaFuncSetAttribute(attn_mma, cudaFuncAttributeMaxDynamicSharedMemorySize, ATTN_SMEM);
    gemm_qkv_mma<<<dim3(3 * EDIM / 128, MTOT / 256), 256, GEMM_SMEM>>>(bqkv);
    attn_mma<<<dim3(SEQ / 128, BATCH * HEADS), 256, ATTN_SMEM>>>();
    gemm_out_mma<<<dim3(EDIM / 128, MTOT / 256), 256, GEMM_SMEM>>>(y);
    ln_kernel<<<MTOT, 256>>>(gamma, beta, out);
}

// round 10
// speedup vs baseline: 3.4025x; 1.0406x over previous
#include <cuda_runtime.h>
#include <cuda_bf16.h>
#include <cstdint>

#define EDIM   1024
#define HEADS  16
#define DHEAD  64
#define BATCH  2
#define SEQ    2048
#define RANK   8
#define MTOT   (BATCH*SEQ)
#define K2     3072          // extended K: A=[hi|hi|lo], B=[hi|lo|hi]
#define NCHUNK 48            // K2 / 64

// ---------------- scratch (device globals; no allocations allowed) ----------
__device__ unsigned short g_A2y[(size_t)MTOT*K2];      // y split-bf16 extended
__device__ unsigned short g_B2q[(size_t)3*EDIM*K2];    // folded qkv weights split-bf16
__device__ unsigned short g_A2o[(size_t)MTOT*K2];      // attention out split-bf16
__device__ unsigned short g_B2o[(size_t)EDIM*K2];      // folded out-proj weights split-bf16
__device__ unsigned short g_Qh[(size_t)BATCH*HEADS*SEQ*DHEAD];  // Q*(log2e/8) hi [bh][s][d]
__device__ unsigned short g_Ql[(size_t)BATCH*HEADS*SEQ*DHEAD];  // Q*(log2e/8) lo
__device__ unsigned short g_Kh[(size_t)BATCH*HEADS*SEQ*DHEAD];
__device__ unsigned short g_Kl[(size_t)BATCH*HEADS*SEQ*DHEAD];
__device__ unsigned short g_Vh[(size_t)BATCH*HEADS*SEQ*DHEAD];
__device__ unsigned short g_Vl[(size_t)BATCH*HEADS*SEQ*DHEAD];
__device__ float g_Mb[(size_t)MTOT*EDIM];              // msa + residual

// ---------------- bf16 split helpers ----------------------------------------
static __device__ __forceinline__ unsigned short bf_hi(float x) {
    return __bfloat16_as_ushort(__float2bfloat16(x));
}
static __device__ __forceinline__ unsigned short bf_lo(float x, unsigned short h) {
    float hf = __bfloat162float(__ushort_as_bfloat16(h));
    return __bfloat16_as_ushort(__float2bfloat16(x - hf));
}
static __device__ __forceinline__ uint32_t cvt_bf2(float lo, float hi) {
    uint32_t r;
    asm("cvt.rn.bf16x2.f32 %0, %1, %2;" : "=r"(r) : "f"(hi), "f"(lo));
    return r;
}

// ---------------- mma.sync helpers -------------------------------------------
static __device__ __forceinline__ uint32_t smem_u32(const void* p) {
    uint32_t a;
    asm("{ .reg .u64 t; cvta.to.shared.u64 t, %1; cvt.u32.u64 %0, t; }" : "=r"(a) : "l"(p));
    return a;
}
static __device__ __forceinline__ void ldmx4(
    uint32_t& r0, uint32_t& r1, uint32_t& r2, uint32_t& r3, uint32_t a) {
    asm volatile("ldmatrix.sync.aligned.m8n8.x4.shared.b16 {%0,%1,%2,%3}, [%4];"
                 : "=r"(r0), "=r"(r1), "=r"(r2), "=r"(r3) : "r"(a));
}
static __device__ __forceinline__ void ldmx4t(
    uint32_t& r0, uint32_t& r1, uint32_t& r2, uint32_t& r3, uint32_t a) {
    asm volatile("ldmatrix.sync.aligned.m8n8.x4.trans.shared.b16 {%0,%1,%2,%3}, [%4];"
                 : "=r"(r0), "=r"(r1), "=r"(r2), "=r"(r3) : "r"(a));
}
static __device__ __forceinline__ void mma16816(
    float& d0, float& d1, float& d2, float& d3,
    uint32_t a0, uint32_t a1, uint32_t a2, uint32_t a3,
    uint32_t b0, uint32_t b1) {
    asm volatile("mma.sync.aligned.m16n8k16.row.col.f32.bf16.bf16.f32 "
                 "{%0,%1,%2,%3}, {%4,%5,%6,%7}, {%8,%9}, {%0,%1,%2,%3};"
                 : "+f"(d0), "+f"(d1), "+f"(d2), "+f"(d3)
                 : "r"(a0), "r"(a1), "r"(a2), "r"(a3), "r"(b0), "r"(b1));
}
#define CP_ASYNC16(dst, src) \
    asm volatile("cp.async.cg.shared.global [%0], [%1], 16;" :: "r"(dst), "l"(src))
#define CP_COMMIT() asm volatile("cp.async.commit_group;" ::: "memory")
#define CP_WAIT1()  asm volatile("cp.async.wait_group 1;" ::: "memory")
#define CP_WAIT0()  asm volatile("cp.async.wait_group 0;" ::: "memory")

// smem tiles [rows][64 cols bf16] = [rows][8] 16B groups, swizzle g^=(row&7)
#define SW_ADDR(base, row, g) ((base) + (row) * 128u + (uint32_t)(((g) ^ ((row) & 7)) << 4))

// ---------------- kernel 1: fold LoRA + split weights to bf16 ---------------
__global__ __launch_bounds__(256) void prep_weights(
    const float* __restrict__ Wqkv, const float* __restrict__ Wmsa,
    const float* __restrict__ Bq, const float* __restrict__ Aq,
    const float* __restrict__ Bk, const float* __restrict__ Ak,
    const float* __restrict__ Bv, const float* __restrict__ Av,
    const float* __restrict__ Bo, const float* __restrict__ Ao)
{
    const int idx = blockIdx.x * blockDim.x + threadIdx.x;
    const int NQKV = 3 * EDIM * EDIM;
    if (idx < NQKV) {
        const int o = idx >> 10;
        const int i = idx & (EDIM - 1);
        const int which = o >> 10;
        const int e = o & (EDIM - 1);
        const float* Bw = (which == 0) ? Bq : (which == 1) ? Bk : Bv;
        const float* Aw = (which == 0) ? Aq : (which == 1) ? Ak : Av;
        float acc = Wqkv[idx];
        #pragma unroll
        for (int r = 0; r < RANK; r++) acc += Bw[i * RANK + r] * Aw[r * EDIM + e];
        unsigned short h = bf_hi(acc), l = bf_lo(acc, h);
        unsigned short* row = g_B2q + (size_t)o * K2;
        row[i] = h; row[EDIM + i] = l; row[2 * EDIM + i] = h;   // B2 = [hi|lo|hi]
    } else {
        const int j = idx - NQKV;
        const int o = j >> 10;
        const int i = j & (EDIM - 1);
        float acc = Wmsa[j];
        #pragma unroll
        for (int r = 0; r < RANK; r++) acc += Bo[i * RANK + r] * Ao[r * EDIM + o];
        unsigned short h = bf_hi(acc), l = bf_lo(acc, h);
        unsigned short* row = g_B2o + (size_t)o * K2;
        row[i] = h; row[EDIM + i] = l; row[2 * EDIM + i] = h;
    }
}

// ---------------- kernel 1b: split y to bf16 extended -----------------------
__global__ __launch_bounds__(256) void convert_y(const float* __restrict__ y)
{
    const int idx = blockIdx.x * blockDim.x + threadIdx.x;
    const int m = idx >> 8;
    const int c = (idx & 255) * 4;
    float4 v = *(const float4*)(y + (size_t)m * EDIM + c);
    unsigned short h0 = bf_hi(v.x), h1 = bf_hi(v.y), h2 = bf_hi(v.z), h3 = bf_hi(v.w);
    unsigned short l0 = bf_lo(v.x, h0), l1 = bf_lo(v.y, h1), l2 = bf_lo(v.z, h2), l3 = bf_lo(v.w, h3);
    uint2 hp = make_uint2((uint32_t)h0 | ((uint32_t)h1 << 16), (uint32_t)h2 | ((uint32_t)h3 << 16));
    uint2 lp = make_uint2((uint32_t)l0 | ((uint32_t)l1 << 16), (uint32_t)l2 | ((uint32_t)l3 << 16));
    unsigned short* row = g_A2y + (size_t)m * K2 + c;          // A2 = [hi|hi|lo]
    *(uint2*)(row) = hp;
    *(uint2*)(row + EDIM) = hp;
    *(uint2*)(row + 2 * EDIM) = lp;
}

// ---------------- big-tile GEMM mainloop: 256x128 tile, cp.async x3 ----------
static __device__ __forceinline__ void issue_loads(
    const unsigned short* __restrict__ Ag, const unsigned short* __restrict__ Bg,
    uint32_t sa, uint32_t sb, int kc, int tid)
{
    const int r0 = tid >> 3, g = tid & 7;
    const int koff = kc * 64 + g * 8;
    #pragma unroll
    for (int p = 0; p < 8; p++) {
        const int row = p * 32 + r0;
        CP_ASYNC16(SW_ADDR(sa, row, g), Ag + (size_t)row * K2 + koff);
    }
    #pragma unroll
    for (int p = 0; p < 4; p++) {
        const int row = p * 32 + r0;
        CP_ASYNC16(SW_ADDR(sb, row, g), Bg + (size_t)row * K2 + koff);
    }
    CP_COMMIT();
}

static __device__ __forceinline__ void mma_mainloop_big(
    const unsigned short* __restrict__ Ag, const unsigned short* __restrict__ Bg,
    uint32_t smbase, float acc[4][8][4], int tid, int lane, int wm, int wn)
{
    issue_loads(Ag, Bg, smbase, smbase + 32768u, 0, tid);
    issue_loads(Ag, Bg, smbase + 49152u, smbase + 81920u, 1, tid);

    const int q = lane >> 3;                 // 0..3 quad-of-8
    for (int kc = 0; kc < NCHUNK; kc++) {
        const int st = kc % 3;
        const uint32_t sa = smbase + (uint32_t)st * 49152u;
        const uint32_t sb = sa + 32768u;
        if (kc == NCHUNK - 1) { CP_WAIT0(); } else { CP_WAIT1(); }
        __syncthreads();
        if (kc + 2 < NCHUNK) {
            const int ns = (kc + 2) % 3;
            issue_loads(Ag, Bg, smbase + (uint32_t)ns * 49152u,
                        smbase + (uint32_t)ns * 49152u + 32768u, kc + 2, tid);
        }

        #pragma unroll
        for (int ks = 0; ks < 4; ks++) {
            uint32_t bf[4][4];
            #pragma unroll
            for (int p = 0; p < 4; p++) {
                const int brow = wn * 64 + p * 16 + (q >> 1) * 8 + (lane & 7);
                const int bg = ks * 2 + (q & 1);
                ldmx4(bf[p][0], bf[p][1], bf[p][2], bf[p][3], SW_ADDR(sb, brow, bg));
            }
            #pragma unroll
            for (int mi = 0; mi < 4; mi++) {
                const int arow = wm * 64 + mi * 16 + (lane & 15);
                const int ag = ks * 2 + (lane >> 4);
                uint32_t a0, a1, a2, a3;
                ldmx4(a0, a1, a2, a3, SW_ADDR(sa, arow, ag));
                #pragma unroll
                for (int p = 0; p < 4; p++) {
                    mma16816(acc[mi][2*p][0], acc[mi][2*p][1], acc[mi][2*p][2], acc[mi][2*p][3],
                             a0, a1, a2, a3, bf[p][0], bf[p][1]);
                    mma16816(acc[mi][2*p+1][0], acc[mi][2*p+1][1], acc[mi][2*p+1][2], acc[mi][2*p+1][3],
                             a0, a1, a2, a3, bf[p][2], bf[p][3]);
                }
            }
        }
    }
}

// ---------------- kernel 2: QKV GEMM (256x128, cp.async x3) ------------------
#define QSCALE_LOG2E 0.18033688011112042f   // (1/8) * log2(e)
__global__ __launch_bounds__(256, 1) void gemm_qkv_mma(const float* __restrict__ bias)
{
    extern __shared__ __align__(16) unsigned short smg[];
    const int tid = threadIdx.x, lane = tid & 31, wid = tid >> 5;
    const int wm = wid >> 1, wn = wid & 1;
    const int m0 = blockIdx.y * 256, n0 = blockIdx.x * 128;

    float acc[4][8][4];
    #pragma unroll
    for (int i = 0; i < 4; i++)
        #pragma unroll
        for (int j = 0; j < 8; j++)
            #pragma unroll
            for (int c = 0; c < 4; c++) acc[i][j][c] = 0.f;

    mma_mainloop_big(g_A2y + (size_t)m0 * K2, g_B2q + (size_t)n0 * K2,
                     smem_u32(smg), acc, tid, lane, wm, wn);

    const int gid = lane >> 2, tin = lane & 3;
    const int which = n0 >> 10;                   // 0=q 1=k 2=v
    unsigned short* Ha = (which == 0) ? g_Qh : (which == 1) ? g_Kh : g_Vh;
    unsigned short* La = (which == 0) ? g_Ql : (which == 1) ? g_Kl : g_Vl;
    const float qscale = (which == 0) ? QSCALE_LOG2E : 1.0f;
    #pragma unroll
    for (int mi = 0; mi < 4; mi++) {
        #pragma unroll
        for (int half = 0; half < 2; half++) {
            const int m = m0 + wm * 64 + mi * 16 + gid + half * 8;
            const int b = m >> 11, s = m & (SEQ - 1);
            #pragma unroll
            for (int ni = 0; ni < 8; ni++) {
                const int n = n0 + wn * 64 + ni * 8 + tin * 2;
                const int e = n & (EDIM - 1);
                const int h = e >> 6, d = e & (DHEAD - 1);
                float vx = (acc[mi][ni][half * 2 + 0] + bias[n]) * qscale;
                float vy = (acc[mi][ni][half * 2 + 1] + bias[n + 1]) * qscale;
                unsigned short h0 = bf_hi(vx), h1 = bf_hi(vy);
                unsigned short l0 = bf_lo(vx, h0), l1 = bf_lo(vy, h1);
                const size_t off = (size_t)((b * HEADS + h) * SEQ + s) * DHEAD + d;
                *(uint32_t*)(Ha + off) = (uint32_t)h0 | ((uint32_t)h1 << 16);
                *(uint32_t*)(La + off) = (uint32_t)l0 | ((uint32_t)l1 << 16);
            }
        }
    }
}

// ---------------- kernel 4: out-proj GEMM (256x128) + residual ---------------
__global__ __launch_bounds__(256, 1) void gemm_out_mma(const float* __restrict__ yres)
{
    extern __shared__ __align__(16) unsigned short smg[];
    const int tid = threadIdx.x, lane = tid & 31, wid = tid >> 5;
    const int wm = wid >> 1, wn = wid & 1;
    const int m0 = blockIdx.y * 256, n0 = blockIdx.x * 128;

    float acc[4][8][4];
    #pragma unroll
    for (int i = 0; i < 4; i++)
        #pragma unroll
        for (int j = 0; j < 8; j++)
            #pragma unroll
            for (int c = 0; c < 4; c++) acc[i][j][c] = 0.f;

    mma_mainloop_big(g_A2o + (size_t)m0 * K2, g_B2o + (size_t)n0 * K2,
                     smem_u32(smg), acc, tid, lane, wm, wn);

    const int gid = lane >> 2, tin = lane & 3;
    #pragma unroll
    for (int mi = 0; mi < 4; mi++) {
        #pragma unroll
        for (int half = 0; half < 2; half++) {
            const int m = m0 + wm * 64 + mi * 16 + gid + half * 8;
            #pragma unroll
            for (int ni = 0; ni < 8; ni++) {
                const int n = n0 + wn * 64 + ni * 8 + tin * 2;
                float2 r = *(const float2*)(yres + (size_t)m * EDIM + n);
                float2 v;
                v.x = acc[mi][ni][half * 2 + 0] + r.x;
                v.y = acc[mi][ni][half * 2 + 1] + r.y;
                *(float2*)(g_Mb + (size_t)m * EDIM + n) = v;
            }
        }
    }
}

// ---------------- kernel 3: flash attention (BQ=64, KVT=64, 2 CTAs/SM) -------
// 128 threads, 4 warps x 16 q-rows. smem bytes: Qh +0 (8KB), Ql +8192;
// KV stage s at 16384 + s*32768: Kh +0, Kl +8192, Vh +16384, Vl +24576.
// Total 16KB + 3*32KB = 112KB  ->  2 CTAs/SM.
#define ATTN_SMEM (112 * 1024)
#define KVT 64
#define NT (SEQ / KVT)

static __device__ __forceinline__ void attn_issue_kv(
    size_t hbase, int t, uint32_t stg, int tid)
{
    const int row = tid >> 3, g = tid & 7;
    const uint32_t aKh = stg, aKl = stg + 8192u, aVh = stg + 16384u, aVl = stg + 24576u;
    #pragma unroll
    for (int i = 0; i < 4; i++) {
        const int r = row + i * 16;
        const size_t src = hbase + (size_t)(t * KVT + r) * DHEAD + g * 8;
        CP_ASYNC16(SW_ADDR(aKh, r, g), g_Kh + src);
        CP_ASYNC16(SW_ADDR(aKl, r, g), g_Kl + src);
        CP_ASYNC16(SW_ADDR(aVh, r, g), g_Vh + src);
        CP_ASYNC16(SW_ADDR(aVl, r, g), g_Vl + src);
    }
    CP_COMMIT();
}

__global__ __launch_bounds__(128, 2) void attn_mma()
{
    extern __shared__ __align__(16) unsigned short smatt[];
    unsigned short* sQh = smatt;
    unsigned short* sQl = smatt + 4096;

    const int tid = threadIdx.x, lane = tid & 31, w = tid >> 5;
    const int gid = lane >> 2, tin = lane & 3;
    const int bh = blockIdx.y, q0 = blockIdx.x * 64;
    const size_t hbase = (size_t)bh * SEQ * DHEAD;
    const uint32_t smbase = smem_u32(smatt);

    // prologue: start KV tiles 0,1 while we stage Q
    attn_issue_kv(hbase, 0, smbase + 16384u, tid);
    attn_issue_kv(hbase, 1, smbase + 49152u, tid);

    {
        const int row = tid >> 3, g = tid & 7;
        #pragma unroll
        for (int i = 0; i < 4; i++) {
            const int r = row + i * 16;
            const size_t src = hbase + (size_t)(q0 + r) * DHEAD + g * 8;
            uint4 vh = *(const uint4*)(g_Qh + src);
            uint4 vl = *(const uint4*)(g_Ql + src);
            asm volatile("st.shared.v4.b32 [%0], {%1,%2,%3,%4};"
                :: "r"(SW_ADDR(smem_u32(sQh), r, g)), "r"(vh.x), "r"(vh.y), "r"(vh.z), "r"(vh.w));
            asm volatile("st.shared.v4.b32 [%0], {%1,%2,%3,%4};"
                :: "r"(SW_ADDR(smem_u32(sQl), r, g)), "r"(vl.x), "r"(vl.y), "r"(vl.z), "r"(vl.w));
        }
    }
    __syncthreads();

    uint32_t qh[4][4], ql[4][4];
    #pragma unroll
    for (int ks = 0; ks < 4; ks++) {
        const int row = w * 16 + (lane & 15);
        const int g = ks * 2 + (lane >> 4);
        ldmx4(qh[ks][0], qh[ks][1], qh[ks][2], qh[ks][3], SW_ADDR(smem_u32(sQh), row, g));
        ldmx4(ql[ks][0], ql[ks][1], ql[ks][2], ql[ks][3], SW_ADDR(smem_u32(sQl), row, g));
    }

    float ma = -1e30f, mb = -1e30f, la = 0.f, lb = 0.f;
    float o[8][4];
    #pragma unroll
    for (int i = 0; i < 8; i++)
        #pragma unroll
        for (int c = 0; c < 4; c++) o[i][c] = 0.f;

    const int q4 = lane >> 3;
    for (int t = 0; t < NT; t++) {
        const uint32_t sg = smbase + 16384u + (uint32_t)(t % 3) * 32768u;
        const uint32_t aKh = sg, aKl = sg + 8192u, aVh = sg + 16384u, aVl = sg + 24576u;
        if (t == NT - 1) { CP_WAIT0(); } else { CP_WAIT1(); }
        __syncthreads();
        if (t + 2 < NT)
            attn_issue_kv(hbase, t + 2, smbase + 16384u + (uint32_t)((t + 2) % 3) * 32768u, tid);

        float s[8][4];
        #pragma unroll
        for (int i = 0; i < 8; i++)
            #pragma unroll
            for (int c = 0; c < 4; c++) s[i][c] = 0.f;

        #pragma unroll
        for (int ks = 0; ks < 4; ks++) {
            #pragma unroll
            for (int nio = 0; nio < 4; nio++) {
                const int krow = (2 * nio + (q4 >> 1)) * 8 + (lane & 7);
                const int kg = ks * 2 + (q4 & 1);
                uint32_t b0, b1, b2, b3;
                ldmx4(b0, b1, b2, b3, SW_ADDR(aKh, krow, kg));
                mma16816(s[2*nio][0], s[2*nio][1], s[2*nio][2], s[2*nio][3],
                         qh[ks][0], qh[ks][1], qh[ks][2], qh[ks][3], b0, b1);
                mma16816(s[2*nio+1][0], s[2*nio+1][1], s[2*nio+1][2], s[2*nio+1][3],
                         qh[ks][0], qh[ks][1], qh[ks][2], qh[ks][3], b2, b3);
                mma16816(s[2*nio][0], s[2*nio][1], s[2*nio][2], s[2*nio][3],
                         ql[ks][0], ql[ks][1], ql[ks][2], ql[ks][3], b0, b1);
                mma16816(s[2*nio+1][0], s[2*nio+1][1], s[2*nio+1][2], s[2*nio+1][3],
                         ql[ks][0], ql[ks][1], ql[ks][2], ql[ks][3], b2, b3);
                uint32_t c0, c1, c2, c3;
                ldmx4(c0, c1, c2, c3, SW_ADDR(aKl, krow, kg));
                mma16816(s[2*nio][0], s[2*nio][1], s[2*nio][2], s[2*nio][3],
                         qh[ks][0], qh[ks][1], qh[ks][2], qh[ks][3], c0, c1);
                mma16816(s[2*nio+1][0], s[2*nio+1][1], s[2*nio+1][2], s[2*nio+1][3],
                         qh[ks][0], qh[ks][1], qh[ks][2], qh[ks][3], c2, c3);
            }
        }

        // scores in log2 domain (log2e folded into Q scale) -> exp2f
        float mxa = -1e30f, mxb = -1e30f;
        #pragma unroll
        for (int i = 0; i < 8; i++) {
            mxa = fmaxf(mxa, fmaxf(s[i][0], s[i][1]));
            mxb = fmaxf(mxb, fmaxf(s[i][2], s[i][3]));
        }
        mxa = fmaxf(mxa, __shfl_xor_sync(0xffffffffu, mxa, 1));
        mxa = fmaxf(mxa, __shfl_xor_sync(0xffffffffu, mxa, 2));
        mxb = fmaxf(mxb, __shfl_xor_sync(0xffffffffu, mxb, 1));
        mxb = fmaxf(mxb, __shfl_xor_sync(0xffffffffu, mxb, 2));
        const float nma = fmaxf(ma, mxa), nmb = fmaxf(mb, mxb);
        const float alfa = exp2f(ma - nma), alfb = exp2f(mb - nmb);
        ma = nma; mb = nmb;
        float sa = 0.f, sb = 0.f;
        #pragma unroll
        for (int i = 0; i < 8; i++) {
            s[i][0] = exp2f(s[i][0] - nma); sa += s[i][0];
            s[i][1] = exp2f(s[i][1] - nma); sa += s[i][1];
            s[i][2] = exp2f(s[i][2] - nmb); sb += s[i][2];
            s[i][3] = exp2f(s[i][3] - nmb); sb += s[i][3];
        }
        sa += __shfl_xor_sync(0xffffffffu, sa, 1);
        sa += __shfl_xor_sync(0xffffffffu, sa, 2);
        sb += __shfl_xor_sync(0xffffffffu, sb, 1);
        sb += __shfl_xor_sync(0xffffffffu, sb, 2);
        la = la * alfa + sa;
        lb = lb * alfb + sb;
        #pragma unroll
        for (int i = 0; i < 8; i++) {
            o[i][0] *= alfa; o[i][1] *= alfa;
            o[i][2] *= alfb; o[i][3] *= alfb;
        }

        #pragma unroll
        for (int kj = 0; kj < 4; kj++) {
            uint32_t ph[4], pl[4];
            #pragma unroll
            for (int u = 0; u < 4; u++) {
                const int ni = 2 * kj + (u >> 1);
                const float p0 = s[ni][(u & 1) * 2 + 0];
                const float p1 = s[ni][(u & 1) * 2 + 1];
                const uint32_t hp = cvt_bf2(p0, p1);
                ph[u] = hp;
                const float f0 = __uint_as_float(hp << 16);
                const float f1 = __uint_as_float(hp & 0xffff0000u);
                pl[u] = cvt_bf2(p0 - f0, p1 - f1);
            }
            #pragma unroll
            for (int ndo = 0; ndo < 4; ndo++) {
                const int vrow = kj * 16 + (q4 & 1) * 8 + (lane & 7);
                const int vg = 2 * ndo + (q4 >> 1);
                uint32_t v0, v1, v2, v3;
                ldmx4t(v0, v1, v2, v3, SW_ADDR(aVh, vrow, vg));
                mma16816(o[2*ndo][0], o[2*ndo][1], o[2*ndo][2], o[2*ndo][3],
                         ph[0], ph[1], ph[2], ph[3], v0, v1);
                mma16816(o[2*ndo+1][0], o[2*ndo+1][1], o[2*ndo+1][2], o[2*ndo+1][3],
                         ph[0], ph[1], ph[2], ph[3], v2, v3);
                mma16816(o[2*ndo][0], o[2*ndo][1], o[2*ndo][2], o[2*ndo][3],
                         pl[0], pl[1], pl[2], pl[3], v0, v1);
                mma16816(o[2*ndo+1][0], o[2*ndo+1][1], o[2*ndo+1][2], o[2*ndo+1][3],
                         pl[0], pl[1], pl[2], pl[3], v2, v3);
                uint32_t u0, u1, u2, u3;
                ldmx4t(u0, u1, u2, u3, SW_ADDR(aVl, vrow, vg));
                mma16816(o[2*ndo][0], o[2*ndo][1], o[2*ndo][2], o[2*ndo][3],
                         ph[0], ph[1], ph[2], ph[3], u0, u1);
                mma16816(o[2*ndo+1][0], o[2*ndo+1][1], o[2*ndo+1][2], o[2*ndo+1][3],
                         ph[0], ph[1], ph[2], ph[3], u2, u3);
            }
        }
    }

    const float inva = 1.0f / la, invb = 1.0f / lb;
    const int b = bh >> 4, h = bh & (HEADS - 1);
    const int ra = q0 + w * 16 + gid, rb = ra + 8;
    unsigned short* rowA = g_A2o + (size_t)(b * SEQ + ra) * K2 + h * DHEAD;
    unsigned short* rowB = g_A2o + (size_t)(b * SEQ + rb) * K2 + h * DHEAD;
    #pragma unroll
    for (int nd = 0; nd < 8; nd++) {
        const int d = nd * 8 + tin * 2;
        const float x0 = o[nd][0] * inva, x1 = o[nd][1] * inva;
        const float x2 = o[nd][2] * invb, x3 = o[nd][3] * invb;
        unsigned short h0 = bf_hi(x0), h1 = bf_hi(x1);
        unsigned short l0 = bf_lo(x0, h0), l1 = bf_lo(x1, h1);
        unsigned short h2 = bf_hi(x2), h3 = bf_hi(x3);
        unsigned short l2 = bf_lo(x2, h2), l3 = bf_lo(x3, h3);
        const uint32_t hpA = (uint32_t)h0 | ((uint32_t)h1 << 16);
        const uint32_t lpA = (uint32_t)l0 | ((uint32_t)l1 << 16);
        const uint32_t hpB = (uint32_t)h2 | ((uint32_t)h3 << 16);
        const uint32_t lpB = (uint32_t)l2 | ((uint32_t)l3 << 16);
        *(uint32_t*)(rowA + d) = hpA;
        *(uint32_t*)(rowA + EDIM + d) = hpA;
        *(uint32_t*)(rowA + 2 * EDIM + d) = lpA;
        *(uint32_t*)(rowB + d) = hpB;
        *(uint32_t*)(rowB + EDIM + d) = hpB;
        *(uint32_t*)(rowB + 2 * EDIM + d) = lpB;
    }
}

// ---------------- kernel 5: LayerNorm ---------------------------------------
__global__ __launch_bounds__(256) void ln_kernel(
    const float* __restrict__ gamma, const float* __restrict__ beta,
    float* __restrict__ out)
{
    const int row = blockIdx.x;
    const int tid = threadIdx.x;
    const float4 v = *(const float4*)&g_Mb[(size_t)row * EDIM + tid * 4];
    float s = v.x + v.y + v.z + v.w;
    float q = v.x * v.x + v.y * v.y + v.z * v.z + v.w * v.w;
    #pragma unroll
    for (int off = 16; off >= 1; off >>= 1) {
        s += __shfl_xor_sync(0xffffffffu, s, off);
        q += __shfl_xor_sync(0xffffffffu, q, off);
    }
    __shared__ float ss[8], sq[8];
    const int w = tid >> 5, lane = tid & 31;
    if (lane == 0) { ss[w] = s; sq[w] = q; }
    __syncthreads();
    float tot = 0.f, totq = 0.f;
    #pragma unroll
    for (int i = 0; i < 8; i++) { tot += ss[i]; totq += sq[i]; }
    const float mu = tot * (1.0f / EDIM);
    const float var = totq * (1.0f / EDIM) - mu * mu;
    const float rs = rsqrtf(var + 1e-6f);
    const float4 g = *(const float4*)&gamma[tid * 4];
    const float4 bb = *(const float4*)&beta[tid * 4];
    float4 o;
    o.x = (v.x - mu) * rs * g.x + bb.x;
    o.y = (v.y - mu) * rs * g.y + bb.y;
    o.z = (v.z - mu) * rs * g.z + bb.z;
    o.w = (v.w - mu) * rs * g.w + bb.w;
    *(float4*)&out[(size_t)row * EDIM + tid * 4] = o;
}

// ---------------- launcher --------------------------------------------------
#define GEMM_SMEM (3 * (256 + 128) * 64 * 2)   // 144 KB

extern "C" void kernel_launch(void* const* d_in, const int* in_sizes, int n_in,
                              void* d_out, int out_size)
{
    (void)in_sizes; (void)n_in; (void)out_size;
    const float* y    = (const float*)d_in[0];
    const float* Wqkv = (const float*)d_in[1];
    const float* bqkv = (const float*)d_in[2];
    const float* Wmsa = (const float*)d_in[3];
    const float* Bq   = (const float*)d_in[4];
    const float* Aq   = (const float*)d_in[5];
    const float* Bk   = (const float*)d_in[6];
    const float* Ak   = (const float*)d_in[7];
    const float* Bv   = (const float*)d_in[8];
    const float* Av   = (const float*)d_in[9];
    const float* Bo   = (const float*)d_in[10];
    const float* Ao   = (const float*)d_in[11];
    const float* gamma= (const float*)d_in[12];
    const float* beta = (const float*)d_in[13];
    float* out = (float*)d_out;

    prep_weights<<<(4 * EDIM * EDIM) / 256, 256>>>(Wqkv, Wmsa, Bq, Aq, Bk, Ak, Bv, Av, Bo, Ao);
    convert_y<<<(MTOT * EDIM / 4) / 256, 256>>>(y);
    (void)cudaFuncSetAttribute(gemm_qkv_mma, cudaFuncAttributeMaxDynamicSharedMemorySize, GEMM_SMEM);
    (void)cudaFuncSetAttribute(gemm_out_mma, cudaFuncAttributeMaxDynamicSharedMemorySize, GEMM_SMEM);
    (void)cudaFuncSetAttribute(attn_mma, cudaFuncAttributeMaxDynamicSharedMemorySize, ATTN_SMEM);
    gemm_qkv_mma<<<dim3(3 * EDIM / 128, MTOT / 256), 256, GEMM_SMEM>>>(bqkv);
    attn_mma<<<dim3(SEQ / 64, BATCH * HEADS), 128, ATTN_SMEM>>>();
    gemm_out_mma<<<dim3(EDIM / 128, MTOT / 256), 256, GEMM_SMEM>>>(y);
    ln_kernel<<<MTOT, 256>>>(gamma, beta, out);
}

// round 12
// speedup vs baseline: 3.6197x; 1.0638x over previous
#include <cuda_runtime.h>
#include <cuda_bf16.h>
#include <cstdint>

#define EDIM   1024
#define HEADS  16
#define DHEAD  64
#define BATCH  2
#define SEQ    2048
#define RANK   8
#define MTOT   (BATCH*SEQ)
#define K2     3072          // extended K: A=[hi|hi|lo], B=[hi|lo|hi]
#define NCHUNK 48            // K2 / 64

// ---------------- scratch (device globals; no allocations allowed) ----------
__device__ unsigned short g_A2y[(size_t)MTOT*K2];      // y split-bf16 extended
__device__ unsigned short g_B2q[(size_t)3*EDIM*K2];    // folded qkv weights split-bf16
__device__ unsigned short g_A2o[(size_t)MTOT*K2];      // attention out split-bf16
__device__ unsigned short g_B2o[(size_t)EDIM*K2];      // folded out-proj weights split-bf16
__device__ unsigned short g_Qh[(size_t)BATCH*HEADS*SEQ*DHEAD];  // Q*(log2e/8) hi [bh][s][d]
__device__ unsigned short g_Ql[(size_t)BATCH*HEADS*SEQ*DHEAD];  // Q*(log2e/8) lo
__device__ unsigned short g_Kh[(size_t)BATCH*HEADS*SEQ*DHEAD];
__device__ unsigned short g_Kl[(size_t)BATCH*HEADS*SEQ*DHEAD];
__device__ unsigned short g_Vh[(size_t)BATCH*HEADS*SEQ*DHEAD];
__device__ unsigned short g_Vl[(size_t)BATCH*HEADS*SEQ*DHEAD];
__device__ float g_Mb[(size_t)MTOT*EDIM];              // msa + residual

// ---------------- bf16 split helpers ----------------------------------------
static __device__ __forceinline__ unsigned short bf_hi(float x) {
    return __bfloat16_as_ushort(__float2bfloat16(x));
}
static __device__ __forceinline__ unsigned short bf_lo(float x, unsigned short h) {
    float hf = __bfloat162float(__ushort_as_bfloat16(h));
    return __bfloat16_as_ushort(__float2bfloat16(x - hf));
}
static __device__ __forceinline__ uint32_t cvt_bf2(float lo, float hi) {
    uint32_t r;
    asm("cvt.rn.bf16x2.f32 %0, %1, %2;" : "=r"(r) : "f"(hi), "f"(lo));
    return r;
}

// ---------------- mma.sync helpers -------------------------------------------
static __device__ __forceinline__ uint32_t smem_u32(const void* p) {
    uint32_t a;
    asm("{ .reg .u64 t; cvta.to.shared.u64 t, %1; cvt.u32.u64 %0, t; }" : "=r"(a) : "l"(p));
    return a;
}
static __device__ __forceinline__ void ldmx4(
    uint32_t& r0, uint32_t& r1, uint32_t& r2, uint32_t& r3, uint32_t a) {
    asm volatile("ldmatrix.sync.aligned.m8n8.x4.shared.b16 {%0,%1,%2,%3}, [%4];"
                 : "=r"(r0), "=r"(r1), "=r"(r2), "=r"(r3) : "r"(a));
}
static __device__ __forceinline__ void ldmx4t(
    uint32_t& r0, uint32_t& r1, uint32_t& r2, uint32_t& r3, uint32_t a) {
    asm volatile("ldmatrix.sync.aligned.m8n8.x4.trans.shared.b16 {%0,%1,%2,%3}, [%4];"
                 : "=r"(r0), "=r"(r1), "=r"(r2), "=r"(r3) : "r"(a));
}
static __device__ __forceinline__ void mma16816(
    float& d0, float& d1, float& d2, float& d3,
    uint32_t a0, uint32_t a1, uint32_t a2, uint32_t a3,
    uint32_t b0, uint32_t b1) {
    asm volatile("mma.sync.aligned.m16n8k16.row.col.f32.bf16.bf16.f32 "
                 "{%0,%1,%2,%3}, {%4,%5,%6,%7}, {%8,%9}, {%0,%1,%2,%3};"
                 : "+f"(d0), "+f"(d1), "+f"(d2), "+f"(d3)
                 : "r"(a0), "r"(a1), "r"(a2), "r"(a3), "r"(b0), "r"(b1));
}
#define CP_ASYNC16(dst, src) \
    asm volatile("cp.async.cg.shared.global [%0], [%1], 16;" :: "r"(dst), "l"(src))
#define CP_COMMIT() asm volatile("cp.async.commit_group;" ::: "memory")
#define CP_WAIT1()  asm volatile("cp.async.wait_group 1;" ::: "memory")
#define CP_WAIT0()  asm volatile("cp.async.wait_group 0;" ::: "memory")

// smem tiles [rows][64 cols bf16] = [rows][8] 16B groups, swizzle g^=(row&7)
#define SW_ADDR(base, row, g) ((base) + (row) * 128u + (uint32_t)(((g) ^ ((row) & 7)) << 4))

// ---------------- kernel 1: fold LoRA + split weights + split y (merged) -----
#define NQKV (3 * EDIM * EDIM)
#define NWM  (EDIM * EDIM)
#define NCNV (MTOT * EDIM / 4)
__global__ __launch_bounds__(256) void prep_all(
    const float* __restrict__ y,
    const float* __restrict__ Wqkv, const float* __restrict__ Wmsa,
    const float* __restrict__ Bq, const float* __restrict__ Aq,
    const float* __restrict__ Bk, const float* __restrict__ Ak,
    const float* __restrict__ Bv, const float* __restrict__ Av,
    const float* __restrict__ Bo, const float* __restrict__ Ao)
{
    const int idx = blockIdx.x * blockDim.x + threadIdx.x;
    if (idx < NQKV) {
        const int o = idx >> 10;
        const int i = idx & (EDIM - 1);
        const int which = o >> 10;
        const int e = o & (EDIM - 1);
        const float* Bw = (which == 0) ? Bq : (which == 1) ? Bk : Bv;
        const float* Aw = (which == 0) ? Aq : (which == 1) ? Ak : Av;
        float acc = Wqkv[idx];
        #pragma unroll
        for (int r = 0; r < RANK; r++) acc += Bw[i * RANK + r] * Aw[r * EDIM + e];
        unsigned short h = bf_hi(acc), l = bf_lo(acc, h);
        unsigned short* row = g_B2q + (size_t)o * K2;
        row[i] = h; row[EDIM + i] = l; row[2 * EDIM + i] = h;   // B2 = [hi|lo|hi]
    } else if (idx < NQKV + NWM) {
        const int j = idx - NQKV;
        const int o = j >> 10;
        const int i = j & (EDIM - 1);
        float acc = Wmsa[j];
        #pragma unroll
        for (int r = 0; r < RANK; r++) acc += Bo[i * RANK + r] * Ao[r * EDIM + o];
        unsigned short h = bf_hi(acc), l = bf_lo(acc, h);
        unsigned short* row = g_B2o + (size_t)o * K2;
        row[i] = h; row[EDIM + i] = l; row[2 * EDIM + i] = h;
    } else {
        const int j = idx - NQKV - NWM;           // [0, MTOT*EDIM/4)
        const int m = j >> 8;
        const int c = (j & 255) * 4;
        float4 v = *(const float4*)(y + (size_t)m * EDIM + c);
        unsigned short h0 = bf_hi(v.x), h1 = bf_hi(v.y), h2 = bf_hi(v.z), h3 = bf_hi(v.w);
        unsigned short l0 = bf_lo(v.x, h0), l1 = bf_lo(v.y, h1), l2 = bf_lo(v.z, h2), l3 = bf_lo(v.w, h3);
        uint2 hp = make_uint2((uint32_t)h0 | ((uint32_t)h1 << 16), (uint32_t)h2 | ((uint32_t)h3 << 16));
        uint2 lp = make_uint2((uint32_t)l0 | ((uint32_t)l1 << 16), (uint32_t)l2 | ((uint32_t)l3 << 16));
        unsigned short* row = g_A2y + (size_t)m * K2 + c;      // A2 = [hi|hi|lo]
        *(uint2*)(row) = hp;
        *(uint2*)(row + EDIM) = hp;
        *(uint2*)(row + 2 * EDIM) = lp;
    }
}

// ---------------- GEMM mainloop: 128x128 tile, 128 thr, cp.async x3 ----------
// stage s (bytes): A at smbase + s*32768, B at +16384. Total 96 KB -> 2 CTAs/SM
static __device__ __forceinline__ void issue_loads(
    const unsigned short* __restrict__ Ag, const unsigned short* __restrict__ Bg,
    uint32_t sa, uint32_t sb, int kc, int tid)
{
    const int r0 = tid >> 3, g = tid & 7;       // r0 0..15, g 0..7
    const int koff = kc * 64 + g * 8;
    #pragma unroll
    for (int p = 0; p < 8; p++) {
        const int row = p * 16 + r0;
        CP_ASYNC16(SW_ADDR(sa, row, g), Ag + (size_t)row * K2 + koff);
    }
    #pragma unroll
    for (int p = 0; p < 8; p++) {
        const int row = p * 16 + r0;
        CP_ASYNC16(SW_ADDR(sb, row, g), Bg + (size_t)row * K2 + koff);
    }
    CP_COMMIT();
}

static __device__ __forceinline__ void mma_mainloop_big(
    const unsigned short* __restrict__ Ag, const unsigned short* __restrict__ Bg,
    uint32_t smbase, float acc[4][8][4], int tid, int lane, int wm, int wn)
{
    issue_loads(Ag, Bg, smbase, smbase + 16384u, 0, tid);
    issue_loads(Ag, Bg, smbase + 32768u, smbase + 49152u, 1, tid);

    const int q = lane >> 3;                 // 0..3 quad-of-8
    for (int kc = 0; kc < NCHUNK; kc++) {
        const int st = kc % 3;
        const uint32_t sa = smbase + (uint32_t)st * 32768u;
        const uint32_t sb = sa + 16384u;
        if (kc == NCHUNK - 1) { CP_WAIT0(); } else { CP_WAIT1(); }
        __syncthreads();
        if (kc + 2 < NCHUNK) {
            const int ns = (kc + 2) % 3;
            issue_loads(Ag, Bg, smbase + (uint32_t)ns * 32768u,
                        smbase + (uint32_t)ns * 32768u + 16384u, kc + 2, tid);
        }

        #pragma unroll
        for (int ks = 0; ks < 4; ks++) {
            uint32_t bf[4][4];
            #pragma unroll
            for (int p = 0; p < 4; p++) {
                const int brow = wn * 64 + p * 16 + (q >> 1) * 8 + (lane & 7);
                const int bg = ks * 2 + (q & 1);
                ldmx4(bf[p][0], bf[p][1], bf[p][2], bf[p][3], SW_ADDR(sb, brow, bg));
            }
            #pragma unroll
            for (int mi = 0; mi < 4; mi++) {
                const int arow = wm * 64 + mi * 16 + (lane & 15);
                const int ag = ks * 2 + (lane >> 4);
                uint32_t a0, a1, a2, a3;
                ldmx4(a0, a1, a2, a3, SW_ADDR(sa, arow, ag));
                #pragma unroll
                for (int p = 0; p < 4; p++) {
                    mma16816(acc[mi][2*p][0], acc[mi][2*p][1], acc[mi][2*p][2], acc[mi][2*p][3],
                             a0, a1, a2, a3, bf[p][0], bf[p][1]);
                    mma16816(acc[mi][2*p+1][0], acc[mi][2*p+1][1], acc[mi][2*p+1][2], acc[mi][2*p+1][3],
                             a0, a1, a2, a3, bf[p][2], bf[p][3]);
                }
            }
        }
    }
}

// ---------------- kernel 2: QKV GEMM (128x128, 2 CTAs/SM) --------------------
#define QSCALE_LOG2E 0.18033688011112042f   // (1/8) * log2(e)
__global__ __launch_bounds__(128, 2) void gemm_qkv_mma(const float* __restrict__ bias)
{
    extern __shared__ __align__(16) unsigned short smg[];
    const int tid = threadIdx.x, lane = tid & 31, wid = tid >> 5;
    const int wm = wid >> 1, wn = wid & 1;
    const int m0 = blockIdx.y * 128, n0 = blockIdx.x * 128;

    float acc[4][8][4];
    #pragma unroll
    for (int i = 0; i < 4; i++)
        #pragma unroll
        for (int j = 0; j < 8; j++)
            #pragma unroll
            for (int c = 0; c < 4; c++) acc[i][j][c] = 0.f;

    mma_mainloop_big(g_A2y + (size_t)m0 * K2, g_B2q + (size_t)n0 * K2,
                     smem_u32(smg), acc, tid, lane, wm, wn);

    const int gid = lane >> 2, tin = lane & 3;
    const int which = n0 >> 10;                   // 0=q 1=k 2=v
    unsigned short* Ha = (which == 0) ? g_Qh : (which == 1) ? g_Kh : g_Vh;
    unsigned short* La = (which == 0) ? g_Ql : (which == 1) ? g_Kl : g_Vl;
    const float qscale = (which == 0) ? QSCALE_LOG2E : 1.0f;
    #pragma unroll
    for (int mi = 0; mi < 4; mi++) {
        #pragma unroll
        for (int half = 0; half < 2; half++) {
            const int m = m0 + wm * 64 + mi * 16 + gid + half * 8;
            const int b = m >> 11, s = m & (SEQ - 1);
            #pragma unroll
            for (int ni = 0; ni < 8; ni++) {
                const int n = n0 + wn * 64 + ni * 8 + tin * 2;
                const int e = n & (EDIM - 1);
                const int h = e >> 6, d = e & (DHEAD - 1);
                float vx = (acc[mi][ni][half * 2 + 0] + bias[n]) * qscale;
                float vy = (acc[mi][ni][half * 2 + 1] + bias[n + 1]) * qscale;
                unsigned short h0 = bf_hi(vx), h1 = bf_hi(vy);
                unsigned short l0 = bf_lo(vx, h0), l1 = bf_lo(vy, h1);
                const size_t off = (size_t)((b * HEADS + h) * SEQ + s) * DHEAD + d;
                *(uint32_t*)(Ha + off) = (uint32_t)h0 | ((uint32_t)h1 << 16);
                *(uint32_t*)(La + off) = (uint32_t)l0 | ((uint32_t)l1 << 16);
            }
        }
    }
}

// ---------------- kernel 4: out-proj GEMM (128x128, 2 CTAs/SM) + residual ----
__global__ __launch_bounds__(128, 2) void gemm_out_mma(const float* __restrict__ yres)
{
    extern __shared__ __align__(16) unsigned short smg[];
    const int tid = threadIdx.x, lane = tid & 31, wid = tid >> 5;
    const int wm = wid >> 1, wn = wid & 1;
    const int m0 = blockIdx.y * 128, n0 = blockIdx.x * 128;

    float acc[4][8][4];
    #pragma unroll
    for (int i = 0; i < 4; i++)
        #pragma unroll
        for (int j = 0; j < 8; j++)
            #pragma unroll
            for (int c = 0; c < 4; c++) acc[i][j][c] = 0.f;

    mma_mainloop_big(g_A2o + (size_t)m0 * K2, g_B2o + (size_t)n0 * K2,
                     smem_u32(smg), acc, tid, lane, wm, wn);

    const int gid = lane >> 2, tin = lane & 3;
    #pragma unroll
    for (int mi = 0; mi < 4; mi++) {
        #pragma unroll
        for (int half = 0; half < 2; half++) {
            const int m = m0 + wm * 64 + mi * 16 + gid + half * 8;
            #pragma unroll
            for (int ni = 0; ni < 8; ni++) {
                const int n = n0 + wn * 64 + ni * 8 + tin * 2;
                float2 r = *(const float2*)(yres + (size_t)m * EDIM + n);
                float2 v;
                v.x = acc[mi][ni][half * 2 + 0] + r.x;
                v.y = acc[mi][ni][half * 2 + 1] + r.y;
                *(float2*)(g_Mb + (size_t)m * EDIM + n) = v;
            }
        }
    }
}

// ---------------- kernel 3: flash attention (BQ=64, KVT=64, 2 CTAs/SM) -------
#define ATTN_SMEM (112 * 1024)
#define KVT 64
#define NT (SEQ / KVT)

static __device__ __forceinline__ void attn_issue_kv(
    size_t hbase, int t, uint32_t stg, int tid)
{
    const int row = tid >> 3, g = tid & 7;
    const uint32_t aKh = stg, aKl = stg + 8192u, aVh = stg + 16384u, aVl = stg + 24576u;
    #pragma unroll
    for (int i = 0; i < 4; i++) {
        const int r = row + i * 16;
        const size_t src = hbase + (size_t)(t * KVT + r) * DHEAD + g * 8;
        CP_ASYNC16(SW_ADDR(aKh, r, g), g_Kh + src);
        CP_ASYNC16(SW_ADDR(aKl, r, g), g_Kl + src);
        CP_ASYNC16(SW_ADDR(aVh, r, g), g_Vh + src);
        CP_ASYNC16(SW_ADDR(aVl, r, g), g_Vl + src);
    }
    CP_COMMIT();
}

__global__ __launch_bounds__(128, 2) void attn_mma()
{
    extern __shared__ __align__(16) unsigned short smatt[];
    unsigned short* sQh = smatt;
    unsigned short* sQl = smatt + 4096;

    const int tid = threadIdx.x, lane = tid & 31, w = tid >> 5;
    const int gid = lane >> 2, tin = lane & 3;
    const int bh = blockIdx.y, q0 = blockIdx.x * 64;
    const size_t hbase = (size_t)bh * SEQ * DHEAD;
    const uint32_t smbase = smem_u32(smatt);

    attn_issue_kv(hbase, 0, smbase + 16384u, tid);
    attn_issue_kv(hbase, 1, smbase + 49152u, tid);

    {
        const int row = tid >> 3, g = tid & 7;
        #pragma unroll
        for (int i = 0; i < 4; i++) {
            const int r = row + i * 16;
            const size_t src = hbase + (size_t)(q0 + r) * DHEAD + g * 8;
            uint4 vh = *(const uint4*)(g_Qh + src);
            uint4 vl = *(const uint4*)(g_Ql + src);
            asm volatile("st.shared.v4.b32 [%0], {%1,%2,%3,%4};"
                :: "r"(SW_ADDR(smem_u32(sQh), r, g)), "r"(vh.x), "r"(vh.y), "r"(vh.z), "r"(vh.w));
            asm volatile("st.shared.v4.b32 [%0], {%1,%2,%3,%4};"
                :: "r"(SW_ADDR(smem_u32(sQl), r, g)), "r"(vl.x), "r"(vl.y), "r"(vl.z), "r"(vl.w));
        }
    }
    __syncthreads();

    uint32_t qh[4][4], ql[4][4];
    #pragma unroll
    for (int ks = 0; ks < 4; ks++) {
        const int row = w * 16 + (lane & 15);
        const int g = ks * 2 + (lane >> 4);
        ldmx4(qh[ks][0], qh[ks][1], qh[ks][2], qh[ks][3], SW_ADDR(smem_u32(sQh), row, g));
        ldmx4(ql[ks][0], ql[ks][1], ql[ks][2], ql[ks][3], SW_ADDR(smem_u32(sQl), row, g));
    }

    float ma = -1e30f, mb = -1e30f, la = 0.f, lb = 0.f;
    float o[8][4];
    #pragma unroll
    for (int i = 0; i < 8; i++)
        #pragma unroll
        for (int c = 0; c < 4; c++) o[i][c] = 0.f;

    const int q4 = lane >> 3;
    for (int t = 0; t < NT; t++) {
        const uint32_t sg = smbase + 16384u + (uint32_t)(t % 3) * 32768u;
        const uint32_t aKh = sg, aKl = sg + 8192u, aVh = sg + 16384u, aVl = sg + 24576u;
        if (t == NT - 1) { CP_WAIT0(); } else { CP_WAIT1(); }
        __syncthreads();
        if (t + 2 < NT)
            attn_issue_kv(hbase, t + 2, smbase + 16384u + (uint32_t)((t + 2) % 3) * 32768u, tid);

        float s[8][4];
        #pragma unroll
        for (int i = 0; i < 8; i++)
            #pragma unroll
            for (int c = 0; c < 4; c++) s[i][c] = 0.f;

        #pragma unroll
        for (int ks = 0; ks < 4; ks++) {
            #pragma unroll
            for (int nio = 0; nio < 4; nio++) {
                const int krow = (2 * nio + (q4 >> 1)) * 8 + (lane & 7);
                const int kg = ks * 2 + (q4 & 1);
                uint32_t b0, b1, b2, b3;
                ldmx4(b0, b1, b2, b3, SW_ADDR(aKh, krow, kg));
                mma16816(s[2*nio][0], s[2*nio][1], s[2*nio][2], s[2*nio][3],
                         qh[ks][0], qh[ks][1], qh[ks][2], qh[ks][3], b0, b1);
                mma16816(s[2*nio+1][0], s[2*nio+1][1], s[2*nio+1][2], s[2*nio+1][3],
                         qh[ks][0], qh[ks][1], qh[ks][2], qh[ks][3], b2, b3);
                mma16816(s[2*nio][0], s[2*nio][1], s[2*nio][2], s[2*nio][3],
                         ql[ks][0], ql[ks][1], ql[ks][2], ql[ks][3], b0, b1);
                mma16816(s[2*nio+1][0], s[2*nio+1][1], s[2*nio+1][2], s[2*nio+1][3],
                         ql[ks][0], ql[ks][1], ql[ks][2], ql[ks][3], b2, b3);
                uint32_t c0, c1, c2, c3;
                ldmx4(c0, c1, c2, c3, SW_ADDR(aKl, krow, kg));
                mma16816(s[2*nio][0], s[2*nio][1], s[2*nio][2], s[2*nio][3],
                         qh[ks][0], qh[ks][1], qh[ks][2], qh[ks][3], c0, c1);
                mma16816(s[2*nio+1][0], s[2*nio+1][1], s[2*nio+1][2], s[2*nio+1][3],
                         qh[ks][0], qh[ks][1], qh[ks][2], qh[ks][3], c2, c3);
            }
        }

        float mxa = -1e30f, mxb = -1e30f;
        #pragma unroll
        for (int i = 0; i < 8; i++) {
            mxa = fmaxf(mxa, fmaxf(s[i][0], s[i][1]));
            mxb = fmaxf(mxb, fmaxf(s[i][2], s[i][3]));
        }
        mxa = fmaxf(mxa, __shfl_xor_sync(0xffffffffu, mxa, 1));
        mxa = fmaxf(mxa, __shfl_xor_sync(0xffffffffu, mxa, 2));
        mxb = fmaxf(mxb, __shfl_xor_sync(0xffffffffu, mxb, 1));
        mxb = fmaxf(mxb, __shfl_xor_sync(0xffffffffu, mxb, 2));
        const float nma = fmaxf(ma, mxa), nmb = fmaxf(mb, mxb);
        const float alfa = exp2f(ma - nma), alfb = exp2f(mb - nmb);
        ma = nma; mb = nmb;
        float sa = 0.f, sb = 0.f;
        #pragma unroll
        for (int i = 0; i < 8; i++) {
            s[i][0] = exp2f(s[i][0] - nma); sa += s[i][0];
            s[i][1] = exp2f(s[i][1] - nma); sa += s[i][1];
            s[i][2] = exp2f(s[i][2] - nmb); sb += s[i][2];
            s[i][3] = exp2f(s[i][3] - nmb); sb += s[i][3];
        }
        sa += __shfl_xor_sync(0xffffffffu, sa, 1);
        sa += __shfl_xor_sync(0xffffffffu, sa, 2);
        sb += __shfl_xor_sync(0xffffffffu, sb, 1);
        sb += __shfl_xor_sync(0xffffffffu, sb, 2);
        la = la * alfa + sa;
        lb = lb * alfb + sb;
        #pragma unroll
        for (int i = 0; i < 8; i++) {
            o[i][0] *= alfa; o[i][1] *= alfa;
            o[i][2] *= alfb; o[i][3] *= alfb;
        }

        #pragma unroll
        for (int kj = 0; kj < 4; kj++) {
            uint32_t ph[4], pl[4];
            #pragma unroll
            for (int u = 0; u < 4; u++) {
                const int ni = 2 * kj + (u >> 1);
                const float p0 = s[ni][(u & 1) * 2 + 0];
                const float p1 = s[ni][(u & 1) * 2 + 1];
                const uint32_t hp = cvt_bf2(p0, p1);
                ph[u] = hp;
                const float f0 = __uint_as_float(hp << 16);
                const float f1 = __uint_as_float(hp & 0xffff0000u);
                pl[u] = cvt_bf2(p0 - f0, p1 - f1);
            }
            #pragma unroll
            for (int ndo = 0; ndo < 4; ndo++) {
                const int vrow = kj * 16 + (q4 & 1) * 8 + (lane & 7);
                const int vg = 2 * ndo + (q4 >> 1);
                uint32_t v0, v1, v2, v3;
                ldmx4t(v0, v1, v2, v3, SW_ADDR(aVh, vrow, vg));
                mma16816(o[2*ndo][0], o[2*ndo][1], o[2*ndo][2], o[2*ndo][3],
                         ph[0], ph[1], ph[2], ph[3], v0, v1);
                mma16816(o[2*ndo+1][0], o[2*ndo+1][1], o[2*ndo+1][2], o[2*ndo+1][3],
                         ph[0], ph[1], ph[2], ph[3], v2, v3);
                mma16816(o[2*ndo][0], o[2*ndo][1], o[2*ndo][2], o[2*ndo][3],
                         pl[0], pl[1], pl[2], pl[3], v0, v1);
                mma16816(o[2*ndo+1][0], o[2*ndo+1][1], o[2*ndo+1][2], o[2*ndo+1][3],
                         pl[0], pl[1], pl[2], pl[3], v2, v3);
                uint32_t u0, u1, u2, u3;
                ldmx4t(u0, u1, u2, u3, SW_ADDR(aVl, vrow, vg));
                mma16816(o[2*ndo][0], o[2*ndo][1], o[2*ndo][2], o[2*ndo][3],
                         ph[0], ph[1], ph[2], ph[3], u0, u1);
                mma16816(o[2*ndo+1][0], o[2*ndo+1][1], o[2*ndo+1][2], o[2*ndo+1][3],
                         ph[0], ph[1], ph[2], ph[3], u2, u3);
            }
        }
    }

    const float inva = 1.0f / la, invb = 1.0f / lb;
    const int b = bh >> 4, h = bh & (HEADS - 1);
    const int ra = q0 + w * 16 + gid, rb = ra + 8;
    unsigned short* rowA = g_A2o + (size_t)(b * SEQ + ra) * K2 + h * DHEAD;
    unsigned short* rowB = g_A2o + (size_t)(b * SEQ + rb) * K2 + h * DHEAD;
    #pragma unroll
    for (int nd = 0; nd < 8; nd++) {
        const int d = nd * 8 + tin * 2;
        const float x0 = o[nd][0] * inva, x1 = o[nd][1] * inva;
        const float x2 = o[nd][2] * invb, x3 = o[nd][3] * invb;
        unsigned short h0 = bf_hi(x0), h1 = bf_hi(x1);
        unsigned short l0 = bf_lo(x0, h0), l1 = bf_lo(x1, h1);
        unsigned short h2 = bf_hi(x2), h3 = bf_hi(x3);
        unsigned short l2 = bf_lo(x2, h2), l3 = bf_lo(x3, h3);
        const uint32_t hpA = (uint32_t)h0 | ((uint32_t)h1 << 16);
        const uint32_t lpA = (uint32_t)l0 | ((uint32_t)l1 << 16);
        const uint32_t hpB = (uint32_t)h2 | ((uint32_t)h3 << 16);
        const uint32_t lpB = (uint32_t)l2 | ((uint32_t)l3 << 16);
        *(uint32_t*)(rowA + d) = hpA;
        *(uint32_t*)(rowA + EDIM + d) = hpA;
        *(uint32_t*)(rowA + 2 * EDIM + d) = lpA;
        *(uint32_t*)(rowB + d) = hpB;
        *(uint32_t*)(rowB + EDIM + d) = hpB;
        *(uint32_t*)(rowB + 2 * EDIM + d) = lpB;
    }
}

// ---------------- kernel 5: LayerNorm ---------------------------------------
__global__ __launch_bounds__(256) void ln_kernel(
    const float* __restrict__ gamma, const float* __restrict__ beta,
    float* __restrict__ out)
{
    const int row = blockIdx.x;
    const int tid = threadIdx.x;
    const float4 v = *(const float4*)&g_Mb[(size_t)row * EDIM + tid * 4];
    float s = v.x + v.y + v.z + v.w;
    float q = v.x * v.x + v.y * v.y + v.z * v.z + v.w * v.w;
    #pragma unroll
    for (int off = 16; off >= 1; off >>= 1) {
        s += __shfl_xor_sync(0xffffffffu, s, off);
        q += __shfl_xor_sync(0xffffffffu, q, off);
    }
    __shared__ float ss[8], sq[8];
    const int w = tid >> 5, lane = tid & 31;
    if (lane == 0) { ss[w] = s; sq[w] = q; }
    __syncthreads();
    float tot = 0.f, totq = 0.f;
    #pragma unroll
    for (int i = 0; i < 8; i++) { tot += ss[i]; totq += sq[i]; }
    const float mu = tot * (1.0f / EDIM);
    const float var = totq * (1.0f / EDIM) - mu * mu;
    const float rs = rsqrtf(var + 1e-6f);
    const float4 g = *(const float4*)&gamma[tid * 4];
    const float4 bb = *(const float4*)&beta[tid * 4];
    float4 o;
    o.x = (v.x - mu) * rs * g.x + bb.x;
    o.y = (v.y - mu) * rs * g.y + bb.y;
    o.z = (v.z - mu) * rs * g.z + bb.z;
    o.w = (v.w - mu) * rs * g.w + bb.w;
    *(float4*)&out[(size_t)row * EDIM + tid * 4] = o;
}

// ---------------- launcher --------------------------------------------------
#define GEMM_SMEM (3 * (128 + 128) * 64 * 2)   // 96 KB

extern "C" void kernel_launch(void* const* d_in, const int* in_sizes, int n_in,
                              void* d_out, int out_size)
{
    (void)in_sizes; (void)n_in; (void)out_size;
    const float* y    = (const float*)d_in[0];
    const float* Wqkv = (const float*)d_in[1];
    const float* bqkv = (const float*)d_in[2];
    const float* Wmsa = (const float*)d_in[3];
    const float* Bq   = (const float*)d_in[4];
    const float* Aq   = (const float*)d_in[5];
    const float* Bk   = (const float*)d_in[6];
    const float* Ak   = (const float*)d_in[7];
    const float* Bv   = (const float*)d_in[8];
    const float* Av   = (const float*)d_in[9];
    const float* Bo   = (const float*)d_in[10];
    const float* Ao   = (const float*)d_in[11];
    const float* gamma= (const float*)d_in[12];
    const float* beta = (const float*)d_in[13];
    float* out = (float*)d_out;

    prep_all<<<(NQKV + NWM + NCNV) / 256, 256>>>(y, Wqkv, Wmsa, Bq, Aq, Bk, Ak, Bv, Av, Bo, Ao);
    (void)cudaFuncSetAttribute(gemm_qkv_mma, cudaFuncAttributeMaxDynamicSharedMemorySize, GEMM_SMEM);
    (void)cudaFuncSetAttribute(gemm_out_mma, cudaFuncAttributeMaxDynamicSharedMemorySize, GEMM_SMEM);
    (void)cudaFuncSetAttribute(attn_mma, cudaFuncAttributeMaxDynamicSharedMemorySize, ATTN_SMEM);
    gemm_qkv_mma<<<dim3(3 * EDIM / 128, MTOT / 128), 128, GEMM_SMEM>>>(bqkv);
    attn_mma<<<dim3(SEQ / 64, BATCH * HEADS), 128, ATTN_SMEM>>>();
    gemm_out_mma<<<dim3(EDIM / 128, MTOT / 128), 128, GEMM_SMEM>>>(y);
    ln_kernel<<<MTOT, 256>>>(gamma, beta, out);
}

// round 14
// speedup vs baseline: 3.9983x; 1.1046x over previous
#include <cuda_runtime.h>
#include <cuda_bf16.h>
#include <cstdint>

#define EDIM   1024
#define HEADS  16
#define DHEAD  64
#define BATCH  2
#define SEQ    2048
#define RANK   8
#define MTOT   (BATCH*SEQ)
#define K2     3072          // extended K: A=[hi|hi|lo], B=[hi|lo|hi]
#define NCHUNK 48            // K2 / 64  (qkv: 3-term)
#define NCHUNK_OUT 32        // out-proj: 2-term -> K=2048 = [hi|hi]x[hi|lo]

// ---------------- scratch (device globals; no allocations allowed) ----------
__device__ unsigned short g_A2y[(size_t)MTOT*K2];      // y split-bf16 extended
__device__ unsigned short g_B2q[(size_t)3*EDIM*K2];    // folded qkv weights split-bf16
__device__ unsigned short g_A2o[(size_t)MTOT*K2];      // attention out split-bf16
__device__ unsigned short g_B2o[(size_t)EDIM*K2];      // folded out-proj weights split-bf16
__device__ unsigned short g_Qh[(size_t)BATCH*HEADS*SEQ*DHEAD];  // Q*(log2e/8) hi [bh][s][d]
__device__ unsigned short g_Ql[(size_t)BATCH*HEADS*SEQ*DHEAD];  // Q*(log2e/8) lo
__device__ unsigned short g_Kh[(size_t)BATCH*HEADS*SEQ*DHEAD];
__device__ unsigned short g_Kl[(size_t)BATCH*HEADS*SEQ*DHEAD];
__device__ unsigned short g_Vh[(size_t)BATCH*HEADS*SEQ*DHEAD];
__device__ unsigned short g_Vl[(size_t)BATCH*HEADS*SEQ*DHEAD];
__device__ float g_Mb[(size_t)MTOT*EDIM];              // msa + residual

// ---------------- bf16 split helpers ----------------------------------------
static __device__ __forceinline__ unsigned short bf_hi(float x) {
    return __bfloat16_as_ushort(__float2bfloat16(x));
}
static __device__ __forceinline__ unsigned short bf_lo(float x, unsigned short h) {
    float hf = __bfloat162float(__ushort_as_bfloat16(h));
    return __bfloat16_as_ushort(__float2bfloat16(x - hf));
}
static __device__ __forceinline__ uint32_t cvt_bf2(float lo, float hi) {
    uint32_t r;
    asm("cvt.rn.bf16x2.f32 %0, %1, %2;" : "=r"(r) : "f"(hi), "f"(lo));
    return r;
}

// ---------------- mma.sync helpers -------------------------------------------
static __device__ __forceinline__ uint32_t smem_u32(const void* p) {
    uint32_t a;
    asm("{ .reg .u64 t; cvta.to.shared.u64 t, %1; cvt.u32.u64 %0, t; }" : "=r"(a) : "l"(p));
    return a;
}
static __device__ __forceinline__ void ldmx4(
    uint32_t& r0, uint32_t& r1, uint32_t& r2, uint32_t& r3, uint32_t a) {
    asm volatile("ldmatrix.sync.aligned.m8n8.x4.shared.b16 {%0,%1,%2,%3}, [%4];"
                 : "=r"(r0), "=r"(r1), "=r"(r2), "=r"(r3) : "r"(a));
}
static __device__ __forceinline__ void ldmx4t(
    uint32_t& r0, uint32_t& r1, uint32_t& r2, uint32_t& r3, uint32_t a) {
    asm volatile("ldmatrix.sync.aligned.m8n8.x4.trans.shared.b16 {%0,%1,%2,%3}, [%4];"
                 : "=r"(r0), "=r"(r1), "=r"(r2), "=r"(r3) : "r"(a));
}
static __device__ __forceinline__ void mma16816(
    float& d0, float& d1, float& d2, float& d3,
    uint32_t a0, uint32_t a1, uint32_t a2, uint32_t a3,
    uint32_t b0, uint32_t b1) {
    asm volatile("mma.sync.aligned.m16n8k16.row.col.f32.bf16.bf16.f32 "
                 "{%0,%1,%2,%3}, {%4,%5,%6,%7}, {%8,%9}, {%0,%1,%2,%3};"
                 : "+f"(d0), "+f"(d1), "+f"(d2), "+f"(d3)
                 : "r"(a0), "r"(a1), "r"(a2), "r"(a3), "r"(b0), "r"(b1));
}
#define CP_ASYNC16(dst, src) \
    asm volatile("cp.async.cg.shared.global [%0], [%1], 16;" :: "r"(dst), "l"(src))
#define CP_COMMIT() asm volatile("cp.async.commit_group;" ::: "memory")
#define CP_WAIT1()  asm volatile("cp.async.wait_group 1;" ::: "memory")
#define CP_WAIT0()  asm volatile("cp.async.wait_group 0;" ::: "memory")

// smem tiles [rows][64 cols bf16] = [rows][8] 16B groups, swizzle g^=(row&7)
#define SW_ADDR(base, row, g) ((base) + (row) * 128u + (uint32_t)(((g) ^ ((row) & 7)) << 4))

// ---------------- kernel 1: fold LoRA + split weights + split y (merged) -----
#define NQKV (3 * EDIM * EDIM)
#define NWM  (EDIM * EDIM)
#define NCNV (MTOT * EDIM / 4)
__global__ __launch_bounds__(256) void prep_all(
    const float* __restrict__ y,
    const float* __restrict__ Wqkv, const float* __restrict__ Wmsa,
    const float* __restrict__ Bq, const float* __restrict__ Aq,
    const float* __restrict__ Bk, const float* __restrict__ Ak,
    const float* __restrict__ Bv, const float* __restrict__ Av,
    const float* __restrict__ Bo, const float* __restrict__ Ao)
{
    const int idx = blockIdx.x * blockDim.x + threadIdx.x;
    if (idx < NQKV) {
        const int o = idx >> 10;
        const int i = idx & (EDIM - 1);
        const int which = o >> 10;
        const int e = o & (EDIM - 1);
        const float* Bw = (which == 0) ? Bq : (which == 1) ? Bk : Bv;
        const float* Aw = (which == 0) ? Aq : (which == 1) ? Ak : Av;
        float acc = Wqkv[idx];
        #pragma unroll
        for (int r = 0; r < RANK; r++) acc += Bw[i * RANK + r] * Aw[r * EDIM + e];
        unsigned short h = bf_hi(acc), l = bf_lo(acc, h);
        unsigned short* row = g_B2q + (size_t)o * K2;
        row[i] = h; row[EDIM + i] = l; row[2 * EDIM + i] = h;   // B2 = [hi|lo|hi]
    } else if (idx < NQKV + NWM) {
        const int j = idx - NQKV;
        const int o = j >> 10;
        const int i = j & (EDIM - 1);
        float acc = Wmsa[j];
        #pragma unroll
        for (int r = 0; r < RANK; r++) acc += Bo[i * RANK + r] * Ao[r * EDIM + o];
        unsigned short h = bf_hi(acc), l = bf_lo(acc, h);
        unsigned short* row = g_B2o + (size_t)o * K2;
        row[i] = h; row[EDIM + i] = l; row[2 * EDIM + i] = h;
    } else {
        const int j = idx - NQKV - NWM;           // [0, MTOT*EDIM/4)
        const int m = j >> 8;
        const int c = (j & 255) * 4;
        float4 v = *(const float4*)(y + (size_t)m * EDIM + c);
        unsigned short h0 = bf_hi(v.x), h1 = bf_hi(v.y), h2 = bf_hi(v.z), h3 = bf_hi(v.w);
        unsigned short l0 = bf_lo(v.x, h0), l1 = bf_lo(v.y, h1), l2 = bf_lo(v.z, h2), l3 = bf_lo(v.w, h3);
        uint2 hp = make_uint2((uint32_t)h0 | ((uint32_t)h1 << 16), (uint32_t)h2 | ((uint32_t)h3 << 16));
        uint2 lp = make_uint2((uint32_t)l0 | ((uint32_t)l1 << 16), (uint32_t)l2 | ((uint32_t)l3 << 16));
        unsigned short* row = g_A2y + (size_t)m * K2 + c;      // A2 = [hi|hi|lo]
        *(uint2*)(row) = hp;
        *(uint2*)(row + EDIM) = hp;
        *(uint2*)(row + 2 * EDIM) = lp;
    }
}

// ---------------- GEMM mainloop: 128x128 tile, 128 thr, cp.async x3 ----------
// stage s (bytes): A at smbase + s*32768, B at +16384. Total 96 KB -> 2 CTAs/SM
static __device__ __forceinline__ void issue_loads(
    const unsigned short* __restrict__ Ag, const unsigned short* __restrict__ Bg,
    uint32_t sa, uint32_t sb, int kc, int tid)
{
    const int r0 = tid >> 3, g = tid & 7;       // r0 0..15, g 0..7
    const int koff = kc * 64 + g * 8;
    #pragma unroll
    for (int p = 0; p < 8; p++) {
        const int row = p * 16 + r0;
        CP_ASYNC16(SW_ADDR(sa, row, g), Ag + (size_t)row * K2 + koff);
    }
    #pragma unroll
    for (int p = 0; p < 8; p++) {
        const int row = p * 16 + r0;
        CP_ASYNC16(SW_ADDR(sb, row, g), Bg + (size_t)row * K2 + koff);
    }
    CP_COMMIT();
}

static __device__ __forceinline__ void mma_mainloop_big(
    const unsigned short* __restrict__ Ag, const unsigned short* __restrict__ Bg,
    uint32_t smbase, float acc[4][8][4], int tid, int lane, int wm, int wn,
    int nchunk)
{
    issue_loads(Ag, Bg, smbase, smbase + 16384u, 0, tid);
    issue_loads(Ag, Bg, smbase + 32768u, smbase + 49152u, 1, tid);

    const int q = lane >> 3;                 // 0..3 quad-of-8
    for (int kc = 0; kc < nchunk; kc++) {
        const int st = kc % 3;
        const uint32_t sa = smbase + (uint32_t)st * 32768u;
        const uint32_t sb = sa + 16384u;
        if (kc == nchunk - 1) { CP_WAIT0(); } else { CP_WAIT1(); }
        __syncthreads();
        if (kc + 2 < nchunk) {
            const int ns = (kc + 2) % 3;
            issue_loads(Ag, Bg, smbase + (uint32_t)ns * 32768u,
                        smbase + (uint32_t)ns * 32768u + 16384u, kc + 2, tid);
        }

        #pragma unroll
        for (int ks = 0; ks < 4; ks++) {
            uint32_t bf[4][4];
            #pragma unroll
            for (int p = 0; p < 4; p++) {
                const int brow = wn * 64 + p * 16 + (q >> 1) * 8 + (lane & 7);
                const int bg = ks * 2 + (q & 1);
                ldmx4(bf[p][0], bf[p][1], bf[p][2], bf[p][3], SW_ADDR(sb, brow, bg));
            }
            #pragma unroll
            for (int mi = 0; mi < 4; mi++) {
                const int arow = wm * 64 + mi * 16 + (lane & 15);
                const int ag = ks * 2 + (lane >> 4);
                uint32_t a0, a1, a2, a3;
                ldmx4(a0, a1, a2, a3, SW_ADDR(sa, arow, ag));
                #pragma unroll
                for (int p = 0; p < 4; p++) {
                    mma16816(acc[mi][2*p][0], acc[mi][2*p][1], acc[mi][2*p][2], acc[mi][2*p][3],
                             a0, a1, a2, a3, bf[p][0], bf[p][1]);
                    mma16816(acc[mi][2*p+1][0], acc[mi][2*p+1][1], acc[mi][2*p+1][2], acc[mi][2*p+1][3],
                             a0, a1, a2, a3, bf[p][2], bf[p][3]);
                }
            }
        }
    }
}

// ---------------- kernel 2: QKV GEMM (128x128, 2 CTAs/SM) --------------------
#define QSCALE_LOG2E 0.18033688011112042f   // (1/8) * log2(e)
__global__ __launch_bounds__(128, 2) void gemm_qkv_mma(const float* __restrict__ bias)
{
    extern __shared__ __align__(16) unsigned short smg[];
    const int tid = threadIdx.x, lane = tid & 31, wid = tid >> 5;
    const int wm = wid >> 1, wn = wid & 1;
    const int m0 = blockIdx.y * 128, n0 = blockIdx.x * 128;

    float acc[4][8][4];
    #pragma unroll
    for (int i = 0; i < 4; i++)
        #pragma unroll
        for (int j = 0; j < 8; j++)
            #pragma unroll
            for (int c = 0; c < 4; c++) acc[i][j][c] = 0.f;

    mma_mainloop_big(g_A2y + (size_t)m0 * K2, g_B2q + (size_t)n0 * K2,
                     smem_u32(smg), acc, tid, lane, wm, wn, NCHUNK);

    const int gid = lane >> 2, tin = lane & 3;
    const int which = n0 >> 10;                   // 0=q 1=k 2=v
    unsigned short* Ha = (which == 0) ? g_Qh : (which == 1) ? g_Kh : g_Vh;
    unsigned short* La = (which == 0) ? g_Ql : (which == 1) ? g_Kl : g_Vl;
    const float qscale = (which == 0) ? QSCALE_LOG2E : 1.0f;
    #pragma unroll
    for (int mi = 0; mi < 4; mi++) {
        #pragma unroll
        for (int half = 0; half < 2; half++) {
            const int m = m0 + wm * 64 + mi * 16 + gid + half * 8;
            const int b = m >> 11, s = m & (SEQ - 1);
            #pragma unroll
            for (int ni = 0; ni < 8; ni++) {
                const int n = n0 + wn * 64 + ni * 8 + tin * 2;
                const int e = n & (EDIM - 1);
                const int h = e >> 6, d = e & (DHEAD - 1);
                float vx = (acc[mi][ni][half * 2 + 0] + bias[n]) * qscale;
                float vy = (acc[mi][ni][half * 2 + 1] + bias[n + 1]) * qscale;
                unsigned short h0 = bf_hi(vx), h1 = bf_hi(vy);
                unsigned short l0 = bf_lo(vx, h0), l1 = bf_lo(vy, h1);
                const size_t off = (size_t)((b * HEADS + h) * SEQ + s) * DHEAD + d;
                *(uint32_t*)(Ha + off) = (uint32_t)h0 | ((uint32_t)h1 << 16);
                *(uint32_t*)(La + off) = (uint32_t)l0 | ((uint32_t)l1 << 16);
            }
        }
    }
}

// ---------------- kernel 4: out-proj GEMM (2-term, K=2048) + residual --------
__global__ __launch_bounds__(128, 2) void gemm_out_mma(const float* __restrict__ yres)
{
    extern __shared__ __align__(16) unsigned short smg[];
    const int tid = threadIdx.x, lane = tid & 31, wid = tid >> 5;
    const int wm = wid >> 1, wn = wid & 1;
    const int m0 = blockIdx.y * 128, n0 = blockIdx.x * 128;

    float acc[4][8][4];
    #pragma unroll
    for (int i = 0; i < 4; i++)
        #pragma unroll
        for (int j = 0; j < 8; j++)
            #pragma unroll
            for (int c = 0; c < 4; c++) acc[i][j][c] = 0.f;

    mma_mainloop_big(g_A2o + (size_t)m0 * K2, g_B2o + (size_t)n0 * K2,
                     smem_u32(smg), acc, tid, lane, wm, wn, NCHUNK_OUT);

    const int gid = lane >> 2, tin = lane & 3;
    #pragma unroll
    for (int mi = 0; mi < 4; mi++) {
        #pragma unroll
        for (int half = 0; half < 2; half++) {
            const int m = m0 + wm * 64 + mi * 16 + gid + half * 8;
            #pragma unroll
            for (int ni = 0; ni < 8; ni++) {
                const int n = n0 + wn * 64 + ni * 8 + tin * 2;
                float2 r = *(const float2*)(yres + (size_t)m * EDIM + n);
                float2 v;
                v.x = acc[mi][ni][half * 2 + 0] + r.x;
                v.y = acc[mi][ni][half * 2 + 1] + r.y;
                *(float2*)(g_Mb + (size_t)m * EDIM + n) = v;
            }
        }
    }
}

// ---------------- kernel 3: flash attention (BQ=64, KVT=64, 2 CTAs/SM) -------
// PV uses 2 terms: Phi*(Vhi + Vlo)  (Plo term dropped; error ~2^-10, linear)
#define ATTN_SMEM (112 * 1024)
#define KVT 64
#define NT (SEQ / KVT)

static __device__ __forceinline__ void attn_issue_kv(
    size_t hbase, int t, uint32_t stg, int tid)
{
    const int row = tid >> 3, g = tid & 7;
    const uint32_t aKh = stg, aKl = stg + 8192u, aVh = stg + 16384u, aVl = stg + 24576u;
    #pragma unroll
    for (int i = 0; i < 4; i++) {
        const int r = row + i * 16;
        const size_t src = hbase + (size_t)(t * KVT + r) * DHEAD + g * 8;
        CP_ASYNC16(SW_ADDR(aKh, r, g), g_Kh + src);
        CP_ASYNC16(SW_ADDR(aKl, r, g), g_Kl + src);
        CP_ASYNC16(SW_ADDR(aVh, r, g), g_Vh + src);
        CP_ASYNC16(SW_ADDR(aVl, r, g), g_Vl + src);
    }
    CP_COMMIT();
}

__global__ __launch_bounds__(128, 2) void attn_mma()
{
    extern __shared__ __align__(16) unsigned short smatt[];
    unsigned short* sQh = smatt;
    unsigned short* sQl = smatt + 4096;

    const int tid = threadIdx.x, lane = tid & 31, w = tid >> 5;
    const int gid = lane >> 2, tin = lane & 3;
    const int bh = blockIdx.y, q0 = blockIdx.x * 64;
    const size_t hbase = (size_t)bh * SEQ * DHEAD;
    const uint32_t smbase = smem_u32(smatt);

    attn_issue_kv(hbase, 0, smbase + 16384u, tid);
    attn_issue_kv(hbase, 1, smbase + 49152u, tid);

    {
        const int row = tid >> 3, g = tid & 7;
        #pragma unroll
        for (int i = 0; i < 4; i++) {
            const int r = row + i * 16;
            const size_t src = hbase + (size_t)(q0 + r) * DHEAD + g * 8;
            uint4 vh = *(const uint4*)(g_Qh + src);
            uint4 vl = *(const uint4*)(g_Ql + src);
            asm volatile("st.shared.v4.b32 [%0], {%1,%2,%3,%4};"
                :: "r"(SW_ADDR(smem_u32(sQh), r, g)), "r"(vh.x), "r"(vh.y), "r"(vh.z), "r"(vh.w));
            asm volatile("st.shared.v4.b32 [%0], {%1,%2,%3,%4};"
                :: "r"(SW_ADDR(smem_u32(sQl), r, g)), "r"(vl.x), "r"(vl.y), "r"(vl.z), "r"(vl.w));
        }
    }
    __syncthreads();

    uint32_t qh[4][4], ql[4][4];
    #pragma unroll
    for (int ks = 0; ks < 4; ks++) {
        const int row = w * 16 + (lane & 15);
        const int g = ks * 2 + (lane >> 4);
        ldmx4(qh[ks][0], qh[ks][1], qh[ks][2], qh[ks][3], SW_ADDR(smem_u32(sQh), row, g));
        ldmx4(ql[ks][0], ql[ks][1], ql[ks][2], ql[ks][3], SW_ADDR(smem_u32(sQl), row, g));
    }

    float ma = -1e30f, mb = -1e30f, la = 0.f, lb = 0.f;
    float o[8][4];
    #pragma unroll
    for (int i = 0; i < 8; i++)
        #pragma unroll
        for (int c = 0; c < 4; c++) o[i][c] = 0.f;

    const int q4 = lane >> 3;
    for (int t = 0; t < NT; t++) {
        const uint32_t sg = smbase + 16384u + (uint32_t)(t % 3) * 32768u;
        const uint32_t aKh = sg, aKl = sg + 8192u, aVh = sg + 16384u, aVl = sg + 24576u;
        if (t == NT - 1) { CP_WAIT0(); } else { CP_WAIT1(); }
        __syncthreads();
        if (t + 2 < NT)
            attn_issue_kv(hbase, t + 2, smbase + 16384u + (uint32_t)((t + 2) % 3) * 32768u, tid);

        float s[8][4];
        #pragma unroll
        for (int i = 0; i < 8; i++)
            #pragma unroll
            for (int c = 0; c < 4; c++) s[i][c] = 0.f;

        #pragma unroll
        for (int ks = 0; ks < 4; ks++) {
            #pragma unroll
            for (int nio = 0; nio < 4; nio++) {
                const int krow = (2 * nio + (q4 >> 1)) * 8 + (lane & 7);
                const int kg = ks * 2 + (q4 & 1);
                uint32_t b0, b1, b2, b3;
                ldmx4(b0, b1, b2, b3, SW_ADDR(aKh, krow, kg));
                mma16816(s[2*nio][0], s[2*nio][1], s[2*nio][2], s[2*nio][3],
                         qh[ks][0], qh[ks][1], qh[ks][2], qh[ks][3], b0, b1);
                mma16816(s[2*nio+1][0], s[2*nio+1][1], s[2*nio+1][2], s[2*nio+1][3],
                         qh[ks][0], qh[ks][1], qh[ks][2], qh[ks][3], b2, b3);
                mma16816(s[2*nio][0], s[2*nio][1], s[2*nio][2], s[2*nio][3],
                         ql[ks][0], ql[ks][1], ql[ks][2], ql[ks][3], b0, b1);
                mma16816(s[2*nio+1][0], s[2*nio+1][1], s[2*nio+1][2], s[2*nio+1][3],
                         ql[ks][0], ql[ks][1], ql[ks][2], ql[ks][3], b2, b3);
                uint32_t c0, c1, c2, c3;
                ldmx4(c0, c1, c2, c3, SW_ADDR(aKl, krow, kg));
                mma16816(s[2*nio][0], s[2*nio][1], s[2*nio][2], s[2*nio][3],
                         qh[ks][0], qh[ks][1], qh[ks][2], qh[ks][3], c0, c1);
                mma16816(s[2*nio+1][0], s[2*nio+1][1], s[2*nio+1][2], s[2*nio+1][3],
                         qh[ks][0], qh[ks][1], qh[ks][2], qh[ks][3], c2, c3);
            }
        }

        float mxa = -1e30f, mxb = -1e30f;
        #pragma unroll
        for (int i = 0; i < 8; i++) {
            mxa = fmaxf(mxa, fmaxf(s[i][0], s[i][1]));
            mxb = fmaxf(mxb, fmaxf(s[i][2], s[i][3]));
        }
        mxa = fmaxf(mxa, __shfl_xor_sync(0xffffffffu, mxa, 1));
        mxa = fmaxf(mxa, __shfl_xor_sync(0xffffffffu, mxa, 2));
        mxb = fmaxf(mxb, __shfl_xor_sync(0xffffffffu, mxb, 1));
        mxb = fmaxf(mxb, __shfl_xor_sync(0xffffffffu, mxb, 2));
        const float nma = fmaxf(ma, mxa), nmb = fmaxf(mb, mxb);
        const float alfa = exp2f(ma - nma), alfb = exp2f(mb - nmb);
        ma = nma; mb = nmb;
        float sa = 0.f, sb = 0.f;
        #pragma unroll
        for (int i = 0; i < 8; i++) {
            s[i][0] = exp2f(s[i][0] - nma); sa += s[i][0];
            s[i][1] = exp2f(s[i][1] - nma); sa += s[i][1];
            s[i][2] = exp2f(s[i][2] - nmb); sb += s[i][2];
            s[i][3] = exp2f(s[i][3] - nmb); sb += s[i][3];
        }
        sa += __shfl_xor_sync(0xffffffffu, sa, 1);
        sa += __shfl_xor_sync(0xffffffffu, sa, 2);
        sb += __shfl_xor_sync(0xffffffffu, sb, 1);
        sb += __shfl_xor_sync(0xffffffffu, sb, 2);
        la = la * alfa + sa;
        lb = lb * alfb + sb;
        #pragma unroll
        for (int i = 0; i < 8; i++) {
            o[i][0] *= alfa; o[i][1] *= alfa;
            o[i][2] *= alfb; o[i][3] *= alfb;
        }

        // ---- O += Phi*(Vhi + Vlo)  (2-term PV) -----------------------------
        #pragma unroll
        for (int kj = 0; kj < 4; kj++) {
            uint32_t ph[4];
            #pragma unroll
            for (int u = 0; u < 4; u++) {
                const int ni = 2 * kj + (u >> 1);
                ph[u] = cvt_bf2(s[ni][(u & 1) * 2 + 0], s[ni][(u & 1) * 2 + 1]);
            }
            #pragma unroll
            for (int ndo = 0; ndo < 4; ndo++) {
                const int vrow = kj * 16 + (q4 & 1) * 8 + (lane & 7);
                const int vg = 2 * ndo + (q4 >> 1);
                uint32_t v0, v1, v2, v3;
                ldmx4t(v0, v1, v2, v3, SW_ADDR(aVh, vrow, vg));
                mma16816(o[2*ndo][0], o[2*ndo][1], o[2*ndo][2], o[2*ndo][3],
                         ph[0], ph[1], ph[2], ph[3], v0, v1);
                mma16816(o[2*ndo+1][0], o[2*ndo+1][1], o[2*ndo+1][2], o[2*ndo+1][3],
                         ph[0], ph[1], ph[2], ph[3], v2, v3);
                uint32_t u0, u1, u2, u3;
                ldmx4t(u0, u1, u2, u3, SW_ADDR(aVl, vrow, vg));
                mma16816(o[2*ndo][0], o[2*ndo][1], o[2*ndo][2], o[2*ndo][3],
                         ph[0], ph[1], ph[2], ph[3], u0, u1);
                mma16816(o[2*ndo+1][0], o[2*ndo+1][1], o[2*ndo+1][2], o[2*ndo+1][3],
                         ph[0], ph[1], ph[2], ph[3], u2, u3);
            }
        }
    }

    // epilogue: write hi twice ([hi|hi]); lo block unused by 2-term out GEMM
    const float inva = 1.0f / la, invb = 1.0f / lb;
    const int b = bh >> 4, h = bh & (HEADS - 1);
    const int ra = q0 + w * 16 + gid, rb = ra + 8;
    unsigned short* rowA = g_A2o + (size_t)(b * SEQ + ra) * K2 + h * DHEAD;
    unsigned short* rowB = g_A2o + (size_t)(b * SEQ + rb) * K2 + h * DHEAD;
    #pragma unroll
    for (int nd = 0; nd < 8; nd++) {
        const int d = nd * 8 + tin * 2;
        const float x0 = o[nd][0] * inva, x1 = o[nd][1] * inva;
        const float x2 = o[nd][2] * invb, x3 = o[nd][3] * invb;
        const uint32_t hpA = cvt_bf2(x0, x1);
        const uint32_t hpB = cvt_bf2(x2, x3);
        *(uint32_t*)(rowA + d) = hpA;
        *(uint32_t*)(rowA + EDIM + d) = hpA;
        *(uint32_t*)(rowB + d) = hpB;
        *(uint32_t*)(rowB + EDIM + d) = hpB;
    }
}

// ---------------- kernel 5: LayerNorm ---------------------------------------
__global__ __launch_bounds__(256) void ln_kernel(
    const float* __restrict__ gamma, const float* __restrict__ beta,
    float* __restrict__ out)
{
    const int row = blockIdx.x;
    const int tid = threadIdx.x;
    const float4 v = *(const float4*)&g_Mb[(size_t)row * EDIM + tid * 4];
    float s = v.x + v.y + v.z + v.w;
    float q = v.x * v.x + v.y * v.y + v.z * v.z + v.w * v.w;
    #pragma unroll
    for (int off = 16; off >= 1; off >>= 1) {
        s += __shfl_xor_sync(0xffffffffu, s, off);
        q += __shfl_xor_sync(0xffffffffu, q, off);
    }
    __shared__ float ss[8], sq[8];
    const int w = tid >> 5, lane = tid & 31;
    if (lane == 0) { ss[w] = s; sq[w] = q; }
    __syncthreads();
    float tot = 0.f, totq = 0.f;
    #pragma unroll
    for (int i = 0; i < 8; i++) { tot += ss[i]; totq += sq[i]; }
    const float mu = tot * (1.0f / EDIM);
    const float var = totq * (1.0f / EDIM) - mu * mu;
    const float rs = rsqrtf(var + 1e-6f);
    const float4 g = *(const float4*)&gamma[tid * 4];
    const float4 bb = *(const float4*)&beta[tid * 4];
    float4 o;
    o.x = (v.x - mu) * rs * g.x + bb.x;
    o.y = (v.y - mu) * rs * g.y + bb.y;
    o.z = (v.z - mu) * rs * g.z + bb.z;
    o.w = (v.w - mu) * rs * g.w + bb.w;
    *(float4*)&out[(size_t)row * EDIM + tid * 4] = o;
}

// ---------------- launcher --------------------------------------------------
#define GEMM_SMEM (3 * (128 + 128) * 64 * 2)   // 96 KB

extern "C" void kernel_launch(void* const* d_in, const int* in_sizes, int n_in,
                              void* d_out, int out_size)
{
    (void)in_sizes; (void)n_in; (void)out_size;
    const float* y    = (const float*)d_in[0];
    const float* Wqkv = (const float*)d_in[1];
    const float* bqkv = (const float*)d_in[2];
    const float* Wmsa = (const float*)d_in[3];
    const float* Bq   = (const float*)d_in[4];
    const float* Aq   = (const float*)d_in[5];
    const float* Bk   = (const float*)d_in[6];
    const float* Ak   = (const float*)d_in[7];
    const float* Bv   = (const float*)d_in[8];
    const float* Av   = (const float*)d_in[9];
    const float* Bo   = (const float*)d_in[10];
    const float* Ao   = (const float*)d_in[11];
    const float* gamma= (const float*)d_in[12];
    const float* beta = (const float*)d_in[13];
    float* out = (float*)d_out;

    prep_all<<<(NQKV + NWM + NCNV) / 256, 256>>>(y, Wqkv, Wmsa, Bq, Aq, Bk, Ak, Bv, Av, Bo, Ao);
    (void)cudaFuncSetAttribute(gemm_qkv_mma, cudaFuncAttributeMaxDynamicSharedMemorySize, GEMM_SMEM);
    (void)cudaFuncSetAttribute(gemm_out_mma, cudaFuncAttributeMaxDynamicSharedMemorySize, GEMM_SMEM);
    (void)cudaFuncSetAttribute(attn_mma, cudaFuncAttributeMaxDynamicSharedMemorySize, ATTN_SMEM);
    gemm_qkv_mma<<<dim3(3 * EDIM / 128, MTOT / 128), 128, GEMM_SMEM>>>(bqkv);
    attn_mma<<<dim3(SEQ / 64, BATCH * HEADS), 128, ATTN_SMEM>>>();
    gemm_out_mma<<<dim3(EDIM / 128, MTOT / 128), 128, GEMM_SMEM>>>(y);
    ln_kernel<<<MTOT, 256>>>(gamma, beta, out);
}

// round 16
// speedup vs baseline: 4.6692x; 1.1678x over previous
#include <cuda_runtime.h>
#include <cuda_bf16.h>
#include <cstdint>

#define EDIM   1024
#define HEADS  16
#define DHEAD  64
#define BATCH  2
#define SEQ    2048
#define RANK   8
#define MTOT   (BATCH*SEQ)
#define K2     3072          // extended K: A=[hi|hi|lo], B=[hi|lo|hi]
#define NCHUNK 48            // 3-term (Q tiles of qkv GEMM)
#define NCHUNK2 32           // 2-term -> K=2048 = [hi|hi]x[hi|lo] (K,V tiles + out GEMM)

// ---------------- scratch (device globals; no allocations allowed) ----------
__device__ unsigned short g_A2y[(size_t)MTOT*K2];      // y split-bf16 extended
__device__ unsigned short g_B2q[(size_t)3*EDIM*K2];    // folded qkv weights split-bf16
__device__ unsigned short g_A2o[(size_t)MTOT*K2];      // attention out split-bf16
__device__ unsigned short g_B2o[(size_t)EDIM*K2];      // folded out-proj weights split-bf16
__device__ unsigned short g_Qh[(size_t)BATCH*HEADS*SEQ*DHEAD];  // Q*(log2e/8) hi [bh][s][d]
__device__ unsigned short g_Ql[(size_t)BATCH*HEADS*SEQ*DHEAD];  // Q*(log2e/8) lo
__device__ unsigned short g_Kh[(size_t)BATCH*HEADS*SEQ*DHEAD];
__device__ unsigned short g_Kl[(size_t)BATCH*HEADS*SEQ*DHEAD];  // (unused by attn now)
__device__ unsigned short g_Vh[(size_t)BATCH*HEADS*SEQ*DHEAD];
__device__ unsigned short g_Vl[(size_t)BATCH*HEADS*SEQ*DHEAD];
__device__ float g_Mb[(size_t)MTOT*EDIM];              // msa + residual

// ---------------- bf16 split helpers ----------------------------------------
static __device__ __forceinline__ unsigned short bf_hi(float x) {
    return __bfloat16_as_ushort(__float2bfloat16(x));
}
static __device__ __forceinline__ unsigned short bf_lo(float x, unsigned short h) {
    float hf = __bfloat162float(__ushort_as_bfloat16(h));
    return __bfloat16_as_ushort(__float2bfloat16(x - hf));
}
static __device__ __forceinline__ uint32_t cvt_bf2(float lo, float hi) {
    uint32_t r;
    asm("cvt.rn.bf16x2.f32 %0, %1, %2;" : "=r"(r) : "f"(hi), "f"(lo));
    return r;
}

// ---------------- mma.sync helpers -------------------------------------------
static __device__ __forceinline__ uint32_t smem_u32(const void* p) {
    uint32_t a;
    asm("{ .reg .u64 t; cvta.to.shared.u64 t, %1; cvt.u32.u64 %0, t; }" : "=r"(a) : "l"(p));
    return a;
}
static __device__ __forceinline__ void ldmx4(
    uint32_t& r0, uint32_t& r1, uint32_t& r2, uint32_t& r3, uint32_t a) {
    asm volatile("ldmatrix.sync.aligned.m8n8.x4.shared.b16 {%0,%1,%2,%3}, [%4];"
                 : "=r"(r0), "=r"(r1), "=r"(r2), "=r"(r3) : "r"(a));
}
static __device__ __forceinline__ void ldmx4t(
    uint32_t& r0, uint32_t& r1, uint32_t& r2, uint32_t& r3, uint32_t a) {
    asm volatile("ldmatrix.sync.aligned.m8n8.x4.trans.shared.b16 {%0,%1,%2,%3}, [%4];"
                 : "=r"(r0), "=r"(r1), "=r"(r2), "=r"(r3) : "r"(a));
}
static __device__ __forceinline__ void mma16816(
    float& d0, float& d1, float& d2, float& d3,
    uint32_t a0, uint32_t a1, uint32_t a2, uint32_t a3,
    uint32_t b0, uint32_t b1) {
    asm volatile("mma.sync.aligned.m16n8k16.row.col.f32.bf16.bf16.f32 "
                 "{%0,%1,%2,%3}, {%4,%5,%6,%7}, {%8,%9}, {%0,%1,%2,%3};"
                 : "+f"(d0), "+f"(d1), "+f"(d2), "+f"(d3)
                 : "r"(a0), "r"(a1), "r"(a2), "r"(a3), "r"(b0), "r"(b1));
}
#define CP_ASYNC16(dst, src) \
    asm volatile("cp.async.cg.shared.global [%0], [%1], 16;" :: "r"(dst), "l"(src))
#define CP_COMMIT() asm volatile("cp.async.commit_group;" ::: "memory")
#define CP_WAIT1()  asm volatile("cp.async.wait_group 1;" ::: "memory")
#define CP_WAIT0()  asm volatile("cp.async.wait_group 0;" ::: "memory")

// smem tiles [rows][64 cols bf16] = [rows][8] 16B groups, swizzle g^=(row&7)
#define SW_ADDR(base, row, g) ((base) + (row) * 128u + (uint32_t)(((g) ^ ((row) & 7)) << 4))

// ---------------- kernel 1: fold LoRA + split weights + split y (merged) -----
#define NQKV (3 * EDIM * EDIM)
#define NWM  (EDIM * EDIM)
#define NCNV (MTOT * EDIM / 4)
__global__ __launch_bounds__(256) void prep_all(
    const float* __restrict__ y,
    const float* __restrict__ Wqkv, const float* __restrict__ Wmsa,
    const float* __restrict__ Bq, const float* __restrict__ Aq,
    const float* __restrict__ Bk, const float* __restrict__ Ak,
    const float* __restrict__ Bv, const float* __restrict__ Av,
    const float* __restrict__ Bo, const float* __restrict__ Ao)
{
    const int idx = blockIdx.x * blockDim.x + threadIdx.x;
    if (idx < NQKV) {
        const int o = idx >> 10;
        const int i = idx & (EDIM - 1);
        const int which = o >> 10;
        const int e = o & (EDIM - 1);
        const float* Bw = (which == 0) ? Bq : (which == 1) ? Bk : Bv;
        const float* Aw = (which == 0) ? Aq : (which == 1) ? Ak : Av;
        float acc = Wqkv[idx];
        #pragma unroll
        for (int r = 0; r < RANK; r++) acc += Bw[i * RANK + r] * Aw[r * EDIM + e];
        unsigned short h = bf_hi(acc), l = bf_lo(acc, h);
        unsigned short* row = g_B2q + (size_t)o * K2;
        row[i] = h; row[EDIM + i] = l; row[2 * EDIM + i] = h;   // B2 = [hi|lo|hi]
    } else if (idx < NQKV + NWM) {
        const int j = idx - NQKV;
        const int o = j >> 10;
        const int i = j & (EDIM - 1);
        float acc = Wmsa[j];
        #pragma unroll
        for (int r = 0; r < RANK; r++) acc += Bo[i * RANK + r] * Ao[r * EDIM + o];
        unsigned short h = bf_hi(acc), l = bf_lo(acc, h);
        unsigned short* row = g_B2o + (size_t)o * K2;
        row[i] = h; row[EDIM + i] = l; row[2 * EDIM + i] = h;
    } else {
        const int j = idx - NQKV - NWM;           // [0, MTOT*EDIM/4)
        const int m = j >> 8;
        const int c = (j & 255) * 4;
        float4 v = *(const float4*)(y + (size_t)m * EDIM + c);
        unsigned short h0 = bf_hi(v.x), h1 = bf_hi(v.y), h2 = bf_hi(v.z), h3 = bf_hi(v.w);
        unsigned short l0 = bf_lo(v.x, h0), l1 = bf_lo(v.y, h1), l2 = bf_lo(v.z, h2), l3 = bf_lo(v.w, h3);
        uint2 hp = make_uint2((uint32_t)h0 | ((uint32_t)h1 << 16), (uint32_t)h2 | ((uint32_t)h3 << 16));
        uint2 lp = make_uint2((uint32_t)l0 | ((uint32_t)l1 << 16), (uint32_t)l2 | ((uint32_t)l3 << 16));
        unsigned short* row = g_A2y + (size_t)m * K2 + c;      // A2 = [hi|hi|lo]
        *(uint2*)(row) = hp;
        *(uint2*)(row + EDIM) = hp;
        *(uint2*)(row + 2 * EDIM) = lp;
    }
}

// ---------------- GEMM mainloop: 128x128 tile, 128 thr, cp.async x3 ----------
// stage s (bytes): A at smbase + s*32768, B at +16384. Total 96 KB -> 2 CTAs/SM
static __device__ __forceinline__ void issue_loads(
    const unsigned short* __restrict__ Ag, const unsigned short* __restrict__ Bg,
    uint32_t sa, uint32_t sb, int kc, int tid)
{
    const int r0 = tid >> 3, g = tid & 7;       // r0 0..15, g 0..7
    const int koff = kc * 64 + g * 8;
    #pragma unroll
    for (int p = 0; p < 8; p++) {
        const int row = p * 16 + r0;
        CP_ASYNC16(SW_ADDR(sa, row, g), Ag + (size_t)row * K2 + koff);
    }
    #pragma unroll
    for (int p = 0; p < 8; p++) {
        const int row = p * 16 + r0;
        CP_ASYNC16(SW_ADDR(sb, row, g), Bg + (size_t)row * K2 + koff);
    }
    CP_COMMIT();
}

static __device__ __forceinline__ void mma_mainloop_big(
    const unsigned short* __restrict__ Ag, const unsigned short* __restrict__ Bg,
    uint32_t smbase, float acc[4][8][4], int tid, int lane, int wm, int wn,
    int nchunk)
{
    issue_loads(Ag, Bg, smbase, smbase + 16384u, 0, tid);
    issue_loads(Ag, Bg, smbase + 32768u, smbase + 49152u, 1, tid);

    const int q = lane >> 3;                 // 0..3 quad-of-8
    for (int kc = 0; kc < nchunk; kc++) {
        const int st = kc % 3;
        const uint32_t sa = smbase + (uint32_t)st * 32768u;
        const uint32_t sb = sa + 16384u;
        if (kc == nchunk - 1) { CP_WAIT0(); } else { CP_WAIT1(); }
        __syncthreads();
        if (kc + 2 < nchunk) {
            const int ns = (kc + 2) % 3;
            issue_loads(Ag, Bg, smbase + (uint32_t)ns * 32768u,
                        smbase + (uint32_t)ns * 32768u + 16384u, kc + 2, tid);
        }

        #pragma unroll
        for (int ks = 0; ks < 4; ks++) {
            uint32_t bf[4][4];
            #pragma unroll
            for (int p = 0; p < 4; p++) {
                const int brow = wn * 64 + p * 16 + (q >> 1) * 8 + (lane & 7);
                const int bg = ks * 2 + (q & 1);
                ldmx4(bf[p][0], bf[p][1], bf[p][2], bf[p][3], SW_ADDR(sb, brow, bg));
            }
            #pragma unroll
            for (int mi = 0; mi < 4; mi++) {
                const int arow = wm * 64 + mi * 16 + (lane & 15);
                const int ag = ks * 2 + (lane >> 4);
                uint32_t a0, a1, a2, a3;
                ldmx4(a0, a1, a2, a3, SW_ADDR(sa, arow, ag));
                #pragma unroll
                for (int p = 0; p < 4; p++) {
                    mma16816(acc[mi][2*p][0], acc[mi][2*p][1], acc[mi][2*p][2], acc[mi][2*p][3],
                             a0, a1, a2, a3, bf[p][0], bf[p][1]);
                    mma16816(acc[mi][2*p+1][0], acc[mi][2*p+1][1], acc[mi][2*p+1][2], acc[mi][2*p+1][3],
                             a0, a1, a2, a3, bf[p][2], bf[p][3]);
                }
            }
        }
    }
}

// ---------------- kernel 2: QKV GEMM (Q tiles 3-term, K/V tiles 2-term) ------
#define QSCALE_LOG2E 0.18033688011112042f   // (1/8) * log2(e)
__global__ __launch_bounds__(128, 2) void gemm_qkv_mma(const float* __restrict__ bias)
{
    extern __shared__ __align__(16) unsigned short smg[];
    const int tid = threadIdx.x, lane = tid & 31, wid = tid >> 5;
    const int wm = wid >> 1, wn = wid & 1;
    const int m0 = blockIdx.y * 128, n0 = blockIdx.x * 128;
    const int which = n0 >> 10;                   // 0=q 1=k 2=v

    float acc[4][8][4];
    #pragma unroll
    for (int i = 0; i < 4; i++)
        #pragma unroll
        for (int j = 0; j < 8; j++)
            #pragma unroll
            for (int c = 0; c < 4; c++) acc[i][j][c] = 0.f;

    mma_mainloop_big(g_A2y + (size_t)m0 * K2, g_B2q + (size_t)n0 * K2,
                     smem_u32(smg), acc, tid, lane, wm, wn,
                     (which == 0) ? NCHUNK : NCHUNK2);

    const int gid = lane >> 2, tin = lane & 3;
    unsigned short* Ha = (which == 0) ? g_Qh : (which == 1) ? g_Kh : g_Vh;
    unsigned short* La = (which == 0) ? g_Ql : (which == 1) ? g_Kl : g_Vl;
    const float qscale = (which == 0) ? QSCALE_LOG2E : 1.0f;
    #pragma unroll
    for (int mi = 0; mi < 4; mi++) {
        #pragma unroll
        for (int half = 0; half < 2; half++) {
            const int m = m0 + wm * 64 + mi * 16 + gid + half * 8;
            const int b = m >> 11, s = m & (SEQ - 1);
            #pragma unroll
            for (int ni = 0; ni < 8; ni++) {
                const int n = n0 + wn * 64 + ni * 8 + tin * 2;
                const int e = n & (EDIM - 1);
                const int h = e >> 6, d = e & (DHEAD - 1);
                float vx = (acc[mi][ni][half * 2 + 0] + bias[n]) * qscale;
                float vy = (acc[mi][ni][half * 2 + 1] + bias[n + 1]) * qscale;
                unsigned short h0 = bf_hi(vx), h1 = bf_hi(vy);
                unsigned short l0 = bf_lo(vx, h0), l1 = bf_lo(vy, h1);
                const size_t off = (size_t)((b * HEADS + h) * SEQ + s) * DHEAD + d;
                *(uint32_t*)(Ha + off) = (uint32_t)h0 | ((uint32_t)h1 << 16);
                *(uint32_t*)(La + off) = (uint32_t)l0 | ((uint32_t)l1 << 16);
            }
        }
    }
}

// ---------------- kernel 4: out-proj GEMM (2-term, K=2048) + residual --------
__global__ __launch_bounds__(128, 2) void gemm_out_mma(const float* __restrict__ yres)
{
    extern __shared__ __align__(16) unsigned short smg[];
    const int tid = threadIdx.x, lane = tid & 31, wid = tid >> 5;
    const int wm = wid >> 1, wn = wid & 1;
    const int m0 = blockIdx.y * 128, n0 = blockIdx.x * 128;

    float acc[4][8][4];
    #pragma unroll
    for (int i = 0; i < 4; i++)
        #pragma unroll
        for (int j = 0; j < 8; j++)
            #pragma unroll
            for (int c = 0; c < 4; c++) acc[i][j][c] = 0.f;

    mma_mainloop_big(g_A2o + (size_t)m0 * K2, g_B2o + (size_t)n0 * K2,
                     smem_u32(smg), acc, tid, lane, wm, wn, NCHUNK2);

    const int gid = lane >> 2, tin = lane & 3;
    #pragma unroll
    for (int mi = 0; mi < 4; mi++) {
        #pragma unroll
        for (int half = 0; half < 2; half++) {
            const int m = m0 + wm * 64 + mi * 16 + gid + half * 8;
            #pragma unroll
            for (int ni = 0; ni < 8; ni++) {
                const int n = n0 + wn * 64 + ni * 8 + tin * 2;
                float2 r = *(const float2*)(yres + (size_t)m * EDIM + n);
                float2 v;
                v.x = acc[mi][ni][half * 2 + 0] + r.x;
                v.y = acc[mi][ni][half * 2 + 1] + r.y;
                *(float2*)(g_Mb + (size_t)m * EDIM + n) = v;
            }
        }
    }
}

// ---------------- kernel 3: flash attention (BQ=64, KVT=64, 2 CTAs/SM) -------
// QK: 2-term (Qhi+Qlo)*Khi  (Klo dropped; K consumed at bf16 precision)
// PV: 2-term Phi*(Vhi+Vlo)
#define ATTN_SMEM (112 * 1024)
#define KVT 64
#define NT (SEQ / KVT)

static __device__ __forceinline__ void attn_issue_kv(
    size_t hbase, int t, uint32_t stg, int tid)
{
    const int row = tid >> 3, g = tid & 7;
    const uint32_t aKh = stg, aVh = stg + 16384u, aVl = stg + 24576u;
    #pragma unroll
    for (int i = 0; i < 4; i++) {
        const int r = row + i * 16;
        const size_t src = hbase + (size_t)(t * KVT + r) * DHEAD + g * 8;
        CP_ASYNC16(SW_ADDR(aKh, r, g), g_Kh + src);
        CP_ASYNC16(SW_ADDR(aVh, r, g), g_Vh + src);
        CP_ASYNC16(SW_ADDR(aVl, r, g), g_Vl + src);
    }
    CP_COMMIT();
}

__global__ __launch_bounds__(128, 2) void attn_mma()
{
    extern __shared__ __align__(16) unsigned short smatt[];
    unsigned short* sQh = smatt;
    unsigned short* sQl = smatt + 4096;

    const int tid = threadIdx.x, lane = tid & 31, w = tid >> 5;
    const int gid = lane >> 2, tin = lane & 3;
    const int bh = blockIdx.y, q0 = blockIdx.x * 64;
    const size_t hbase = (size_t)bh * SEQ * DHEAD;
    const uint32_t smbase = smem_u32(smatt);

    attn_issue_kv(hbase, 0, smbase + 16384u, tid);
    attn_issue_kv(hbase, 1, smbase + 49152u, tid);

    {
        const int row = tid >> 3, g = tid & 7;
        #pragma unroll
        for (int i = 0; i < 4; i++) {
            const int r = row + i * 16;
            const size_t src = hbase + (size_t)(q0 + r) * DHEAD + g * 8;
            uint4 vh = *(const uint4*)(g_Qh + src);
            uint4 vl = *(const uint4*)(g_Ql + src);
            asm volatile("st.shared.v4.b32 [%0], {%1,%2,%3,%4};"
                :: "r"(SW_ADDR(smem_u32(sQh), r, g)), "r"(vh.x), "r"(vh.y), "r"(vh.z), "r"(vh.w));
            asm volatile("st.shared.v4.b32 [%0], {%1,%2,%3,%4};"
                :: "r"(SW_ADDR(smem_u32(sQl), r, g)), "r"(vl.x), "r"(vl.y), "r"(vl.z), "r"(vl.w));
        }
    }
    __syncthreads();

    uint32_t qh[4][4], ql[4][4];
    #pragma unroll
    for (int ks = 0; ks < 4; ks++) {
        const int row = w * 16 + (lane & 15);
        const int g = ks * 2 + (lane >> 4);
        ldmx4(qh[ks][0], qh[ks][1], qh[ks][2], qh[ks][3], SW_ADDR(smem_u32(sQh), row, g));
        ldmx4(ql[ks][0], ql[ks][1], ql[ks][2], ql[ks][3], SW_ADDR(smem_u32(sQl), row, g));
    }

    float ma = -1e30f, mb = -1e30f, la = 0.f, lb = 0.f;
    float o[8][4];
    #pragma unroll
    for (int i = 0; i < 8; i++)
        #pragma unroll
        for (int c = 0; c < 4; c++) o[i][c] = 0.f;

    const int q4 = lane >> 3;
    for (int t = 0; t < NT; t++) {
        const uint32_t sg = smbase + 16384u + (uint32_t)(t % 3) * 32768u;
        const uint32_t aKh = sg, aVh = sg + 16384u, aVl = sg + 24576u;
        if (t == NT - 1) { CP_WAIT0(); } else { CP_WAIT1(); }
        __syncthreads();
        if (t + 2 < NT)
            attn_issue_kv(hbase, t + 2, smbase + 16384u + (uint32_t)((t + 2) % 3) * 32768u, tid);

        float s[8][4];
        #pragma unroll
        for (int i = 0; i < 8; i++)
            #pragma unroll
            for (int c = 0; c < 4; c++) s[i][c] = 0.f;

        // ---- S = (Qhi+Qlo) * Khi  (2-term QK) ------------------------------
        #pragma unroll
        for (int ks = 0; ks < 4; ks++) {
            #pragma unroll
            for (int nio = 0; nio < 4; nio++) {
                const int krow = (2 * nio + (q4 >> 1)) * 8 + (lane & 7);
                const int kg = ks * 2 + (q4 & 1);
                uint32_t b0, b1, b2, b3;
                ldmx4(b0, b1, b2, b3, SW_ADDR(aKh, krow, kg));
                mma16816(s[2*nio][0], s[2*nio][1], s[2*nio][2], s[2*nio][3],
                         qh[ks][0], qh[ks][1], qh[ks][2], qh[ks][3], b0, b1);
                mma16816(s[2*nio+1][0], s[2*nio+1][1], s[2*nio+1][2], s[2*nio+1][3],
                         qh[ks][0], qh[ks][1], qh[ks][2], qh[ks][3], b2, b3);
                mma16816(s[2*nio][0], s[2*nio][1], s[2*nio][2], s[2*nio][3],
                         ql[ks][0], ql[ks][1], ql[ks][2], ql[ks][3], b0, b1);
                mma16816(s[2*nio+1][0], s[2*nio+1][1], s[2*nio+1][2], s[2*nio+1][3],
                         ql[ks][0], ql[ks][1], ql[ks][2], ql[ks][3], b2, b3);
            }
        }

        float mxa = -1e30f, mxb = -1e30f;
        #pragma unroll
        for (int i = 0; i < 8; i++) {
            mxa = fmaxf(mxa, fmaxf(s[i][0], s[i][1]));
            mxb = fmaxf(mxb, fmaxf(s[i][2], s[i][3]));
        }
        mxa = fmaxf(mxa, __shfl_xor_sync(0xffffffffu, mxa, 1));
        mxa = fmaxf(mxa, __shfl_xor_sync(0xffffffffu, mxa, 2));
        mxb = fmaxf(mxb, __shfl_xor_sync(0xffffffffu, mxb, 1));
        mxb = fmaxf(mxb, __shfl_xor_sync(0xffffffffu, mxb, 2));
        const float nma = fmaxf(ma, mxa), nmb = fmaxf(mb, mxb);
        const float alfa = exp2f(ma - nma), alfb = exp2f(mb - nmb);
        ma = nma; mb = nmb;
        float sa = 0.f, sb = 0.f;
        #pragma unroll
        for (int i = 0; i < 8; i++) {
            s[i][0] = exp2f(s[i][0] - nma); sa += s[i][0];
            s[i][1] = exp2f(s[i][1] - nma); sa += s[i][1];
            s[i][2] = exp2f(s[i][2] - nmb); sb += s[i][2];
            s[i][3] = exp2f(s[i][3] - nmb); sb += s[i][3];
        }
        sa += __shfl_xor_sync(0xffffffffu, sa, 1);
        sa += __shfl_xor_sync(0xffffffffu, sa, 2);
        sb += __shfl_xor_sync(0xffffffffu, sb, 1);
        sb += __shfl_xor_sync(0xffffffffu, sb, 2);
        la = la * alfa + sa;
        lb = lb * alfb + sb;
        #pragma unroll
        for (int i = 0; i < 8; i++) {
            o[i][0] *= alfa; o[i][1] *= alfa;
            o[i][2] *= alfb; o[i][3] *= alfb;
        }

        // ---- O += Phi*(Vhi + Vlo)  (2-term PV) -----------------------------
        #pragma unroll
        for (int kj = 0; kj < 4; kj++) {
            uint32_t ph[4];
            #pragma unroll
            for (int u = 0; u < 4; u++) {
                const int ni = 2 * kj + (u >> 1);
                ph[u] = cvt_bf2(s[ni][(u & 1) * 2 + 0], s[ni][(u & 1) * 2 + 1]);
            }
            #pragma unroll
            for (int ndo = 0; ndo < 4; ndo++) {
                const int vrow = kj * 16 + (q4 & 1) * 8 + (lane & 7);
                const int vg = 2 * ndo + (q4 >> 1);
                uint32_t v0, v1, v2, v3;
                ldmx4t(v0, v1, v2, v3, SW_ADDR(aVh, vrow, vg));
                mma16816(o[2*ndo][0], o[2*ndo][1], o[2*ndo][2], o[2*ndo][3],
                         ph[0], ph[1], ph[2], ph[3], v0, v1);
                mma16816(o[2*ndo+1][0], o[2*ndo+1][1], o[2*ndo+1][2], o[2*ndo+1][3],
                         ph[0], ph[1], ph[2], ph[3], v2, v3);
                uint32_t u0, u1, u2, u3;
                ldmx4t(u0, u1, u2, u3, SW_ADDR(aVl, vrow, vg));
                mma16816(o[2*ndo][0], o[2*ndo][1], o[2*ndo][2], o[2*ndo][3],
                         ph[0], ph[1], ph[2], ph[3], u0, u1);
                mma16816(o[2*ndo+1][0], o[2*ndo+1][1], o[2*ndo+1][2], o[2*ndo+1][3],
                         ph[0], ph[1], ph[2], ph[3], u2, u3);
            }
        }
    }

    // epilogue: write hi twice ([hi|hi]); lo block unused by 2-term out GEMM
    const float inva = 1.0f / la, invb = 1.0f / lb;
    const int b = bh >> 4, h = bh & (HEADS - 1);
    const int ra = q0 + w * 16 + gid, rb = ra + 8;
    unsigned short* rowA = g_A2o + (size_t)(b * SEQ + ra) * K2 + h * DHEAD;
    unsigned short* rowB = g_A2o + (size_t)(b * SEQ + rb) * K2 + h * DHEAD;
    #pragma unroll
    for (int nd = 0; nd < 8; nd++) {
        const int d = nd * 8 + tin * 2;
        const float x0 = o[nd][0] * inva, x1 = o[nd][1] * inva;
        const float x2 = o[nd][2] * invb, x3 = o[nd][3] * invb;
        const uint32_t hpA = cvt_bf2(x0, x1);
        const uint32_t hpB = cvt_bf2(x2, x3);
        *(uint32_t*)(rowA + d) = hpA;
        *(uint32_t*)(rowA + EDIM + d) = hpA;
        *(uint32_t*)(rowB + d) = hpB;
        *(uint32_t*)(rowB + EDIM + d) = hpB;
    }
}

// ---------------- kernel 5: LayerNorm ---------------------------------------
__global__ __launch_bounds__(256) void ln_kernel(
    const float* __restrict__ gamma, const float* __restrict__ beta,
    float* __restrict__ out)
{
    const int row = blockIdx.x;
    const int tid = threadIdx.x;
    const float4 v = *(const float4*)&g_Mb[(size_t)row * EDIM + tid * 4];
    float s = v.x + v.y + v.z + v.w;
    float q = v.x * v.x + v.y * v.y + v.z * v.z + v.w * v.w;
    #pragma unroll
    for (int off = 16; off >= 1; off >>= 1) {
        s += __shfl_xor_sync(0xffffffffu, s, off);
        q += __shfl_xor_sync(0xffffffffu, q, off);
    }
    __shared__ float ss[8], sq[8];
    const int w = tid >> 5, lane = tid & 31;
    if (lane == 0) { ss[w] = s; sq[w] = q; }
    __syncthreads();
    float tot = 0.f, totq = 0.f;
    #pragma unroll
    for (int i = 0; i < 8; i++) { tot += ss[i]; totq += sq[i]; }
    const float mu = tot * (1.0f / EDIM);
    const float var = totq * (1.0f / EDIM) - mu * mu;
    const float rs = rsqrtf(var + 1e-6f);
    const float4 g = *(const float4*)&gamma[tid * 4];
    const float4 bb = *(const float4*)&beta[tid * 4];
    float4 o;
    o.x = (v.x - mu) * rs * g.x + bb.x;
    o.y = (v.y - mu) * rs * g.y + bb.y;
    o.z = (v.z - mu) * rs * g.z + bb.z;
    o.w = (v.w - mu) * rs * g.w + bb.w;
    *(float4*)&out[(size_t)row * EDIM + tid * 4] = o;
}

// ---------------- launcher --------------------------------------------------
#define GEMM_SMEM (3 * (128 + 128) * 64 * 2)   // 96 KB

extern "C" void kernel_launch(void* const* d_in, const int* in_sizes, int n_in,
                              void* d_out, int out_size)
{
    (void)in_sizes; (void)n_in; (void)out_size;
    const float* y    = (const float*)d_in[0];
    const float* Wqkv = (const float*)d_in[1];
    const float* bqkv = (const float*)d_in[2];
    const float* Wmsa = (const float*)d_in[3];
    const float* Bq   = (const float*)d_in[4];
    const float* Aq   = (const float*)d_in[5];
    const float* Bk   = (const float*)d_in[6];
    const float* Ak   = (const float*)d_in[7];
    const float* Bv   = (const float*)d_in[8];
    const float* Av   = (const float*)d_in[9];
    const float* Bo   = (const float*)d_in[10];
    const float* Ao   = (const float*)d_in[11];
    const float* gamma= (const float*)d_in[12];
    const float* beta = (const float*)d_in[13];
    float* out = (float*)d_out;

    prep_all<<<(NQKV + NWM + NCNV) / 256, 256>>>(y, Wqkv, Wmsa, Bq, Aq, Bk, Ak, Bv, Av, Bo, Ao);
    (void)cudaFuncSetAttribute(gemm_qkv_mma, cudaFuncAttributeMaxDynamicSharedMemorySize, GEMM_SMEM);
    (void)cudaFuncSetAttribute(gemm_out_mma, cudaFuncAttributeMaxDynamicSharedMemorySize, GEMM_SMEM);
    (void)cudaFuncSetAttribute(attn_mma, cudaFuncAttributeMaxDynamicSharedMemorySize, ATTN_SMEM);
    gemm_qkv_mma<<<dim3(3 * EDIM / 128, MTOT / 128), 128, GEMM_SMEM>>>(bqkv);
    attn_mma<<<dim3(SEQ / 64, BATCH * HEADS), 128, ATTN_SMEM>>>();
    gemm_out_mma<<<dim3(EDIM / 128, MTOT / 128), 128, GEMM_SMEM>>>(y);
    ln_kernel<<<MTOT, 256>>>(gamma, beta, out);
}